// round 8
// baseline (speedup 1.0000x reference)
#include <cuda_runtime.h>
#include <cuda_bf16.h>
#include <cstdint>

#define Bz  8
#define Nn  8192
#define Dm  256
#define Hh  4
#define Rr  64
#define HDd 64
#define Mm  (Bz*Nn)

typedef unsigned long long u64;

// ---------------- device scratch ----------------
__device__ float g_bK[Dm];
__device__ float g_xv[(size_t)Mm*Dm];                 // fp32 xv (exact gate term)
__device__ __nv_bfloat16 g_eb  [(size_t)Mm*Dm];       // bf16 raw exp(attn)
__device__ float g_rs[(size_t)Mm*Hh];                 // fp32 rowsum of e per (n,h)
__device__ float g_pool[Bz*Hh*Rr*HDd];                // fp32 P0 accumulator
__device__ __nv_bfloat16 g_poolb[Bz*Hh*Rr*HDd];       // bf16 P0/S
__device__ float g_S [Bz*Hh*Rr];
__device__ __nv_bfloat16 g_Wh[2][Dm*Dm];              // bf16 hi image of W ([k][n])
__device__ __nv_bfloat16 g_Wl[2][Dm*Dm];              // bf16 lo image (gemm0 only used)

// ---------------- helpers ----------------
__device__ __forceinline__ void cpa16(uint32_t d, const void* s) {
    asm volatile("cp.async.cg.shared.global [%0], [%1], 16;" :: "r"(d), "l"(s));
}
#define CPCOMMIT() asm volatile("cp.async.commit_group;")
#define CPWAIT0()  asm volatile("cp.async.wait_group 0;")
#define CPWAIT1()  asm volatile("cp.async.wait_group 1;")

__device__ __forceinline__ void ldsm4(uint32_t* r, uint32_t a) {
    asm volatile("ldmatrix.sync.aligned.m8n8.x4.shared.b16 {%0,%1,%2,%3}, [%4];"
        : "=r"(r[0]), "=r"(r[1]), "=r"(r[2]), "=r"(r[3]) : "r"(a));
}
__device__ __forceinline__ void ldsm4t(uint32_t* r, uint32_t a) {
    asm volatile("ldmatrix.sync.aligned.m8n8.x4.trans.shared.b16 {%0,%1,%2,%3}, [%4];"
        : "=r"(r[0]), "=r"(r[1]), "=r"(r[2]), "=r"(r[3]) : "r"(a));
}
__device__ __forceinline__ void hmma(float* c, const uint32_t* a, uint32_t b0, uint32_t b1) {
    asm volatile("mma.sync.aligned.m16n8k16.row.col.f32.bf16.bf16.f32 "
        "{%0,%1,%2,%3}, {%4,%5,%6,%7}, {%8,%9}, {%0,%1,%2,%3};"
        : "+f"(c[0]), "+f"(c[1]), "+f"(c[2]), "+f"(c[3])
        : "r"(a[0]), "r"(a[1]), "r"(a[2]), "r"(a[3]), "r"(b0), "r"(b1));
}
__device__ __forceinline__ uint2 f4_to_bf16x4(float4 v) {
    uint32_t a, b;
    asm("cvt.rn.bf16x2.f32 %0, %1, %2;" : "=r"(a) : "f"(v.y), "f"(v.x));
    asm("cvt.rn.bf16x2.f32 %0, %1, %2;" : "=r"(b) : "f"(v.w), "f"(v.z));
    return make_uint2(a, b);
}

// ---------------- small kernels ----------------
__global__ void kzero() {
    int i = blockIdx.x*blockDim.x + threadIdx.x;
    if (i < Bz*Hh*Rr*HDd) g_pool[i] = 0.f;
    if (i < Bz*Hh*Rr)     g_S[i]   = 0.f;
}

__global__ void kprep(const float* __restrict__ Wq, const float* __restrict__ bq,
                      const float* __restrict__ K) {
    int col = threadIdx.x;
    int h = col >> 6, r = col & 63;
    const float* Krow = K + r*Dm + h*HDd;
    if (blockIdx.x < Dm) {
        int c = blockIdx.x;
        const float* wq = Wq + c*Dm + h*HDd;
        float s = 0.f;
        #pragma unroll 16
        for (int d = 0; d < HDd; d++) s = fmaf(wq[d], Krow[d], s);
        s *= 0.125f;
        __nv_bfloat16 hi = __float2bfloat16(s);
        g_Wh[1][c*Dm + col] = hi;
        g_Wl[1][c*Dm + col] = __float2bfloat16(s - __bfloat162float(hi));
    } else {
        float s = 0.f;
        #pragma unroll 16
        for (int d = 0; d < HDd; d++) s = fmaf(bq[h*HDd + d], Krow[d], s);
        g_bK[col] = 0.125f * s;
    }
}

__global__ void kprep2(const float* __restrict__ Wv) {
    int k = blockIdx.x, n = threadIdx.x;
    float wv = Wv[(size_t)k*Dm + n];
    __nv_bfloat16 hi = __float2bfloat16(wv);
    g_Wh[0][k*Dm + n] = hi;
    g_Wl[0][k*Dm + n] = __float2bfloat16(wv - __bfloat162float(hi));
}

// ---------------- HMMA GEMM: C[128,128] per CTA, K=256, B double-buffered ----------------
// smem: A hi @0 (128x144=18432), A lo @18432
//       B stage s @ 36864 + s*34816: hi (64x272=17408) + lo @ +17408
// epilogue: C fp32 [128][132] @0
#define A_HI    0
#define A_LO    18432
#define B_ST(s) (36864 + (s)*34816)
#define B_LO    17408
#define SMEM_MMA 106496

__global__ void __launch_bounds__(256, 2)
kgemm_mma(const float* __restrict__ X, const float* __restrict__ Z,
          const float* __restrict__ bias) {
    extern __shared__ char sm[];
    uint32_t smb = (uint32_t)__cvta_generic_to_shared(sm);
    const int t = threadIdx.x, w = t >> 5, lane = t & 31;
    const int m0 = blockIdx.x*128, nh = blockIdx.y;
    const int gemm = blockIdx.z;
    const float* A = gemm ? Z : X;
    const __nv_bfloat16* Wh = g_Wh[gemm];
    const __nv_bfloat16* Wl = g_Wl[gemm];
    const float* bp = gemm ? g_bK : bias;
    const int wm = (w >> 1)*32, wn = (w & 1)*64;

    float acc[2][8][4];
    #pragma unroll
    for (int i = 0; i < 2; i++)
        #pragma unroll
        for (int j = 0; j < 8; j++)
            #pragma unroll
            for (int q = 0; q < 4; q++) acc[i][j][q] = 0.f;

#define STAGE_B(kc, s)                                                        \
    {                                                                         \
        const __nv_bfloat16* srcH = Wh + (size_t)((kc)*64)*Dm + nh*128;       \
        const __nv_bfloat16* srcL = Wl + (size_t)((kc)*64)*Dm + nh*128;       \
        _Pragma("unroll")                                                     \
        for (int p = 0; p < 4; p++) {                                         \
            int idx = t + p*256;                                              \
            int row = idx >> 4, seg = idx & 15;                               \
            uint32_t d = smb + B_ST(s) + (uint32_t)(row*272 + seg*16);        \
            cpa16(d,        srcH + (size_t)row*Dm + seg*8);                   \
            cpa16(d + B_LO, srcL + (size_t)row*Dm + seg*8);                   \
        }                                                                     \
        CPCOMMIT();                                                           \
    }
#define STAGE_A(kc)                                                           \
    {                                                                         \
        int row = t >> 1, kq = (t & 1)*32;                                    \
        const float4* ar = (const float4*)(A + (size_t)(m0 + row)*Dm + (kc)*64 + kq); \
        char* wbH = sm + A_HI + row*144 + kq*2;                               \
        char* wbL = sm + A_LO + row*144 + kq*2;                               \
        _Pragma("unroll")                                                     \
        for (int j4 = 0; j4 < 8; j4++) {                                      \
            float4 v = ar[j4];                                                \
            uint32_t h01, h23, q01, q23;                                      \
            asm("cvt.rn.bf16x2.f32 %0, %1, %2;" : "=r"(h01) : "f"(v.y), "f"(v.x)); \
            asm("cvt.rn.bf16x2.f32 %0, %1, %2;" : "=r"(h23) : "f"(v.w), "f"(v.z)); \
            float l0 = v.x - __uint_as_float(h01 << 16);                      \
            float l1 = v.y - __uint_as_float(h01 & 0xffff0000u);              \
            float l2 = v.z - __uint_as_float(h23 << 16);                      \
            float l3 = v.w - __uint_as_float(h23 & 0xffff0000u);              \
            asm("cvt.rn.bf16x2.f32 %0, %1, %2;" : "=r"(q01) : "f"(l1), "f"(l0)); \
            asm("cvt.rn.bf16x2.f32 %0, %1, %2;" : "=r"(q23) : "f"(l3), "f"(l2)); \
            *(uint2*)(wbH + j4*8) = make_uint2(h01, h23);                     \
            *(uint2*)(wbL + j4*8) = make_uint2(q01, q23);                     \
        }                                                                     \
    }

    STAGE_B(0, 0);
    STAGE_A(0);

    for (int kc = 0; kc < 4; kc++) {
        int s = kc & 1;
        if (kc < 3) {
            STAGE_B(kc + 1, s ^ 1);
            CPWAIT1();
        } else {
            CPWAIT0();
        }
        __syncthreads();

        uint32_t aoff = smb + A_HI + (uint32_t)((wm + (lane & 15))*144) + (lane >> 4)*16;
        uint32_t boff = smb + B_ST(s) + (uint32_t)((lane & 15)*272) + (uint32_t)((wn + (lane >> 4)*8)*2);
        if (gemm == 0) {
            #pragma unroll
            for (int ks = 0; ks < 4; ks++) {
                uint32_t ah[2][4], al[2][4];
                uint32_t ab = aoff + ks*32;
                ldsm4(ah[0], ab);
                ldsm4(ah[1], ab + 16*144);
                ldsm4(al[0], ab + A_LO);
                ldsm4(al[1], ab + A_LO + 16*144);
                uint32_t bb = boff + ks*16*272;
                #pragma unroll
                for (int nq = 0; nq < 4; nq++) {
                    uint32_t bh[4], bl[4];
                    ldsm4t(bh, bb + nq*32);
                    ldsm4t(bl, bb + nq*32 + B_LO);
                    #pragma unroll
                    for (int mt = 0; mt < 2; mt++) {
                        #pragma unroll
                        for (int sub = 0; sub < 2; sub++) {
                            float* c = acc[mt][nq*2 + sub];
                            hmma(c, ah[mt], bh[sub*2], bh[sub*2+1]);
                            hmma(c, al[mt], bh[sub*2], bh[sub*2+1]);
                            hmma(c, ah[mt], bl[sub*2], bl[sub*2+1]);
                        }
                    }
                }
            }
        } else {
            #pragma unroll
            for (int ks = 0; ks < 4; ks++) {
                uint32_t ah[2][4], al[2][4];
                uint32_t ab = aoff + ks*32;
                ldsm4(ah[0], ab);
                ldsm4(ah[1], ab + 16*144);
                ldsm4(al[0], ab + A_LO);
                ldsm4(al[1], ab + A_LO + 16*144);
                uint32_t bb = boff + ks*16*272;
                #pragma unroll
                for (int nq = 0; nq < 4; nq++) {
                    uint32_t bh[4];
                    ldsm4t(bh, bb + nq*32);
                    #pragma unroll
                    for (int mt = 0; mt < 2; mt++) {
                        #pragma unroll
                        for (int sub = 0; sub < 2; sub++) {
                            float* c = acc[mt][nq*2 + sub];
                            hmma(c, ah[mt], bh[sub*2], bh[sub*2+1]);
                            hmma(c, al[mt], bh[sub*2], bh[sub*2+1]);
                        }
                    }
                }
            }
        }
        __syncthreads();
        if (kc < 3) STAGE_A(kc + 1);
    }

    // ---- epilogue: C through smem (coalesced) ----
    float* Cs = (float*)sm;
    #pragma unroll
    for (int mt = 0; mt < 2; mt++)
        #pragma unroll
        for (int j = 0; j < 8; j++) {
            int r = wm + mt*16 + (lane >> 2);
            int c = wn + j*8 + (lane & 3)*2;
            *(float2*)&Cs[r*132 + c]     = make_float2(acc[mt][j][0], acc[mt][j][1]);
            *(float2*)&Cs[(r+8)*132 + c] = make_float2(acc[mt][j][2], acc[mt][j][3]);
        }
    __syncthreads();

    float4 bv4 = *(const float4*)(bp + nh*128 + lane*4);
    if (gemm == 0) {
        #pragma unroll
        for (int p = 0; p < 16; p++) {
            int row = p*8 + w;
            float4 v = *(const float4*)&Cs[row*132 + lane*4];
            v.x += bv4.x; v.y += bv4.y; v.z += bv4.z; v.w += bv4.w;
            *(float4*)(g_xv + (size_t)(m0 + row)*Dm + nh*128 + lane*4) = v;
        }
    } else {
        #pragma unroll
        for (int p = 0; p < 16; p++) {
            int row = p*8 + w;
            float4 v = *(const float4*)&Cs[row*132 + lane*4];
            v.x = __expf(v.x + bv4.x);
            v.y = __expf(v.y + bv4.y);
            v.z = __expf(v.z + bv4.z);
            v.w = __expf(v.w + bv4.w);
            float s = v.x + v.y + v.z + v.w;
            s += __shfl_xor_sync(0xffffffffu, s, 1);
            s += __shfl_xor_sync(0xffffffffu, s, 2);
            s += __shfl_xor_sync(0xffffffffu, s, 4);
            s += __shfl_xor_sync(0xffffffffu, s, 8);
            *(uint2*)(g_eb + (size_t)(m0 + row)*Dm + nh*128 + lane*4) = f4_to_bf16x4(v);
            if ((lane & 15) == 0)
                g_rs[(size_t)(m0 + row)*Hh + nh*2 + (lane >> 4)] = s;
        }
    }
}

// ---------------- kpool: P0[r,d] = sum_n e_bf * bf16(xv/rs)  (HMMA) ----------------
__global__ void __launch_bounds__(256, 4) kpool() {
    __shared__ char smE[64*144];
    __shared__ char smX[64*144];
    uint32_t sE = (uint32_t)__cvta_generic_to_shared(smE);
    uint32_t sX = (uint32_t)__cvta_generic_to_shared(smX);
    const int t = threadIdx.x, w = t >> 5, lane = t & 31;
    const int ch = blockIdx.x, h = blockIdx.y, b = blockIdx.z;
    const int r_base = (w & 3)*16, d_base = (w >> 2)*32;
    float acc[4][4];
    #pragma unroll
    for (int i = 0; i < 4; i++)
        #pragma unroll
        for (int q = 0; q < 4; q++) acc[i][q] = 0.f;
    float Sacc = 0.f;

    uint32_t aoff = sE + (uint32_t)((((lane >> 4) << 3) + (lane & 7))*144)
                  + (uint32_t)((r_base + (((lane >> 3) & 1) << 3))*2);
    uint32_t boff = sX + (uint32_t)((lane & 15)*144) + (uint32_t)((d_base + (lane >> 4)*8)*2);

    for (int tile = 0; tile < 16; tile++) {
        int n0 = ch*1024 + tile*64;
        size_t gbase = ((size_t)(b*Nn + n0))*Dm + h*64;
        #pragma unroll
        for (int p = 0; p < 2; p++) {
            int c = t + p*256;
            int row = c >> 3, off = c & 7;
            cpa16(sE + row*144 + off*16, g_eb + gbase + (size_t)row*Dm + off*8);
        }
        CPCOMMIT();
        // xv fp32 -> scale by 1/rs -> bf16 -> smX
        #pragma unroll
        for (int p = 0; p < 4; p++) {
            int c = t + p*256;
            int row = c >> 4, col4 = c & 15;
            float4 v = *(const float4*)(g_xv + gbase + (size_t)row*Dm + col4*4);
            float inv = __fdividef(1.f, g_rs[((size_t)(b*Nn + n0 + row))*Hh + h]);
            float4 sv = {v.x*inv, v.y*inv, v.z*inv, v.w*inv};
            *(uint2*)(smX + row*144 + col4*8) = f4_to_bf16x4(sv);
        }
        CPWAIT0();
        __syncthreads();

        if (t < 64) {
            const __nv_bfloat16* Eb = (const __nv_bfloat16*)smE;
            float s = 0.f;
            #pragma unroll 8
            for (int n = 0; n < 64; n++) s += __bfloat162float(Eb[n*72 + t]);
            Sacc += s;
        }
        #pragma unroll
        for (int ks = 0; ks < 4; ks++) {
            uint32_t a[4];
            ldsm4t(a, aoff + ks*16*144);
            #pragma unroll
            for (int dq = 0; dq < 2; dq++) {
                uint32_t bf[4];
                ldsm4t(bf, boff + ks*16*144 + dq*32);
                hmma(acc[dq*2],   a, bf[0], bf[1]);
                hmma(acc[dq*2+1], a, bf[2], bf[3]);
            }
        }
        __syncthreads();
    }
    float* pp = g_pool + ((size_t)(b*Hh + h)*Rr)*HDd;
    #pragma unroll
    for (int i = 0; i < 4; i++) {
        int r = r_base + (lane >> 2);
        int d = d_base + i*8 + (lane & 3)*2;
        atomicAdd(&pp[r*HDd + d],       acc[i][0]);
        atomicAdd(&pp[r*HDd + d + 1],   acc[i][1]);
        atomicAdd(&pp[(r+8)*HDd + d],   acc[i][2]);
        atomicAdd(&pp[(r+8)*HDd + d+1], acc[i][3]);
    }
    if (t < 64) atomicAdd(&g_S[(b*Hh + h)*Rr + t], Sacc);
}

// ---------------- kfin: poolb = bf16(P0 / S) ----------------
__global__ void kfin() {
    int row = blockIdx.x*256 + threadIdx.x;
    float inv = 1.f / g_S[row];
    const float4* p = (const float4*)(g_pool + (size_t)row*HDd);
    uint2* q = (uint2*)(g_poolb + (size_t)row*HDd);
    #pragma unroll
    for (int i = 0; i < 16; i++) {
        float4 v = p[i];
        v.x *= inv; v.y *= inv; v.z *= inv; v.w *= inv;
        q[i] = f4_to_bf16x4(v);
    }
}

// ---------------- kout: out = sa*xv + sb*(E · P)  (HMMA per head) ----------------
#define KO_E  0                  // 64 rows x 528B
#define KO_P  33792              // 256 rows x 144B
#define SMEM_KOUT 70656
__global__ void __launch_bounds__(256)
kout(const float* __restrict__ alpha, const float* __restrict__ beta,
     float* __restrict__ out) {
    extern __shared__ char sm[];
    uint32_t smb = (uint32_t)__cvta_generic_to_shared(sm);
    const int t = threadIdx.x, w = t >> 5, lane = t & 31;
    const int b = blockIdx.x >> 7;
    const int n0 = (blockIdx.x & 127)*64;
    const int hw = w & 3, m_base = (w >> 2)*32;
    size_t gbase = ((size_t)(b*Nn + n0))*Dm;

    #pragma unroll
    for (int p = 0; p < 8; p++) {
        int c = t + p*256;
        int row = c >> 5, off = c & 31;
        cpa16(smb + KO_E + row*528 + off*16, g_eb + gbase + (size_t)row*Dm + off*8);
        int prow = c >> 3, poff = c & 7;
        cpa16(smb + KO_P + prow*144 + poff*16,
              g_poolb + (size_t)b*(Hh*Rr*HDd) + prow*64 + poff*8);
    }
    CPCOMMIT();
    CPWAIT0();
    __syncthreads();

    float acc[2][8][4];
    #pragma unroll
    for (int i = 0; i < 2; i++)
        #pragma unroll
        for (int j = 0; j < 8; j++)
            #pragma unroll
            for (int q = 0; q < 4; q++) acc[i][j][q] = 0.f;

    uint32_t aoff = smb + KO_E + (uint32_t)((m_base + (lane & 15))*528)
                  + (uint32_t)(hw*128) + (lane >> 4)*16;
    uint32_t boff = smb + KO_P + (uint32_t)(hw*9216)
                  + (uint32_t)((lane & 15)*144) + (uint32_t)((lane >> 4)*16);

    #pragma unroll
    for (int ks = 0; ks < 4; ks++) {
        uint32_t a0[4], a1[4];
        ldsm4(a0, aoff + ks*32);
        ldsm4(a1, aoff + ks*32 + 16*528);
        #pragma unroll
        for (int dq = 0; dq < 4; dq++) {
            uint32_t bf[4];
            ldsm4t(bf, boff + ks*16*144 + dq*32);
            hmma(acc[0][dq*2],   a0, bf[0], bf[1]);
            hmma(acc[0][dq*2+1], a0, bf[2], bf[3]);
            hmma(acc[1][dq*2],   a1, bf[0], bf[1]);
            hmma(acc[1][dq*2+1], a1, bf[2], bf[3]);
        }
    }

    float sa = 1.f / (1.f + __expf(-alpha[hw]));
    float sb = 1.f / (1.f + __expf(-beta[hw]));
    #pragma unroll
    for (int mt = 0; mt < 2; mt++)
        #pragma unroll
        for (int j = 0; j < 8; j++) {
            int row = m_base + mt*16 + (lane >> 2);
            int col = hw*64 + j*8 + (lane & 3)*2;
            const float* c = acc[mt][j];
            {
                float2 xv = *(const float2*)(g_xv + gbase + (size_t)row*Dm + col);
                float2 o = {fmaf(sa, xv.x, sb*c[0]), fmaf(sa, xv.y, sb*c[1])};
                *(float2*)(out + gbase + (size_t)row*Dm + col) = o;
            }
            {
                float2 xv = *(const float2*)(g_xv + gbase + (size_t)(row+8)*Dm + col);
                float2 o = {fmaf(sa, xv.x, sb*c[2]), fmaf(sa, xv.y, sb*c[3])};
                *(float2*)(out + gbase + (size_t)(row+8)*Dm + col) = o;
            }
        }
}

extern "C" void kernel_launch(void* const* d_in, const int* in_sizes, int n_in,
                              void* d_out, int out_size) {
    const float* x     = (const float*)d_in[0];
    const float* z     = (const float*)d_in[1];
    const float* Wq    = (const float*)d_in[2];
    const float* bq    = (const float*)d_in[3];
    const float* K     = (const float*)d_in[4];
    const float* Wv    = (const float*)d_in[5];
    const float* bv    = (const float*)d_in[6];
    const float* alpha = (const float*)d_in[7];
    const float* beta  = (const float*)d_in[8];
    float* out = (float*)d_out;

    cudaFuncSetAttribute(kgemm_mma, cudaFuncAttributeMaxDynamicSharedMemorySize, SMEM_MMA);
    cudaFuncSetAttribute(kout,      cudaFuncAttributeMaxDynamicSharedMemorySize, SMEM_KOUT);

    kzero<<<512, 256>>>();
    kprep<<<Dm + 1, 256>>>(Wq, bq, K);
    kprep2<<<Dm, 256>>>(Wv);
    kgemm_mma<<<dim3(Mm/128, 2, 2), 256, SMEM_MMA>>>(x, z, bv);  // both GEMMs, one grid
    kpool<<<dim3(8, Hh, Bz), 256>>>();
    kfin<<<8, 256>>>();
    kout<<<Mm/64, 256, SMEM_KOUT>>>(alpha, beta, out);
}

// round 9
// speedup vs baseline: 1.1840x; 1.1840x over previous
#include <cuda_runtime.h>
#include <cuda_bf16.h>
#include <cstdint>

#define Bz  8
#define Nn  8192
#define Dm  256
#define Hh  4
#define Rr  64
#define HDd 64
#define Mm  (Bz*Nn)

typedef unsigned long long u64;

// ---------------- device scratch ----------------
__device__ float g_bK[Dm];
__device__ float g_xv[(size_t)Mm*Dm];                 // fp32 xv (exact gate term)
__device__ __nv_bfloat16 g_eb  [(size_t)Mm*Dm];       // bf16 raw exp(attn)
__device__ float g_rs[(size_t)Mm*Hh];                 // fp32 rowsum of e per (n,h)
__device__ float g_pool[Bz*Hh*Rr*HDd];                // fp32 P0 accumulator
__device__ __nv_bfloat16 g_poolb[Bz*Hh*Rr*HDd];       // bf16 P0/S
__device__ float g_S [Bz*Hh*Rr];
__device__ __nv_bfloat16 g_Wh[2][Dm*Dm];              // bf16 hi image of W ([k][n])
__device__ __nv_bfloat16 g_Wl[2][Dm*Dm];              // bf16 lo image (used by gemm0 only)

// ---------------- helpers ----------------
__device__ __forceinline__ void cpa16(uint32_t d, const void* s) {
    asm volatile("cp.async.cg.shared.global [%0], [%1], 16;" :: "r"(d), "l"(s));
}
#define CPCOMMIT() asm volatile("cp.async.commit_group;")
#define CPWAIT0()  asm volatile("cp.async.wait_group 0;")

__device__ __forceinline__ void ldsm4(uint32_t* r, uint32_t a) {
    asm volatile("ldmatrix.sync.aligned.m8n8.x4.shared.b16 {%0,%1,%2,%3}, [%4];"
        : "=r"(r[0]), "=r"(r[1]), "=r"(r[2]), "=r"(r[3]) : "r"(a));
}
__device__ __forceinline__ void ldsm4t(uint32_t* r, uint32_t a) {
    asm volatile("ldmatrix.sync.aligned.m8n8.x4.trans.shared.b16 {%0,%1,%2,%3}, [%4];"
        : "=r"(r[0]), "=r"(r[1]), "=r"(r[2]), "=r"(r[3]) : "r"(a));
}
__device__ __forceinline__ void hmma(float* c, const uint32_t* a, uint32_t b0, uint32_t b1) {
    asm volatile("mma.sync.aligned.m16n8k16.row.col.f32.bf16.bf16.f32 "
        "{%0,%1,%2,%3}, {%4,%5,%6,%7}, {%8,%9}, {%0,%1,%2,%3};"
        : "+f"(c[0]), "+f"(c[1]), "+f"(c[2]), "+f"(c[3])
        : "r"(a[0]), "r"(a[1]), "r"(a[2]), "r"(a[3]), "r"(b0), "r"(b1));
}
__device__ __forceinline__ uint2 f4_to_bf16x4(float4 v) {
    uint32_t a, b;
    asm("cvt.rn.bf16x2.f32 %0, %1, %2;" : "=r"(a) : "f"(v.y), "f"(v.x));
    asm("cvt.rn.bf16x2.f32 %0, %1, %2;" : "=r"(b) : "f"(v.w), "f"(v.z));
    return make_uint2(a, b);
}

// ---------------- small kernels ----------------
__global__ void kzero() {
    int i = blockIdx.x*blockDim.x + threadIdx.x;
    if (i < Bz*Hh*Rr*HDd) g_pool[i] = 0.f;
    if (i < Bz*Hh*Rr)     g_S[i]   = 0.f;
}

__global__ void kprep(const float* __restrict__ Wq, const float* __restrict__ bq,
                      const float* __restrict__ K) {
    int col = threadIdx.x;
    int h = col >> 6, r = col & 63;
    const float* Krow = K + r*Dm + h*HDd;
    if (blockIdx.x < Dm) {
        int c = blockIdx.x;
        const float* wq = Wq + c*Dm + h*HDd;
        float s = 0.f;
        #pragma unroll 16
        for (int d = 0; d < HDd; d++) s = fmaf(wq[d], Krow[d], s);
        s *= 0.125f;
        __nv_bfloat16 hi = __float2bfloat16(s);
        g_Wh[1][c*Dm + col] = hi;
        g_Wl[1][c*Dm + col] = __float2bfloat16(s - __bfloat162float(hi));
    } else {
        float s = 0.f;
        #pragma unroll 16
        for (int d = 0; d < HDd; d++) s = fmaf(bq[h*HDd + d], Krow[d], s);
        g_bK[col] = 0.125f * s;
    }
}

__global__ void kprep2(const float* __restrict__ Wv) {
    int k = blockIdx.x, n = threadIdx.x;
    float wv = Wv[(size_t)k*Dm + n];
    __nv_bfloat16 hi = __float2bfloat16(wv);
    g_Wh[0][k*Dm + n] = hi;
    g_Wl[0][k*Dm + n] = __float2bfloat16(wv - __bfloat162float(hi));
}

// ---------------- HMMA GEMM: C[128,128] per CTA, K=256 (R6 shape) ----------------
// smem: Ah[128][72] bf16 @0 (18432), Al @18432, Bh[64][136] @36864 (17408), Bl @54272
// C fp32 [128][132] aliases @0 after mainloop.
#define AH_OFF 0
#define AL_OFF 18432
#define BH_OFF 36864
#define BL_OFF 54272
#define SMEM_MMA 71680

__global__ void __launch_bounds__(256, 2)
kgemm_mma(const float* __restrict__ A, const float* __restrict__ bias, int gemm) {
    extern __shared__ char sm[];
    uint32_t smb = (uint32_t)__cvta_generic_to_shared(sm);
    const int t = threadIdx.x, w = t >> 5, lane = t & 31;
    const int m0 = blockIdx.x*128, nh = blockIdx.y;
    const __nv_bfloat16* Wh = g_Wh[gemm];
    const __nv_bfloat16* Wl = g_Wl[gemm];
    const float* bp = gemm ? g_bK : bias;

    float acc[2][8][4];
    #pragma unroll
    for (int i = 0; i < 2; i++)
        #pragma unroll
        for (int j = 0; j < 8; j++)
            #pragma unroll
            for (int q = 0; q < 4; q++) acc[i][j][q] = 0.f;

    const int wm = (w >> 1)*32, wn = (w & 1)*64;
    uint32_t aoff = smb + AH_OFF + (uint32_t)((wm + (lane & 15))*144) + (lane >> 4)*16;
    uint32_t boff = smb + BH_OFF + (uint32_t)((lane & 15)*272) + (uint32_t)((wn + (lane >> 4)*8)*2);

    for (int kc = 0; kc < 4; kc++) {
        // stage B hi (+lo only for gemm0) via cp.async
        {
            const __nv_bfloat16* srcH = Wh + (size_t)(kc*64)*Dm + nh*128;
            const __nv_bfloat16* srcL = Wl + (size_t)(kc*64)*Dm + nh*128;
            #pragma unroll
            for (int p = 0; p < 4; p++) {
                int idx = t + p*256;
                int row = idx >> 4, seg = idx & 15;
                uint32_t d = smb + BH_OFF + (uint32_t)(row*272 + seg*16);
                cpa16(d, srcH + (size_t)row*Dm + seg*8);
                if (gemm == 0)
                    cpa16(d + (BL_OFF - BH_OFF), srcL + (size_t)row*Dm + seg*8);
            }
            CPCOMMIT();
        }
        // stage A: fp32 -> bf16 hi/lo (overlaps B's cp.async flight)
        {
            int row = t >> 1, kq = (t & 1)*32;
            const float4* ar = (const float4*)(A + (size_t)(m0 + row)*Dm + kc*64 + kq);
            char* wbH = sm + AH_OFF + row*144 + kq*2;
            char* wbL = sm + AL_OFF + row*144 + kq*2;
            #pragma unroll
            for (int j4 = 0; j4 < 8; j4++) {
                float4 v = ar[j4];
                uint32_t h01, h23, q01, q23;
                asm("cvt.rn.bf16x2.f32 %0, %1, %2;" : "=r"(h01) : "f"(v.y), "f"(v.x));
                asm("cvt.rn.bf16x2.f32 %0, %1, %2;" : "=r"(h23) : "f"(v.w), "f"(v.z));
                float l0 = v.x - __uint_as_float(h01 << 16);
                float l1 = v.y - __uint_as_float(h01 & 0xffff0000u);
                float l2 = v.z - __uint_as_float(h23 << 16);
                float l3 = v.w - __uint_as_float(h23 & 0xffff0000u);
                asm("cvt.rn.bf16x2.f32 %0, %1, %2;" : "=r"(q01) : "f"(l1), "f"(l0));
                asm("cvt.rn.bf16x2.f32 %0, %1, %2;" : "=r"(q23) : "f"(l3), "f"(l2));
                *(uint2*)(wbH + j4*8) = make_uint2(h01, h23);
                *(uint2*)(wbL + j4*8) = make_uint2(q01, q23);
            }
        }
        CPWAIT0();
        __syncthreads();

        if (gemm == 0) {
            #pragma unroll
            for (int ks = 0; ks < 4; ks++) {
                uint32_t ah[2][4], al[2][4];
                uint32_t ab = aoff + ks*32;
                ldsm4(ah[0], ab);
                ldsm4(ah[1], ab + 16*144);
                ldsm4(al[0], ab + (AL_OFF - AH_OFF));
                ldsm4(al[1], ab + (AL_OFF - AH_OFF) + 16*144);
                uint32_t bb = boff + ks*16*272;
                #pragma unroll
                for (int nq = 0; nq < 4; nq++) {
                    uint32_t bh[4], bl[4];
                    ldsm4t(bh, bb + nq*32);
                    ldsm4t(bl, bb + nq*32 + (BL_OFF - BH_OFF));
                    #pragma unroll
                    for (int mt = 0; mt < 2; mt++) {
                        #pragma unroll
                        for (int sub = 0; sub < 2; sub++) {
                            float* c = acc[mt][nq*2 + sub];
                            hmma(c, ah[mt], bh[sub*2], bh[sub*2+1]);
                            hmma(c, al[mt], bh[sub*2], bh[sub*2+1]);
                            hmma(c, ah[mt], bl[sub*2], bl[sub*2+1]);
                        }
                    }
                }
            }
        } else {
            // 2-product attn: (Ahi + Alo) * Whi — W-lo omitted (validated: err cancels in softmax)
            #pragma unroll
            for (int ks = 0; ks < 4; ks++) {
                uint32_t ah[2][4], al[2][4];
                uint32_t ab = aoff + ks*32;
                ldsm4(ah[0], ab);
                ldsm4(ah[1], ab + 16*144);
                ldsm4(al[0], ab + (AL_OFF - AH_OFF));
                ldsm4(al[1], ab + (AL_OFF - AH_OFF) + 16*144);
                uint32_t bb = boff + ks*16*272;
                #pragma unroll
                for (int nq = 0; nq < 4; nq++) {
                    uint32_t bh[4];
                    ldsm4t(bh, bb + nq*32);
                    #pragma unroll
                    for (int mt = 0; mt < 2; mt++) {
                        #pragma unroll
                        for (int sub = 0; sub < 2; sub++) {
                            float* c = acc[mt][nq*2 + sub];
                            hmma(c, ah[mt], bh[sub*2], bh[sub*2+1]);
                            hmma(c, al[mt], bh[sub*2], bh[sub*2+1]);
                        }
                    }
                }
            }
        }
        __syncthreads();
    }

    // ---- epilogue: C through smem (coalesced) ----
    float* Cs = (float*)sm;
    #pragma unroll
    for (int mt = 0; mt < 2; mt++)
        #pragma unroll
        for (int j = 0; j < 8; j++) {
            int r = wm + mt*16 + (lane >> 2);
            int c = wn + j*8 + (lane & 3)*2;
            *(float2*)&Cs[r*132 + c]     = make_float2(acc[mt][j][0], acc[mt][j][1]);
            *(float2*)&Cs[(r+8)*132 + c] = make_float2(acc[mt][j][2], acc[mt][j][3]);
        }
    __syncthreads();

    float4 bv4 = *(const float4*)(bp + nh*128 + lane*4);
    if (gemm == 0) {
        #pragma unroll
        for (int p = 0; p < 16; p++) {
            int row = p*8 + w;
            float4 v = *(const float4*)&Cs[row*132 + lane*4];
            v.x += bv4.x; v.y += bv4.y; v.z += bv4.z; v.w += bv4.w;
            *(float4*)(g_xv + (size_t)(m0 + row)*Dm + nh*128 + lane*4) = v;
        }
    } else {
        #pragma unroll
        for (int p = 0; p < 16; p++) {
            int row = p*8 + w;
            float4 v = *(const float4*)&Cs[row*132 + lane*4];
            v.x = __expf(v.x + bv4.x);
            v.y = __expf(v.y + bv4.y);
            v.z = __expf(v.z + bv4.z);
            v.w = __expf(v.w + bv4.w);
            float s = v.x + v.y + v.z + v.w;
            s += __shfl_xor_sync(0xffffffffu, s, 1);
            s += __shfl_xor_sync(0xffffffffu, s, 2);
            s += __shfl_xor_sync(0xffffffffu, s, 4);
            s += __shfl_xor_sync(0xffffffffu, s, 8);
            *(uint2*)(g_eb + (size_t)(m0 + row)*Dm + nh*128 + lane*4) = f4_to_bf16x4(v);
            if ((lane & 15) == 0)
                g_rs[(size_t)(m0 + row)*Hh + nh*2 + (lane >> 4)] = s;
        }
    }
}

// ---------------- kpool: P0[r,d] = sum_n e_bf * bf16(xv/rs)  (HMMA) ----------------
__global__ void __launch_bounds__(256, 4) kpool() {
    __shared__ char smE[64*144];
    __shared__ char smX[64*144];
    uint32_t sE = (uint32_t)__cvta_generic_to_shared(smE);
    uint32_t sX = (uint32_t)__cvta_generic_to_shared(smX);
    const int t = threadIdx.x, w = t >> 5, lane = t & 31;
    const int ch = blockIdx.x, h = blockIdx.y, b = blockIdx.z;
    const int r_base = (w & 3)*16, d_base = (w >> 2)*32;
    float acc[4][4];
    #pragma unroll
    for (int i = 0; i < 4; i++)
        #pragma unroll
        for (int q = 0; q < 4; q++) acc[i][q] = 0.f;
    float Sacc = 0.f;

    uint32_t aoff = sE + (uint32_t)((((lane >> 4) << 3) + (lane & 7))*144)
                  + (uint32_t)((r_base + (((lane >> 3) & 1) << 3))*2);
    uint32_t boff = sX + (uint32_t)((lane & 15)*144) + (uint32_t)((d_base + (lane >> 4)*8)*2);

    for (int tile = 0; tile < 16; tile++) {
        int n0 = ch*1024 + tile*64;
        size_t gbase = ((size_t)(b*Nn + n0))*Dm + h*64;
        #pragma unroll
        for (int p = 0; p < 2; p++) {
            int c = t + p*256;
            int row = c >> 3, off = c & 7;
            cpa16(sE + row*144 + off*16, g_eb + gbase + (size_t)row*Dm + off*8);
        }
        CPCOMMIT();
        // xv fp32 -> scale by 1/rs -> bf16 -> smX
        #pragma unroll
        for (int p = 0; p < 4; p++) {
            int c = t + p*256;
            int row = c >> 4, col4 = c & 15;
            float4 v = *(const float4*)(g_xv + gbase + (size_t)row*Dm + col4*4);
            float inv = __fdividef(1.f, g_rs[((size_t)(b*Nn + n0 + row))*Hh + h]);
            float4 sv = {v.x*inv, v.y*inv, v.z*inv, v.w*inv};
            *(uint2*)(smX + row*144 + col4*8) = f4_to_bf16x4(sv);
        }
        CPWAIT0();
        __syncthreads();

        if (t < 64) {
            const __nv_bfloat16* Eb = (const __nv_bfloat16*)smE;
            float s = 0.f;
            #pragma unroll 8
            for (int n = 0; n < 64; n++) s += __bfloat162float(Eb[n*72 + t]);
            Sacc += s;
        }
        #pragma unroll
        for (int ks = 0; ks < 4; ks++) {
            uint32_t a[4];
            ldsm4t(a, aoff + ks*16*144);
            #pragma unroll
            for (int dq = 0; dq < 2; dq++) {
                uint32_t bf[4];
                ldsm4t(bf, boff + ks*16*144 + dq*32);
                hmma(acc[dq*2],   a, bf[0], bf[1]);
                hmma(acc[dq*2+1], a, bf[2], bf[3]);
            }
        }
        __syncthreads();
    }
    float* pp = g_pool + ((size_t)(b*Hh + h)*Rr)*HDd;
    #pragma unroll
    for (int i = 0; i < 4; i++) {
        int r = r_base + (lane >> 2);
        int d = d_base + i*8 + (lane & 3)*2;
        atomicAdd(&pp[r*HDd + d],       acc[i][0]);
        atomicAdd(&pp[r*HDd + d + 1],   acc[i][1]);
        atomicAdd(&pp[(r+8)*HDd + d],   acc[i][2]);
        atomicAdd(&pp[(r+8)*HDd + d+1], acc[i][3]);
    }
    if (t < 64) atomicAdd(&g_S[(b*Hh + h)*Rr + t], Sacc);
}

// ---------------- kfin: poolb = bf16(P0 / S) ----------------
__global__ void kfin() {
    int row = blockIdx.x*256 + threadIdx.x;
    float inv = 1.f / g_S[row];
    const float4* p = (const float4*)(g_pool + (size_t)row*HDd);
    uint2* q = (uint2*)(g_poolb + (size_t)row*HDd);
    #pragma unroll
    for (int i = 0; i < 16; i++) {
        float4 v = p[i];
        v.x *= inv; v.y *= inv; v.z *= inv; v.w *= inv;
        q[i] = f4_to_bf16x4(v);
    }
}

// ---------------- kout: out = sa*xv + sb*(E · P)  (HMMA per head) ----------------
#define KO_E  0                  // 64 rows x 528B
#define KO_P  33792              // 256 rows x 144B
#define SMEM_KOUT 70656
__global__ void __launch_bounds__(256)
kout(const float* __restrict__ alpha, const float* __restrict__ beta,
     float* __restrict__ out) {
    extern __shared__ char sm[];
    uint32_t smb = (uint32_t)__cvta_generic_to_shared(sm);
    const int t = threadIdx.x, w = t >> 5, lane = t & 31;
    const int b = blockIdx.x >> 7;
    const int n0 = (blockIdx.x & 127)*64;
    const int hw = w & 3, m_base = (w >> 2)*32;
    size_t gbase = ((size_t)(b*Nn + n0))*Dm;

    #pragma unroll
    for (int p = 0; p < 8; p++) {
        int c = t + p*256;
        int row = c >> 5, off = c & 31;
        cpa16(smb + KO_E + row*528 + off*16, g_eb + gbase + (size_t)row*Dm + off*8);
        int prow = c >> 3, poff = c & 7;
        cpa16(smb + KO_P + prow*144 + poff*16,
              g_poolb + (size_t)b*(Hh*Rr*HDd) + prow*64 + poff*8);
    }
    CPCOMMIT();
    CPWAIT0();
    __syncthreads();

    float acc[2][8][4];
    #pragma unroll
    for (int i = 0; i < 2; i++)
        #pragma unroll
        for (int j = 0; j < 8; j++)
            #pragma unroll
            for (int q = 0; q < 4; q++) acc[i][j][q] = 0.f;

    uint32_t aoff = smb + KO_E + (uint32_t)((m_base + (lane & 15))*528)
                  + (uint32_t)(hw*128) + (lane >> 4)*16;
    uint32_t boff = smb + KO_P + (uint32_t)(hw*9216)
                  + (uint32_t)((lane & 15)*144) + (uint32_t)((lane >> 4)*16);

    #pragma unroll
    for (int ks = 0; ks < 4; ks++) {
        uint32_t a0[4], a1[4];
        ldsm4(a0, aoff + ks*32);
        ldsm4(a1, aoff + ks*32 + 16*528);
        #pragma unroll
        for (int dq = 0; dq < 4; dq++) {
            uint32_t bf[4];
            ldsm4t(bf, boff + ks*16*144 + dq*32);
            hmma(acc[0][dq*2],   a0, bf[0], bf[1]);
            hmma(acc[0][dq*2+1], a0, bf[2], bf[3]);
            hmma(acc[1][dq*2],   a1, bf[0], bf[1]);
            hmma(acc[1][dq*2+1], a1, bf[2], bf[3]);
        }
    }

    float sa = 1.f / (1.f + __expf(-alpha[hw]));
    float sb = 1.f / (1.f + __expf(-beta[hw]));
    #pragma unroll
    for (int mt = 0; mt < 2; mt++)
        #pragma unroll
        for (int j = 0; j < 8; j++) {
            int row = m_base + mt*16 + (lane >> 2);
            int col = hw*64 + j*8 + (lane & 3)*2;
            const float* c = acc[mt][j];
            {
                float2 xv = *(const float2*)(g_xv + gbase + (size_t)row*Dm + col);
                float2 o = {fmaf(sa, xv.x, sb*c[0]), fmaf(sa, xv.y, sb*c[1])};
                *(float2*)(out + gbase + (size_t)row*Dm + col) = o;
            }
            {
                float2 xv = *(const float2*)(g_xv + gbase + (size_t)(row+8)*Dm + col);
                float2 o = {fmaf(sa, xv.x, sb*c[2]), fmaf(sa, xv.y, sb*c[3])};
                *(float2*)(out + gbase + (size_t)(row+8)*Dm + col) = o;
            }
        }
}

extern "C" void kernel_launch(void* const* d_in, const int* in_sizes, int n_in,
                              void* d_out, int out_size) {
    const float* x     = (const float*)d_in[0];
    const float* z     = (const float*)d_in[1];
    const float* Wq    = (const float*)d_in[2];
    const float* bq    = (const float*)d_in[3];
    const float* K     = (const float*)d_in[4];
    const float* Wv    = (const float*)d_in[5];
    const float* bv    = (const float*)d_in[6];
    const float* alpha = (const float*)d_in[7];
    const float* beta  = (const float*)d_in[8];
    float* out = (float*)d_out;

    cudaFuncSetAttribute(kgemm_mma, cudaFuncAttributeMaxDynamicSharedMemorySize, SMEM_MMA);
    cudaFuncSetAttribute(kout,      cudaFuncAttributeMaxDynamicSharedMemorySize, SMEM_KOUT);

    kzero<<<512, 256>>>();
    kprep<<<Dm + 1, 256>>>(Wq, bq, K);
    kprep2<<<Dm, 256>>>(Wv);
    kgemm_mma<<<dim3(Mm/128, 2), 256, SMEM_MMA>>>(z, bv, 1);   // attn (2-product)
    kgemm_mma<<<dim3(Mm/128, 2), 256, SMEM_MMA>>>(x, bv, 0);   // xv (3-product)
    kpool<<<dim3(8, Hh, Bz), 256>>>();
    kfin<<<8, 256>>>();
    kout<<<Mm/64, 256, SMEM_KOUT>>>(alpha, beta, out);
}

// round 10
// speedup vs baseline: 1.2474x; 1.0535x over previous
#include <cuda_runtime.h>
#include <cuda_bf16.h>
#include <cstdint>

#define Bz  8
#define Nn  8192
#define Dm  256
#define Hh  4
#define Rr  64
#define HDd 64
#define Mm  (Bz*Nn)

typedef unsigned long long u64;

// ---------------- device scratch ----------------
__device__ float g_bK[Dm];
__device__ float g_xv[(size_t)Mm*Dm];                 // fp32 xv (exact gate term)
__device__ __nv_bfloat16 g_eb  [(size_t)Mm*Dm];       // bf16 raw exp(attn)
__device__ float g_rs[(size_t)Mm*Hh];                 // fp32 rowsum of e per (n,h)
__device__ float g_pool[Bz*Hh*Rr*HDd];                // fp32 P0 accumulator
__device__ __nv_bfloat16 g_poolb[Bz*Hh*Rr*HDd];       // bf16 P0/S
__device__ float g_S [Bz*Hh*Rr];
__device__ __nv_bfloat16 g_Wh[2][Dm*Dm];              // bf16 hi image of W ([k][n])
__device__ __nv_bfloat16 g_Wl[2][Dm*Dm];              // bf16 lo image (used by gemm0 only)

// ---------------- helpers ----------------
__device__ __forceinline__ void cpa16(uint32_t d, const void* s) {
    asm volatile("cp.async.cg.shared.global [%0], [%1], 16;" :: "r"(d), "l"(s));
}
#define CPCOMMIT() asm volatile("cp.async.commit_group;")
#define CPWAIT0()  asm volatile("cp.async.wait_group 0;")

__device__ __forceinline__ void ldsm4(uint32_t* r, uint32_t a) {
    asm volatile("ldmatrix.sync.aligned.m8n8.x4.shared.b16 {%0,%1,%2,%3}, [%4];"
        : "=r"(r[0]), "=r"(r[1]), "=r"(r[2]), "=r"(r[3]) : "r"(a));
}
__device__ __forceinline__ void ldsm4t(uint32_t* r, uint32_t a) {
    asm volatile("ldmatrix.sync.aligned.m8n8.x4.trans.shared.b16 {%0,%1,%2,%3}, [%4];"
        : "=r"(r[0]), "=r"(r[1]), "=r"(r[2]), "=r"(r[3]) : "r"(a));
}
__device__ __forceinline__ void hmma(float* c, const uint32_t* a, uint32_t b0, uint32_t b1) {
    asm volatile("mma.sync.aligned.m16n8k16.row.col.f32.bf16.bf16.f32 "
        "{%0,%1,%2,%3}, {%4,%5,%6,%7}, {%8,%9}, {%0,%1,%2,%3};"
        : "+f"(c[0]), "+f"(c[1]), "+f"(c[2]), "+f"(c[3])
        : "r"(a[0]), "r"(a[1]), "r"(a[2]), "r"(a[3]), "r"(b0), "r"(b1));
}
__device__ __forceinline__ uint2 f4_to_bf16x4(float4 v) {
    uint32_t a, b;
    asm("cvt.rn.bf16x2.f32 %0, %1, %2;" : "=r"(a) : "f"(v.y), "f"(v.x));
    asm("cvt.rn.bf16x2.f32 %0, %1, %2;" : "=r"(b) : "f"(v.w), "f"(v.z));
    return make_uint2(a, b);
}

// ---------------- small kernels ----------------
__global__ void kzero() {
    int i = blockIdx.x*blockDim.x + threadIdx.x;
    if (i < Bz*Hh*Rr*HDd) g_pool[i] = 0.f;
    if (i < Bz*Hh*Rr)     g_S[i]   = 0.f;
}

__global__ void kprep(const float* __restrict__ Wq, const float* __restrict__ bq,
                      const float* __restrict__ K) {
    int col = threadIdx.x;
    int h = col >> 6, r = col & 63;
    const float* Krow = K + r*Dm + h*HDd;
    if (blockIdx.x < Dm) {
        int c = blockIdx.x;
        const float* wq = Wq + c*Dm + h*HDd;
        float s = 0.f;
        #pragma unroll 16
        for (int d = 0; d < HDd; d++) s = fmaf(wq[d], Krow[d], s);
        s *= 0.125f;
        __nv_bfloat16 hi = __float2bfloat16(s);
        g_Wh[1][c*Dm + col] = hi;
        g_Wl[1][c*Dm + col] = __float2bfloat16(s - __bfloat162float(hi));
    } else {
        float s = 0.f;
        #pragma unroll 16
        for (int d = 0; d < HDd; d++) s = fmaf(bq[h*HDd + d], Krow[d], s);
        g_bK[col] = 0.125f * s;
    }
}

__global__ void kprep2(const float* __restrict__ Wv) {
    int k = blockIdx.x, n = threadIdx.x;
    float wv = Wv[(size_t)k*Dm + n];
    __nv_bfloat16 hi = __float2bfloat16(wv);
    g_Wh[0][k*Dm + n] = hi;
    g_Wl[0][k*Dm + n] = __float2bfloat16(wv - __bfloat162float(hi));
}

// ---------------- HMMA GEMM: C[128,128] per CTA, K=256 in 8 chunks of 32 ----------
// A stage s: hi @ s*20480 (128 rows x 80B), lo @ +10240
// B stage s: hi @ 40960 + s*17408 (32 rows x 272B), lo @ +8704 (gemm0 only)
// Epilogue: C fp32 [128][132] aliases @0.
#define KC     32
#define ABUF(s) ((s)*20480)
#define A_LOO   10240
#define BBUF(s) (40960 + (s)*17408)
#define B_LOO   8704
#define SMEM_MMA 75776

__global__ void __launch_bounds__(256, 2)
kgemm_mma(const float* __restrict__ A, const float* __restrict__ bias, int gemm) {
    extern __shared__ char sm[];
    uint32_t smb = (uint32_t)__cvta_generic_to_shared(sm);
    const int t = threadIdx.x, w = t >> 5, lane = t & 31;
    const int m0 = blockIdx.x*128, nh = blockIdx.y;
    const __nv_bfloat16* Wh = g_Wh[gemm];
    const __nv_bfloat16* Wl = g_Wl[gemm];
    const float* bp = gemm ? g_bK : bias;
    const int wm = (w >> 1)*32, wn = (w & 1)*64;

    float acc[2][8][4];
    #pragma unroll
    for (int i = 0; i < 2; i++)
        #pragma unroll
        for (int j = 0; j < 8; j++)
            #pragma unroll
            for (int q = 0; q < 4; q++) acc[i][j][q] = 0.f;

#define STG_B(c, s)                                                           \
    {                                                                         \
        const __nv_bfloat16* srcH = Wh + (size_t)((c)*KC)*Dm + nh*128;        \
        const __nv_bfloat16* srcL = Wl + (size_t)((c)*KC)*Dm + nh*128;        \
        _Pragma("unroll")                                                     \
        for (int p = 0; p < 2; p++) {                                         \
            int idx = t + p*256;                                              \
            int row = idx >> 4, seg = idx & 15;                               \
            uint32_t d = smb + BBUF(s) + (uint32_t)(row*272 + seg*16);        \
            cpa16(d, srcH + (size_t)row*Dm + seg*8);                          \
            if (gemm == 0)                                                    \
                cpa16(d + B_LOO, srcL + (size_t)row*Dm + seg*8);              \
        }                                                                     \
        CPCOMMIT();                                                           \
    }
#define STG_A(c, s)                                                           \
    {                                                                         \
        int row = t >> 1, half = t & 1;                                       \
        const float4* ar = (const float4*)(A + (size_t)(m0 + row)*Dm + (c)*KC + half*16); \
        char* wbH = sm + ABUF(s) + row*80 + half*32;                          \
        char* wbL = wbH + A_LOO;                                              \
        _Pragma("unroll")                                                     \
        for (int j4 = 0; j4 < 4; j4++) {                                      \
            float4 v = ar[j4];                                                \
            uint32_t h01, h23, q01, q23;                                      \
            asm("cvt.rn.bf16x2.f32 %0, %1, %2;" : "=r"(h01) : "f"(v.y), "f"(v.x)); \
            asm("cvt.rn.bf16x2.f32 %0, %1, %2;" : "=r"(h23) : "f"(v.w), "f"(v.z)); \
            float l0 = v.x - __uint_as_float(h01 << 16);                      \
            float l1 = v.y - __uint_as_float(h01 & 0xffff0000u);              \
            float l2 = v.z - __uint_as_float(h23 << 16);                      \
            float l3 = v.w - __uint_as_float(h23 & 0xffff0000u);              \
            asm("cvt.rn.bf16x2.f32 %0, %1, %2;" : "=r"(q01) : "f"(l1), "f"(l0)); \
            asm("cvt.rn.bf16x2.f32 %0, %1, %2;" : "=r"(q23) : "f"(l3), "f"(l2)); \
            *(uint2*)(wbH + j4*8) = make_uint2(h01, h23);                     \
            *(uint2*)(wbL + j4*8) = make_uint2(q01, q23);                     \
        }                                                                     \
    }

    // prologue: stage chunk 0 into buffer 0
    STG_B(0, 0);
    STG_A(0, 0);

    for (int c = 0; c < 8; c++) {
        int s = c & 1;
        CPWAIT0();          // B(c) landed (only outstanding group)
        __syncthreads();    // all compute(c-1) done; all STS A(c) done
        if (c < 7) {
            STG_B(c + 1, s ^ 1);   // flight hidden under compute(c)
            STG_A(c + 1, s ^ 1);   // LDG stall covered by other warps' compute
        }
        uint32_t aoff = smb + ABUF(s) + (uint32_t)((wm + (lane & 15))*80) + (lane >> 4)*16;
        uint32_t boff = smb + BBUF(s) + (uint32_t)((lane & 15)*272) + (uint32_t)((wn + (lane >> 4)*8)*2);
        if (gemm == 0) {
            #pragma unroll
            for (int ks = 0; ks < 2; ks++) {
                uint32_t ah[2][4], al[2][4];
                uint32_t ab = aoff + ks*32;
                ldsm4(ah[0], ab);
                ldsm4(ah[1], ab + 16*80);
                ldsm4(al[0], ab + A_LOO);
                ldsm4(al[1], ab + A_LOO + 16*80);
                uint32_t bb = boff + ks*16*272;
                #pragma unroll
                for (int nq = 0; nq < 4; nq++) {
                    uint32_t bh[4], bl[4];
                    ldsm4t(bh, bb + nq*32);
                    ldsm4t(bl, bb + nq*32 + B_LOO);
                    #pragma unroll
                    for (int mt = 0; mt < 2; mt++) {
                        #pragma unroll
                        for (int sub = 0; sub < 2; sub++) {
                            float* cc = acc[mt][nq*2 + sub];
                            hmma(cc, ah[mt], bh[sub*2], bh[sub*2+1]);
                            hmma(cc, al[mt], bh[sub*2], bh[sub*2+1]);
                            hmma(cc, ah[mt], bl[sub*2], bl[sub*2+1]);
                        }
                    }
                }
            }
        } else {
            #pragma unroll
            for (int ks = 0; ks < 2; ks++) {
                uint32_t ah[2][4], al[2][4];
                uint32_t ab = aoff + ks*32;
                ldsm4(ah[0], ab);
                ldsm4(ah[1], ab + 16*80);
                ldsm4(al[0], ab + A_LOO);
                ldsm4(al[1], ab + A_LOO + 16*80);
                uint32_t bb = boff + ks*16*272;
                #pragma unroll
                for (int nq = 0; nq < 4; nq++) {
                    uint32_t bh[4];
                    ldsm4t(bh, bb + nq*32);
                    #pragma unroll
                    for (int mt = 0; mt < 2; mt++) {
                        #pragma unroll
                        for (int sub = 0; sub < 2; sub++) {
                            float* cc = acc[mt][nq*2 + sub];
                            hmma(cc, ah[mt], bh[sub*2], bh[sub*2+1]);
                            hmma(cc, al[mt], bh[sub*2], bh[sub*2+1]);
                        }
                    }
                }
            }
        }
    }
    __syncthreads();

    // ---- epilogue: C through smem (coalesced) ----
    float* Cs = (float*)sm;
    #pragma unroll
    for (int mt = 0; mt < 2; mt++)
        #pragma unroll
        for (int j = 0; j < 8; j++) {
            int r = wm + mt*16 + (lane >> 2);
            int c = wn + j*8 + (lane & 3)*2;
            *(float2*)&Cs[r*132 + c]     = make_float2(acc[mt][j][0], acc[mt][j][1]);
            *(float2*)&Cs[(r+8)*132 + c] = make_float2(acc[mt][j][2], acc[mt][j][3]);
        }
    __syncthreads();

    float4 bv4 = *(const float4*)(bp + nh*128 + lane*4);
    if (gemm == 0) {
        #pragma unroll
        for (int p = 0; p < 16; p++) {
            int row = p*8 + w;
            float4 v = *(const float4*)&Cs[row*132 + lane*4];
            v.x += bv4.x; v.y += bv4.y; v.z += bv4.z; v.w += bv4.w;
            *(float4*)(g_xv + (size_t)(m0 + row)*Dm + nh*128 + lane*4) = v;
        }
    } else {
        #pragma unroll
        for (int p = 0; p < 16; p++) {
            int row = p*8 + w;
            float4 v = *(const float4*)&Cs[row*132 + lane*4];
            v.x = __expf(v.x + bv4.x);
            v.y = __expf(v.y + bv4.y);
            v.z = __expf(v.z + bv4.z);
            v.w = __expf(v.w + bv4.w);
            float s = v.x + v.y + v.z + v.w;
            s += __shfl_xor_sync(0xffffffffu, s, 1);
            s += __shfl_xor_sync(0xffffffffu, s, 2);
            s += __shfl_xor_sync(0xffffffffu, s, 4);
            s += __shfl_xor_sync(0xffffffffu, s, 8);
            *(uint2*)(g_eb + (size_t)(m0 + row)*Dm + nh*128 + lane*4) = f4_to_bf16x4(v);
            if ((lane & 15) == 0)
                g_rs[(size_t)(m0 + row)*Hh + nh*2 + (lane >> 4)] = s;
        }
    }
}

// ---------------- kpool: P0[r,d] = sum_n e_bf * bf16(xv/rs), double-buffered ----------------
__global__ void __launch_bounds__(256, 4) kpool() {
    __shared__ char smE[2][64*144];
    __shared__ char smX[2][64*144];
    __shared__ float sred[256];
    uint32_t sE[2] = {(uint32_t)__cvta_generic_to_shared(smE[0]),
                      (uint32_t)__cvta_generic_to_shared(smE[1])};
    uint32_t sX[2] = {(uint32_t)__cvta_generic_to_shared(smX[0]),
                      (uint32_t)__cvta_generic_to_shared(smX[1])};
    const int t = threadIdx.x, w = t >> 5, lane = t & 31;
    const int ch = blockIdx.x, h = blockIdx.y, b = blockIdx.z;
    const int r_base = (w & 3)*16, d_base = (w >> 2)*32;
    float acc[4][4];
    #pragma unroll
    for (int i = 0; i < 4; i++)
        #pragma unroll
        for (int q = 0; q < 4; q++) acc[i][q] = 0.f;
    float Sacc = 0.f;
    const int scol = t & 63, sq = t >> 6;

#define STG_EX(tl, s)                                                         \
    {                                                                         \
        int n0 = ch*1024 + (tl)*64;                                           \
        size_t gbase = ((size_t)(b*Nn + n0))*Dm + h*64;                       \
        _Pragma("unroll")                                                     \
        for (int p = 0; p < 2; p++) {                                         \
            int c = t + p*256;                                                \
            int row = c >> 3, off = c & 7;                                    \
            cpa16(sE[s] + row*144 + off*16, g_eb + gbase + (size_t)row*Dm + off*8); \
        }                                                                     \
        CPCOMMIT();                                                           \
        _Pragma("unroll")                                                     \
        for (int p = 0; p < 4; p++) {                                         \
            int c = t + p*256;                                                \
            int row = c >> 4, col4 = c & 15;                                  \
            float4 v = *(const float4*)(g_xv + gbase + (size_t)row*Dm + col4*4); \
            float inv = __fdividef(1.f, g_rs[((size_t)(b*Nn + n0 + row))*Hh + h]); \
            float4 sv = {v.x*inv, v.y*inv, v.z*inv, v.w*inv};                 \
            *(uint2*)(smX[s] + row*144 + col4*8) = f4_to_bf16x4(sv);          \
        }                                                                     \
    }

    STG_EX(0, 0);

    for (int tile = 0; tile < 16; tile++) {
        int s = tile & 1;
        CPWAIT0();
        __syncthreads();
        if (tile < 15) STG_EX(tile + 1, s ^ 1);

        // distributed raw-e column sum: thread -> (col, quarter)
        {
            const __nv_bfloat16* Eb = (const __nv_bfloat16*)smE[s];
            float ps = 0.f;
            #pragma unroll
            for (int i = 0; i < 16; i++)
                ps += __bfloat162float(Eb[(sq*16 + i)*72 + scol]);
            Sacc += ps;
        }
        uint32_t aoff = sE[s] + (uint32_t)((((lane >> 4) << 3) + (lane & 7))*144)
                      + (uint32_t)((r_base + (((lane >> 3) & 1) << 3))*2);
        uint32_t boff = sX[s] + (uint32_t)((lane & 15)*144) + (uint32_t)((d_base + (lane >> 4)*8)*2);
        #pragma unroll
        for (int ks = 0; ks < 4; ks++) {
            uint32_t a[4];
            ldsm4t(a, aoff + ks*16*144);
            #pragma unroll
            for (int dq = 0; dq < 2; dq++) {
                uint32_t bf[4];
                ldsm4t(bf, boff + ks*16*144 + dq*32);
                hmma(acc[dq*2],   a, bf[0], bf[1]);
                hmma(acc[dq*2+1], a, bf[2], bf[3]);
            }
        }
    }
    float* pp = g_pool + ((size_t)(b*Hh + h)*Rr)*HDd;
    #pragma unroll
    for (int i = 0; i < 4; i++) {
        int r = r_base + (lane >> 2);
        int d = d_base + i*8 + (lane & 3)*2;
        atomicAdd(&pp[r*HDd + d],       acc[i][0]);
        atomicAdd(&pp[r*HDd + d + 1],   acc[i][1]);
        atomicAdd(&pp[(r+8)*HDd + d],   acc[i][2]);
        atomicAdd(&pp[(r+8)*HDd + d+1], acc[i][3]);
    }
    __syncthreads();
    sred[t] = Sacc;
    __syncthreads();
    if (t < 64)
        atomicAdd(&g_S[(b*Hh + h)*Rr + t],
                  sred[t] + sred[t+64] + sred[t+128] + sred[t+192]);
}

// ---------------- kfin: poolb = bf16(P0 / S) ----------------
__global__ void kfin() {
    int row = blockIdx.x*256 + threadIdx.x;
    float inv = 1.f / g_S[row];
    const float4* p = (const float4*)(g_pool + (size_t)row*HDd);
    uint2* q = (uint2*)(g_poolb + (size_t)row*HDd);
    #pragma unroll
    for (int i = 0; i < 16; i++) {
        float4 v = p[i];
        v.x *= inv; v.y *= inv; v.z *= inv; v.w *= inv;
        q[i] = f4_to_bf16x4(v);
    }
}

// ---------------- kout: out = sa*xv + sb*(E · P)  (HMMA per head) ----------------
#define KO_E  0                  // 64 rows x 528B
#define KO_P  33792              // 256 rows x 144B
#define SMEM_KOUT 70656
__global__ void __launch_bounds__(256)
kout(const float* __restrict__ alpha, const float* __restrict__ beta,
     float* __restrict__ out) {
    extern __shared__ char sm[];
    uint32_t smb = (uint32_t)__cvta_generic_to_shared(sm);
    const int t = threadIdx.x, w = t >> 5, lane = t & 31;
    const int b = blockIdx.x >> 7;
    const int n0 = (blockIdx.x & 127)*64;
    const int hw = w & 3, m_base = (w >> 2)*32;
    size_t gbase = ((size_t)(b*Nn + n0))*Dm;

    #pragma unroll
    for (int p = 0; p < 8; p++) {
        int c = t + p*256;
        int row = c >> 5, off = c & 31;
        cpa16(smb + KO_E + row*528 + off*16, g_eb + gbase + (size_t)row*Dm + off*8);
        int prow = c >> 3, poff = c & 7;
        cpa16(smb + KO_P + prow*144 + poff*16,
              g_poolb + (size_t)b*(Hh*Rr*HDd) + prow*64 + poff*8);
    }
    CPCOMMIT();
    CPWAIT0();
    __syncthreads();

    float acc[2][8][4];
    #pragma unroll
    for (int i = 0; i < 2; i++)
        #pragma unroll
        for (int j = 0; j < 8; j++)
            #pragma unroll
            for (int q = 0; q < 4; q++) acc[i][j][q] = 0.f;

    uint32_t aoff = smb + KO_E + (uint32_t)((m_base + (lane & 15))*528)
                  + (uint32_t)(hw*128) + (lane >> 4)*16;
    uint32_t boff = smb + KO_P + (uint32_t)(hw*9216)
                  + (uint32_t)((lane & 15)*144) + (uint32_t)((lane >> 4)*16);

    #pragma unroll
    for (int ks = 0; ks < 4; ks++) {
        uint32_t a0[4], a1[4];
        ldsm4(a0, aoff + ks*32);
        ldsm4(a1, aoff + ks*32 + 16*528);
        #pragma unroll
        for (int dq = 0; dq < 4; dq++) {
            uint32_t bf[4];
            ldsm4t(bf, boff + ks*16*144 + dq*32);
            hmma(acc[0][dq*2],   a0, bf[0], bf[1]);
            hmma(acc[0][dq*2+1], a0, bf[2], bf[3]);
            hmma(acc[1][dq*2],   a1, bf[0], bf[1]);
            hmma(acc[1][dq*2+1], a1, bf[2], bf[3]);
        }
    }

    float sa = 1.f / (1.f + __expf(-alpha[hw]));
    float sb = 1.f / (1.f + __expf(-beta[hw]));
    #pragma unroll
    for (int mt = 0; mt < 2; mt++)
        #pragma unroll
        for (int j = 0; j < 8; j++) {
            int row = m_base + mt*16 + (lane >> 2);
            int col = hw*64 + j*8 + (lane & 3)*2;
            const float* c = acc[mt][j];
            {
                float2 xv = *(const float2*)(g_xv + gbase + (size_t)row*Dm + col);
                float2 o = {fmaf(sa, xv.x, sb*c[0]), fmaf(sa, xv.y, sb*c[1])};
                *(float2*)(out + gbase + (size_t)row*Dm + col) = o;
            }
            {
                float2 xv = *(const float2*)(g_xv + gbase + (size_t)(row+8)*Dm + col);
                float2 o = {fmaf(sa, xv.x, sb*c[2]), fmaf(sa, xv.y, sb*c[3])};
                *(float2*)(out + gbase + (size_t)(row+8)*Dm + col) = o;
            }
        }
}

extern "C" void kernel_launch(void* const* d_in, const int* in_sizes, int n_in,
                              void* d_out, int out_size) {
    const float* x     = (const float*)d_in[0];
    const float* z     = (const float*)d_in[1];
    const float* Wq    = (const float*)d_in[2];
    const float* bq    = (const float*)d_in[3];
    const float* K     = (const float*)d_in[4];
    const float* Wv    = (const float*)d_in[5];
    const float* bv    = (const float*)d_in[6];
    const float* alpha = (const float*)d_in[7];
    const float* beta  = (const float*)d_in[8];
    float* out = (float*)d_out;

    cudaFuncSetAttribute(kgemm_mma, cudaFuncAttributeMaxDynamicSharedMemorySize, SMEM_MMA);
    cudaFuncSetAttribute(kout,      cudaFuncAttributeMaxDynamicSharedMemorySize, SMEM_KOUT);

    kzero<<<512, 256>>>();
    kprep<<<Dm + 1, 256>>>(Wq, bq, K);
    kprep2<<<Dm, 256>>>(Wv);
    kgemm_mma<<<dim3(Mm/128, 2), 256, SMEM_MMA>>>(z, bv, 1);   // attn (2-product)
    kgemm_mma<<<dim3(Mm/128, 2), 256, SMEM_MMA>>>(x, bv, 0);   // xv (3-product)
    kpool<<<dim3(8, Hh, Bz), 256>>>();
    kfin<<<8, 256>>>();
    kout<<<Mm/64, 256, SMEM_KOUT>>>(alpha, beta, out);
}

// round 11
// speedup vs baseline: 1.2788x; 1.0252x over previous
#include <cuda_runtime.h>
#include <cuda_bf16.h>
#include <cstdint>

#define Bz  8
#define Nn  8192
#define Dm  256
#define Hh  4
#define Rr  64
#define HDd 64
#define Mm  (Bz*Nn)

typedef unsigned long long u64;

// ---------------- device scratch ----------------
__device__ float g_bK[Dm];
__device__ float g_xv[(size_t)Mm*Dm];                 // fp32 xv (exact gate term)
__device__ __nv_bfloat16 g_eb  [(size_t)Mm*Dm];       // bf16 raw exp(attn)
__device__ float g_rs[(size_t)Mm*Hh];                 // fp32 rowsum of e per (n,h)
__device__ float g_pool[Bz*Hh*Rr*HDd];                // fp32 P0 accumulator
__device__ __nv_bfloat16 g_poolb[Bz*Hh*Rr*HDd];       // bf16 P0/S
__device__ float g_S [Bz*Hh*Rr];
__device__ __nv_bfloat16 g_Wh[2][Dm*Dm];              // bf16 hi image of W ([k][n])
__device__ __nv_bfloat16 g_Wl[2][Dm*Dm];              // bf16 lo image (used by gemm0 only)

// ---------------- helpers ----------------
__device__ __forceinline__ void cpa16(uint32_t d, const void* s) {
    asm volatile("cp.async.cg.shared.global [%0], [%1], 16;" :: "r"(d), "l"(s));
}
#define CPCOMMIT() asm volatile("cp.async.commit_group;")
#define CPWAIT0()  asm volatile("cp.async.wait_group 0;")

__device__ __forceinline__ void ldsm4(uint32_t* r, uint32_t a) {
    asm volatile("ldmatrix.sync.aligned.m8n8.x4.shared.b16 {%0,%1,%2,%3}, [%4];"
        : "=r"(r[0]), "=r"(r[1]), "=r"(r[2]), "=r"(r[3]) : "r"(a));
}
__device__ __forceinline__ void ldsm4t(uint32_t* r, uint32_t a) {
    asm volatile("ldmatrix.sync.aligned.m8n8.x4.trans.shared.b16 {%0,%1,%2,%3}, [%4];"
        : "=r"(r[0]), "=r"(r[1]), "=r"(r[2]), "=r"(r[3]) : "r"(a));
}
__device__ __forceinline__ void hmma(float* c, const uint32_t* a, uint32_t b0, uint32_t b1) {
    asm volatile("mma.sync.aligned.m16n8k16.row.col.f32.bf16.bf16.f32 "
        "{%0,%1,%2,%3}, {%4,%5,%6,%7}, {%8,%9}, {%0,%1,%2,%3};"
        : "+f"(c[0]), "+f"(c[1]), "+f"(c[2]), "+f"(c[3])
        : "r"(a[0]), "r"(a[1]), "r"(a[2]), "r"(a[3]), "r"(b0), "r"(b1));
}
__device__ __forceinline__ uint2 f4_to_bf16x4(float4 v) {
    uint32_t a, b;
    asm("cvt.rn.bf16x2.f32 %0, %1, %2;" : "=r"(a) : "f"(v.y), "f"(v.x));
    asm("cvt.rn.bf16x2.f32 %0, %1, %2;" : "=r"(b) : "f"(v.w), "f"(v.z));
    return make_uint2(a, b);
}

// ---------------- small kernels ----------------
__global__ void kzero() {
    int i = blockIdx.x*blockDim.x + threadIdx.x;
    if (i < Bz*Hh*Rr*HDd) g_pool[i] = 0.f;
    if (i < Bz*Hh*Rr)     g_S[i]   = 0.f;
}

__global__ void kprep(const float* __restrict__ Wq, const float* __restrict__ bq,
                      const float* __restrict__ K) {
    int col = threadIdx.x;
    int h = col >> 6, r = col & 63;
    const float* Krow = K + r*Dm + h*HDd;
    if (blockIdx.x < Dm) {
        int c = blockIdx.x;
        const float* wq = Wq + c*Dm + h*HDd;
        float s = 0.f;
        #pragma unroll 16
        for (int d = 0; d < HDd; d++) s = fmaf(wq[d], Krow[d], s);
        s *= 0.125f;
        __nv_bfloat16 hi = __float2bfloat16(s);
        g_Wh[1][c*Dm + col] = hi;
        g_Wl[1][c*Dm + col] = __float2bfloat16(s - __bfloat162float(hi));
    } else {
        float s = 0.f;
        #pragma unroll 16
        for (int d = 0; d < HDd; d++) s = fmaf(bq[h*HDd + d], Krow[d], s);
        g_bK[col] = 0.125f * s;
    }
}

__global__ void kprep2(const float* __restrict__ Wv) {
    int k = blockIdx.x, n = threadIdx.x;
    float wv = Wv[(size_t)k*Dm + n];
    __nv_bfloat16 hi = __float2bfloat16(wv);
    g_Wh[0][k*Dm + n] = hi;
    g_Wl[0][k*Dm + n] = __float2bfloat16(wv - __bfloat162float(hi));
}

// ---------------- HMMA GEMM: C[128,128] per CTA, K=256 in 8 chunks of 32 ----------
// A stage s: hi @ s*20480 (128 rows x 80B), lo @ +10240 (gemm0 only)
// B stage s: hi @ 40960 + s*17408 (32 rows x 272B), lo @ +8704 (gemm0 only)
#define KC     32
#define ABUF(s) ((s)*20480)
#define A_LOO   10240
#define BBUF(s) (40960 + (s)*17408)
#define B_LOO   8704
#define SMEM_MMA 75776

__global__ void __launch_bounds__(256, 2)
kgemm_mma(const float* __restrict__ A, const float* __restrict__ bias, int gemm) {
    extern __shared__ char sm[];
    uint32_t smb = (uint32_t)__cvta_generic_to_shared(sm);
    const int t = threadIdx.x, w = t >> 5, lane = t & 31;
    const int m0 = blockIdx.x*128, nh = blockIdx.y;
    const __nv_bfloat16* Wh = g_Wh[gemm];
    const __nv_bfloat16* Wl = g_Wl[gemm];
    const float* bp = gemm ? g_bK : bias;
    const int wm = (w >> 1)*32, wn = (w & 1)*64;

    float acc[2][8][4];
    #pragma unroll
    for (int i = 0; i < 2; i++)
        #pragma unroll
        for (int j = 0; j < 8; j++)
            #pragma unroll
            for (int q = 0; q < 4; q++) acc[i][j][q] = 0.f;

#define STG_B(c, s)                                                           \
    {                                                                         \
        const __nv_bfloat16* srcH = Wh + (size_t)((c)*KC)*Dm + nh*128;        \
        const __nv_bfloat16* srcL = Wl + (size_t)((c)*KC)*Dm + nh*128;        \
        _Pragma("unroll")                                                     \
        for (int p = 0; p < 2; p++) {                                         \
            int idx = t + p*256;                                              \
            int row = idx >> 4, seg = idx & 15;                               \
            uint32_t d = smb + BBUF(s) + (uint32_t)(row*272 + seg*16);        \
            cpa16(d, srcH + (size_t)row*Dm + seg*8);                          \
            if (gemm == 0)                                                    \
                cpa16(d + B_LOO, srcL + (size_t)row*Dm + seg*8);              \
        }                                                                     \
        CPCOMMIT();                                                           \
    }
#define STG_A(c, s)                                                           \
    {                                                                         \
        int row = t >> 1, half = t & 1;                                       \
        const float4* ar = (const float4*)(A + (size_t)(m0 + row)*Dm + (c)*KC + half*16); \
        char* wbH = sm + ABUF(s) + row*80 + half*32;                          \
        char* wbL = wbH + A_LOO;                                              \
        _Pragma("unroll")                                                     \
        for (int j4 = 0; j4 < 4; j4++) {                                      \
            float4 v = ar[j4];                                                \
            uint32_t h01, h23;                                                \
            asm("cvt.rn.bf16x2.f32 %0, %1, %2;" : "=r"(h01) : "f"(v.y), "f"(v.x)); \
            asm("cvt.rn.bf16x2.f32 %0, %1, %2;" : "=r"(h23) : "f"(v.w), "f"(v.z)); \
            *(uint2*)(wbH + j4*8) = make_uint2(h01, h23);                     \
            if (gemm == 0) {                                                  \
                uint32_t q01, q23;                                            \
                float l0 = v.x - __uint_as_float(h01 << 16);                  \
                float l1 = v.y - __uint_as_float(h01 & 0xffff0000u);          \
                float l2 = v.z - __uint_as_float(h23 << 16);                  \
                float l3 = v.w - __uint_as_float(h23 & 0xffff0000u);          \
                asm("cvt.rn.bf16x2.f32 %0, %1, %2;" : "=r"(q01) : "f"(l1), "f"(l0)); \
                asm("cvt.rn.bf16x2.f32 %0, %1, %2;" : "=r"(q23) : "f"(l3), "f"(l2)); \
                *(uint2*)(wbL + j4*8) = make_uint2(q01, q23);                 \
            }                                                                 \
        }                                                                     \
    }

    STG_B(0, 0);
    STG_A(0, 0);

    for (int c = 0; c < 8; c++) {
        int s = c & 1;
        CPWAIT0();
        __syncthreads();
        if (c < 7) {
            STG_B(c + 1, s ^ 1);
            STG_A(c + 1, s ^ 1);
        }
        uint32_t aoff = smb + ABUF(s) + (uint32_t)((wm + (lane & 15))*80) + (lane >> 4)*16;
        uint32_t boff = smb + BBUF(s) + (uint32_t)((lane & 15)*272) + (uint32_t)((wn + (lane >> 4)*8)*2);
        if (gemm == 0) {
            #pragma unroll
            for (int ks = 0; ks < 2; ks++) {
                uint32_t ah[2][4], al[2][4];
                uint32_t ab = aoff + ks*32;
                ldsm4(ah[0], ab);
                ldsm4(ah[1], ab + 16*80);
                ldsm4(al[0], ab + A_LOO);
                ldsm4(al[1], ab + A_LOO + 16*80);
                uint32_t bb = boff + ks*16*272;
                #pragma unroll
                for (int nq = 0; nq < 4; nq++) {
                    uint32_t bh[4], bl[4];
                    ldsm4t(bh, bb + nq*32);
                    ldsm4t(bl, bb + nq*32 + B_LOO);
                    #pragma unroll
                    for (int mt = 0; mt < 2; mt++) {
                        #pragma unroll
                        for (int sub = 0; sub < 2; sub++) {
                            float* cc = acc[mt][nq*2 + sub];
                            hmma(cc, ah[mt], bh[sub*2], bh[sub*2+1]);
                            hmma(cc, al[mt], bh[sub*2], bh[sub*2+1]);
                            hmma(cc, ah[mt], bl[sub*2], bl[sub*2+1]);
                        }
                    }
                }
            }
        } else {
            // single-product attn: Ahi * Whi (lo terms cancel in softmax; validated R8/R9)
            #pragma unroll
            for (int ks = 0; ks < 2; ks++) {
                uint32_t ah[2][4];
                uint32_t ab = aoff + ks*32;
                ldsm4(ah[0], ab);
                ldsm4(ah[1], ab + 16*80);
                uint32_t bb = boff + ks*16*272;
                #pragma unroll
                for (int nq = 0; nq < 4; nq++) {
                    uint32_t bh[4];
                    ldsm4t(bh, bb + nq*32);
                    #pragma unroll
                    for (int mt = 0; mt < 2; mt++) {
                        #pragma unroll
                        for (int sub = 0; sub < 2; sub++) {
                            float* cc = acc[mt][nq*2 + sub];
                            hmma(cc, ah[mt], bh[sub*2], bh[sub*2+1]);
                        }
                    }
                }
            }
        }
    }

    // ---- register-direct epilogue (no smem staging) ----
    const float* bp2 = bp + nh*128;
    const int rl = lane >> 2, cq = (lane & 3)*2;
    if (gemm == 0) {
        #pragma unroll
        for (int mt = 0; mt < 2; mt++)
            #pragma unroll
            for (int j = 0; j < 8; j++) {
                int cl = wn + j*8 + cq;
                float b0 = bp2[cl], b1 = bp2[cl+1];
                int r = m0 + wm + mt*16 + rl;
                float2 o0 = {acc[mt][j][0] + b0, acc[mt][j][1] + b1};
                float2 o1 = {acc[mt][j][2] + b0, acc[mt][j][3] + b1};
                *(float2*)(g_xv + (size_t)r*Dm + nh*128 + cl)     = o0;
                *(float2*)(g_xv + (size_t)(r+8)*Dm + nh*128 + cl) = o1;
            }
    } else {
        float ps[2][2] = {{0.f,0.f},{0.f,0.f}};
        #pragma unroll
        for (int mt = 0; mt < 2; mt++)
            #pragma unroll
            for (int j = 0; j < 8; j++) {
                int cl = wn + j*8 + cq;
                float b0 = bp2[cl], b1 = bp2[cl+1];
                int r = m0 + wm + mt*16 + rl;
                float e00 = __expf(acc[mt][j][0] + b0);
                float e01 = __expf(acc[mt][j][1] + b1);
                float e10 = __expf(acc[mt][j][2] + b0);
                float e11 = __expf(acc[mt][j][3] + b1);
                ps[mt][0] += e00 + e01;
                ps[mt][1] += e10 + e11;
                uint32_t p0, p1;
                asm("cvt.rn.bf16x2.f32 %0, %1, %2;" : "=r"(p0) : "f"(e01), "f"(e00));
                asm("cvt.rn.bf16x2.f32 %0, %1, %2;" : "=r"(p1) : "f"(e11), "f"(e10));
                *(uint32_t*)(g_eb + (size_t)r*Dm + nh*128 + cl)     = p0;
                *(uint32_t*)(g_eb + (size_t)(r+8)*Dm + nh*128 + cl) = p1;
            }
        int head = nh*2 + (w & 1);
        #pragma unroll
        for (int mt = 0; mt < 2; mt++)
            #pragma unroll
            for (int rr = 0; rr < 2; rr++) {
                float s = ps[mt][rr];
                s += __shfl_xor_sync(0xffffffffu, s, 1);
                s += __shfl_xor_sync(0xffffffffu, s, 2);
                if ((lane & 3) == 0) {
                    int r = m0 + wm + mt*16 + rl + rr*8;
                    g_rs[(size_t)r*Hh + head] = s;
                }
            }
    }
}

// ---------------- kpool: P0[r,d] = sum_n e_bf * bf16(xv/rs), double-buffered ----------------
__global__ void __launch_bounds__(256, 4) kpool() {
    __shared__ char smE[2][64*144];
    __shared__ char smX[2][64*144];
    __shared__ float sred[256];
    uint32_t sE[2] = {(uint32_t)__cvta_generic_to_shared(smE[0]),
                      (uint32_t)__cvta_generic_to_shared(smE[1])};
    uint32_t sX[2] = {(uint32_t)__cvta_generic_to_shared(smX[0]),
                      (uint32_t)__cvta_generic_to_shared(smX[1])};
    const int t = threadIdx.x, w = t >> 5, lane = t & 31;
    const int ch = blockIdx.x, h = blockIdx.y, b = blockIdx.z;
    const int r_base = (w & 3)*16, d_base = (w >> 2)*32;
    float acc[4][4];
    #pragma unroll
    for (int i = 0; i < 4; i++)
        #pragma unroll
        for (int q = 0; q < 4; q++) acc[i][q] = 0.f;
    float Sacc = 0.f;
    const int scol = t & 63, sq = t >> 6;

#define STG_EX(tl, s)                                                         \
    {                                                                         \
        int n0 = ch*1024 + (tl)*64;                                           \
        size_t gbase = ((size_t)(b*Nn + n0))*Dm + h*64;                       \
        _Pragma("unroll")                                                     \
        for (int p = 0; p < 2; p++) {                                         \
            int c = t + p*256;                                                \
            int row = c >> 3, off = c & 7;                                    \
            cpa16(sE[s] + row*144 + off*16, g_eb + gbase + (size_t)row*Dm + off*8); \
        }                                                                     \
        CPCOMMIT();                                                           \
        _Pragma("unroll")                                                     \
        for (int p = 0; p < 4; p++) {                                         \
            int c = t + p*256;                                                \
            int row = c >> 4, col4 = c & 15;                                  \
            float4 v = *(const float4*)(g_xv + gbase + (size_t)row*Dm + col4*4); \
            float inv = __fdividef(1.f, g_rs[((size_t)(b*Nn + n0 + row))*Hh + h]); \
            float4 sv = {v.x*inv, v.y*inv, v.z*inv, v.w*inv};                 \
            *(uint2*)(smX[s] + row*144 + col4*8) = f4_to_bf16x4(sv);          \
        }                                                                     \
    }

    STG_EX(0, 0);

    for (int tile = 0; tile < 16; tile++) {
        int s = tile & 1;
        CPWAIT0();
        __syncthreads();
        if (tile < 15) STG_EX(tile + 1, s ^ 1);

        {
            const __nv_bfloat16* Eb = (const __nv_bfloat16*)smE[s];
            float psum = 0.f;
            #pragma unroll
            for (int i = 0; i < 16; i++)
                psum += __bfloat162float(Eb[(sq*16 + i)*72 + scol]);
            Sacc += psum;
        }
        uint32_t aoff = sE[s] + (uint32_t)((((lane >> 4) << 3) + (lane & 7))*144)
                      + (uint32_t)((r_base + (((lane >> 3) & 1) << 3))*2);
        uint32_t boff = sX[s] + (uint32_t)((lane & 15)*144) + (uint32_t)((d_base + (lane >> 4)*8)*2);
        #pragma unroll
        for (int ks = 0; ks < 4; ks++) {
            uint32_t a[4];
            ldsm4t(a, aoff + ks*16*144);
            #pragma unroll
            for (int dq = 0; dq < 2; dq++) {
                uint32_t bf[4];
                ldsm4t(bf, boff + ks*16*144 + dq*32);
                hmma(acc[dq*2],   a, bf[0], bf[1]);
                hmma(acc[dq*2+1], a, bf[2], bf[3]);
            }
        }
    }
    float* pp = g_pool + ((size_t)(b*Hh + h)*Rr)*HDd;
    #pragma unroll
    for (int i = 0; i < 4; i++) {
        int r = r_base + (lane >> 2);
        int d = d_base + i*8 + (lane & 3)*2;
        atomicAdd(&pp[r*HDd + d],       acc[i][0]);
        atomicAdd(&pp[r*HDd + d + 1],   acc[i][1]);
        atomicAdd(&pp[(r+8)*HDd + d],   acc[i][2]);
        atomicAdd(&pp[(r+8)*HDd + d+1], acc[i][3]);
    }
    __syncthreads();
    sred[t] = Sacc;
    __syncthreads();
    if (t < 64)
        atomicAdd(&g_S[(b*Hh + h)*Rr + t],
                  sred[t] + sred[t+64] + sred[t+128] + sred[t+192]);
}

// ---------------- kfin: poolb = bf16(P0 / S) ----------------
__global__ void kfin() {
    int row = blockIdx.x*256 + threadIdx.x;
    float inv = 1.f / g_S[row];
    const float4* p = (const float4*)(g_pool + (size_t)row*HDd);
    uint2* q = (uint2*)(g_poolb + (size_t)row*HDd);
    #pragma unroll
    for (int i = 0; i < 16; i++) {
        float4 v = p[i];
        v.x *= inv; v.y *= inv; v.z *= inv; v.w *= inv;
        q[i] = f4_to_bf16x4(v);
    }
}

// ---------------- kout: out = sa*xv + sb*(E · P)  (HMMA per head) ----------------
#define KO_E  0                  // 64 rows x 528B
#define KO_P  33792              // 256 rows x 144B
#define SMEM_KOUT 70656
__global__ void __launch_bounds__(256)
kout(const float* __restrict__ alpha, const float* __restrict__ beta,
     float* __restrict__ out) {
    extern __shared__ char sm[];
    uint32_t smb = (uint32_t)__cvta_generic_to_shared(sm);
    const int t = threadIdx.x, w = t >> 5, lane = t & 31;
    const int b = blockIdx.x >> 7;
    const int n0 = (blockIdx.x & 127)*64;
    const int hw = w & 3, m_base = (w >> 2)*32;
    size_t gbase = ((size_t)(b*Nn + n0))*Dm;

    #pragma unroll
    for (int p = 0; p < 8; p++) {
        int c = t + p*256;
        int row = c >> 5, off = c & 31;
        cpa16(smb + KO_E + row*528 + off*16, g_eb + gbase + (size_t)row*Dm + off*8);
        int prow = c >> 3, poff = c & 7;
        cpa16(smb + KO_P + prow*144 + poff*16,
              g_poolb + (size_t)b*(Hh*Rr*HDd) + prow*64 + poff*8);
    }
    CPCOMMIT();
    CPWAIT0();
    __syncthreads();

    float acc[2][8][4];
    #pragma unroll
    for (int i = 0; i < 2; i++)
        #pragma unroll
        for (int j = 0; j < 8; j++)
            #pragma unroll
            for (int q = 0; q < 4; q++) acc[i][j][q] = 0.f;

    uint32_t aoff = smb + KO_E + (uint32_t)((m_base + (lane & 15))*528)
                  + (uint32_t)(hw*128) + (lane >> 4)*16;
    uint32_t boff = smb + KO_P + (uint32_t)(hw*9216)
                  + (uint32_t)((lane & 15)*144) + (uint32_t)((lane >> 4)*16);

    #pragma unroll
    for (int ks = 0; ks < 4; ks++) {
        uint32_t a0[4], a1[4];
        ldsm4(a0, aoff + ks*32);
        ldsm4(a1, aoff + ks*32 + 16*528);
        #pragma unroll
        for (int dq = 0; dq < 4; dq++) {
            uint32_t bf[4];
            ldsm4t(bf, boff + ks*16*144 + dq*32);
            hmma(acc[0][dq*2],   a0, bf[0], bf[1]);
            hmma(acc[0][dq*2+1], a0, bf[2], bf[3]);
            hmma(acc[1][dq*2],   a1, bf[0], bf[1]);
            hmma(acc[1][dq*2+1], a1, bf[2], bf[3]);
        }
    }

    float sa = 1.f / (1.f + __expf(-alpha[hw]));
    float sb = 1.f / (1.f + __expf(-beta[hw]));
    #pragma unroll
    for (int mt = 0; mt < 2; mt++)
        #pragma unroll
        for (int j = 0; j < 8; j++) {
            int row = m_base + mt*16 + (lane >> 2);
            int col = hw*64 + j*8 + (lane & 3)*2;
            const float* c = acc[mt][j];
            {
                float2 xv = *(const float2*)(g_xv + gbase + (size_t)row*Dm + col);
                float2 o = {fmaf(sa, xv.x, sb*c[0]), fmaf(sa, xv.y, sb*c[1])};
                *(float2*)(out + gbase + (size_t)row*Dm + col) = o;
            }
            {
                float2 xv = *(const float2*)(g_xv + gbase + (size_t)(row+8)*Dm + col);
                float2 o = {fmaf(sa, xv.x, sb*c[2]), fmaf(sa, xv.y, sb*c[3])};
                *(float2*)(out + gbase + (size_t)(row+8)*Dm + col) = o;
            }
        }
}

extern "C" void kernel_launch(void* const* d_in, const int* in_sizes, int n_in,
                              void* d_out, int out_size) {
    const float* x     = (const float*)d_in[0];
    const float* z     = (const float*)d_in[1];
    const float* Wq    = (const float*)d_in[2];
    const float* bq    = (const float*)d_in[3];
    const float* K     = (const float*)d_in[4];
    const float* Wv    = (const float*)d_in[5];
    const float* bv    = (const float*)d_in[6];
    const float* alpha = (const float*)d_in[7];
    const float* beta  = (const float*)d_in[8];
    float* out = (float*)d_out;

    cudaFuncSetAttribute(kgemm_mma, cudaFuncAttributeMaxDynamicSharedMemorySize, SMEM_MMA);
    cudaFuncSetAttribute(kout,      cudaFuncAttributeMaxDynamicSharedMemorySize, SMEM_KOUT);

    kzero<<<512, 256>>>();
    kprep<<<Dm + 1, 256>>>(Wq, bq, K);
    kprep2<<<Dm, 256>>>(Wv);
    kgemm_mma<<<dim3(Mm/128, 2), 256, SMEM_MMA>>>(z, bv, 1);   // attn (1-product)
    kgemm_mma<<<dim3(Mm/128, 2), 256, SMEM_MMA>>>(x, bv, 0);   // xv (3-product)
    kpool<<<dim3(8, Hh, Bz), 256>>>();
    kfin<<<8, 256>>>();
    kout<<<Mm/64, 256, SMEM_KOUT>>>(alpha, beta, out);
}

// round 12
// speedup vs baseline: 1.3936x; 1.0898x over previous
#include <cuda_runtime.h>
#include <cuda_bf16.h>
#include <cstdint>

#define Bz  8
#define Nn  8192
#define Dm  256
#define Hh  4
#define Rr  64
#define HDd 64
#define Mm  (Bz*Nn)

typedef unsigned long long u64;

// ---------------- device scratch ----------------
__device__ float g_bK[Dm];
__device__ float g_xv[(size_t)Mm*Dm];                 // fp32 xv (exact gate term)
__device__ __nv_bfloat16 g_eb  [(size_t)Mm*Dm];       // bf16 raw exp(attn)
__device__ float g_rs[(size_t)Mm*Hh];                 // fp32 rowsum of e per (n,h)
__device__ float g_pool[Bz*Hh*Rr*HDd];                // fp32 P0 accumulator
__device__ __nv_bfloat16 g_poolb[Bz*Hh*Rr*HDd];       // bf16 P0/S
__device__ float g_S [Bz*Hh*Rr];
__device__ __nv_bfloat16 g_Wh[2][Dm*Dm];              // bf16 hi image of W ([k][n])
__device__ __nv_bfloat16 g_Wl[2][Dm*Dm];              // bf16 lo image (used by gemm0 only)

// ---------------- helpers ----------------
__device__ __forceinline__ void cpa16(uint32_t d, const void* s) {
    asm volatile("cp.async.cg.shared.global [%0], [%1], 16;" :: "r"(d), "l"(s));
}
#define CPCOMMIT() asm volatile("cp.async.commit_group;")
#define CPWAIT0()  asm volatile("cp.async.wait_group 0;")

__device__ __forceinline__ void ldsm4(uint32_t* r, uint32_t a) {
    asm volatile("ldmatrix.sync.aligned.m8n8.x4.shared.b16 {%0,%1,%2,%3}, [%4];"
        : "=r"(r[0]), "=r"(r[1]), "=r"(r[2]), "=r"(r[3]) : "r"(a));
}
__device__ __forceinline__ void ldsm4t(uint32_t* r, uint32_t a) {
    asm volatile("ldmatrix.sync.aligned.m8n8.x4.trans.shared.b16 {%0,%1,%2,%3}, [%4];"
        : "=r"(r[0]), "=r"(r[1]), "=r"(r[2]), "=r"(r[3]) : "r"(a));
}
__device__ __forceinline__ void hmma(float* c, const uint32_t* a, uint32_t b0, uint32_t b1) {
    asm volatile("mma.sync.aligned.m16n8k16.row.col.f32.bf16.bf16.f32 "
        "{%0,%1,%2,%3}, {%4,%5,%6,%7}, {%8,%9}, {%0,%1,%2,%3};"
        : "+f"(c[0]), "+f"(c[1]), "+f"(c[2]), "+f"(c[3])
        : "r"(a[0]), "r"(a[1]), "r"(a[2]), "r"(a[3]), "r"(b0), "r"(b1));
}
__device__ __forceinline__ uint2 f4_to_bf16x4(float4 v) {
    uint32_t a, b;
    asm("cvt.rn.bf16x2.f32 %0, %1, %2;" : "=r"(a) : "f"(v.y), "f"(v.x));
    asm("cvt.rn.bf16x2.f32 %0, %1, %2;" : "=r"(b) : "f"(v.w), "f"(v.z));
    return make_uint2(a, b);
}

// ---------------- fused init: zero accumulators + fold WK + split Wv ----------------
__global__ void kinit(const float* __restrict__ Wq, const float* __restrict__ bq,
                      const float* __restrict__ K, const float* __restrict__ Wv) {
    int bid = blockIdx.x;
    if (bid < 512) {                       // zero g_pool / g_S
        int i = bid*256 + threadIdx.x;
        if (i < Bz*Hh*Rr*HDd) g_pool[i] = 0.f;
        if (i < Bz*Hh*Rr)     g_S[i]   = 0.f;
    } else if (bid < 512 + Dm + 1) {       // fold Wq@K -> WK (bf16 split) + bias
        int col = threadIdx.x;
        int h = col >> 6, r = col & 63;
        const float* Krow = K + r*Dm + h*HDd;
        if (bid - 512 < Dm) {
            int c = bid - 512;
            const float* wq = Wq + c*Dm + h*HDd;
            float s = 0.f;
            #pragma unroll 16
            for (int d = 0; d < HDd; d++) s = fmaf(wq[d], Krow[d], s);
            s *= 0.125f;
            __nv_bfloat16 hi = __float2bfloat16(s);
            g_Wh[1][c*Dm + col] = hi;
            g_Wl[1][c*Dm + col] = __float2bfloat16(s - __bfloat162float(hi));
        } else {
            float s = 0.f;
            #pragma unroll 16
            for (int d = 0; d < HDd; d++) s = fmaf(bq[h*HDd + d], Krow[d], s);
            g_bK[col] = 0.125f * s;
        }
    } else {                               // split Wv
        int k = bid - (512 + Dm + 1), n = threadIdx.x;
        float wv = Wv[(size_t)k*Dm + n];
        __nv_bfloat16 hi = __float2bfloat16(wv);
        g_Wh[0][k*Dm + n] = hi;
        g_Wl[0][k*Dm + n] = __float2bfloat16(wv - __bfloat162float(hi));
    }
}

// ---------------- HMMA GEMM: C[128,128] per CTA, K=256 in 8 chunks of 32 ----------
// grid (Mm/128, 2 nh, 2 gemm): z=0 -> xv (3-product), z=1 -> attn (1-product)
// A stage s: hi @ s*20480 (128 rows x 80B), lo @ +10240 (gemm0 only)
// B stage s: hi @ 40960 + s*17408 (32 rows x 272B), lo @ +8704 (gemm0 only)
#define KC     32
#define ABUF(s) ((s)*20480)
#define A_LOO   10240
#define BBUF(s) (40960 + (s)*17408)
#define B_LOO   8704
#define SMEM_MMA 75776

__global__ void __launch_bounds__(256, 2)
kgemm_mma(const float* __restrict__ X, const float* __restrict__ Z,
          const float* __restrict__ bias) {
    extern __shared__ char sm[];
    uint32_t smb = (uint32_t)__cvta_generic_to_shared(sm);
    const int t = threadIdx.x, w = t >> 5, lane = t & 31;
    const int m0 = blockIdx.x*128, nh = blockIdx.y;
    const int gemm = blockIdx.z;
    const float* A = gemm ? Z : X;
    const __nv_bfloat16* Wh = g_Wh[gemm];
    const __nv_bfloat16* Wl = g_Wl[gemm];
    const float* bp = gemm ? g_bK : bias;
    const int wm = (w >> 1)*32, wn = (w & 1)*64;

    float acc[2][8][4];
    #pragma unroll
    for (int i = 0; i < 2; i++)
        #pragma unroll
        for (int j = 0; j < 8; j++)
            #pragma unroll
            for (int q = 0; q < 4; q++) acc[i][j][q] = 0.f;

#define STG_B(c, s)                                                           \
    {                                                                         \
        const __nv_bfloat16* srcH = Wh + (size_t)((c)*KC)*Dm + nh*128;        \
        const __nv_bfloat16* srcL = Wl + (size_t)((c)*KC)*Dm + nh*128;        \
        _Pragma("unroll")                                                     \
        for (int p = 0; p < 2; p++) {                                         \
            int idx = t + p*256;                                              \
            int row = idx >> 4, seg = idx & 15;                               \
            uint32_t d = smb + BBUF(s) + (uint32_t)(row*272 + seg*16);        \
            cpa16(d, srcH + (size_t)row*Dm + seg*8);                          \
            if (gemm == 0)                                                    \
                cpa16(d + B_LOO, srcL + (size_t)row*Dm + seg*8);              \
        }                                                                     \
        CPCOMMIT();                                                           \
    }
#define STG_A(c, s)                                                           \
    {                                                                         \
        int row = t >> 1, half = t & 1;                                       \
        const float4* ar = (const float4*)(A + (size_t)(m0 + row)*Dm + (c)*KC + half*16); \
        float4 vv[4];                                                         \
        _Pragma("unroll")                                                     \
        for (int j4 = 0; j4 < 4; j4++) vv[j4] = ar[j4];   /* batch LDGs: MLP=4 */ \
        char* wbH = sm + ABUF(s) + row*80 + half*32;                          \
        char* wbL = wbH + A_LOO;                                              \
        _Pragma("unroll")                                                     \
        for (int j4 = 0; j4 < 4; j4++) {                                      \
            float4 v = vv[j4];                                                \
            uint32_t h01, h23;                                                \
            asm("cvt.rn.bf16x2.f32 %0, %1, %2;" : "=r"(h01) : "f"(v.y), "f"(v.x)); \
            asm("cvt.rn.bf16x2.f32 %0, %1, %2;" : "=r"(h23) : "f"(v.w), "f"(v.z)); \
            *(uint2*)(wbH + j4*8) = make_uint2(h01, h23);                     \
            if (gemm == 0) {                                                  \
                uint32_t q01, q23;                                            \
                float l0 = v.x - __uint_as_float(h01 << 16);                  \
                float l1 = v.y - __uint_as_float(h01 & 0xffff0000u);          \
                float l2 = v.z - __uint_as_float(h23 << 16);                  \
                float l3 = v.w - __uint_as_float(h23 & 0xffff0000u);          \
                asm("cvt.rn.bf16x2.f32 %0, %1, %2;" : "=r"(q01) : "f"(l1), "f"(l0)); \
                asm("cvt.rn.bf16x2.f32 %0, %1, %2;" : "=r"(q23) : "f"(l3), "f"(l2)); \
                *(uint2*)(wbL + j4*8) = make_uint2(q01, q23);                 \
            }                                                                 \
        }                                                                     \
    }

    STG_B(0, 0);
    STG_A(0, 0);

    for (int c = 0; c < 8; c++) {
        int s = c & 1;
        CPWAIT0();
        __syncthreads();
        if (c < 7) {
            STG_B(c + 1, s ^ 1);
            STG_A(c + 1, s ^ 1);
        }
        uint32_t aoff = smb + ABUF(s) + (uint32_t)((wm + (lane & 15))*80) + (lane >> 4)*16;
        uint32_t boff = smb + BBUF(s) + (uint32_t)((lane & 15)*272) + (uint32_t)((wn + (lane >> 4)*8)*2);
        if (gemm == 0) {
            #pragma unroll
            for (int ks = 0; ks < 2; ks++) {
                uint32_t ah[2][4], al[2][4];
                uint32_t ab = aoff + ks*32;
                ldsm4(ah[0], ab);
                ldsm4(ah[1], ab + 16*80);
                ldsm4(al[0], ab + A_LOO);
                ldsm4(al[1], ab + A_LOO + 16*80);
                uint32_t bb = boff + ks*16*272;
                #pragma unroll
                for (int nq = 0; nq < 4; nq++) {
                    uint32_t bh[4], bl[4];
                    ldsm4t(bh, bb + nq*32);
                    ldsm4t(bl, bb + nq*32 + B_LOO);
                    #pragma unroll
                    for (int mt = 0; mt < 2; mt++) {
                        #pragma unroll
                        for (int sub = 0; sub < 2; sub++) {
                            float* cc = acc[mt][nq*2 + sub];
                            hmma(cc, ah[mt], bh[sub*2], bh[sub*2+1]);
                            hmma(cc, al[mt], bh[sub*2], bh[sub*2+1]);
                            hmma(cc, ah[mt], bl[sub*2], bl[sub*2+1]);
                        }
                    }
                }
            }
        } else {
            // single-product attn: Ahi * Whi (lo terms cancel in softmax; validated R8-R11)
            #pragma unroll
            for (int ks = 0; ks < 2; ks++) {
                uint32_t ah[2][4];
                uint32_t ab = aoff + ks*32;
                ldsm4(ah[0], ab);
                ldsm4(ah[1], ab + 16*80);
                uint32_t bb = boff + ks*16*272;
                #pragma unroll
                for (int nq = 0; nq < 4; nq++) {
                    uint32_t bh[4];
                    ldsm4t(bh, bb + nq*32);
                    #pragma unroll
                    for (int mt = 0; mt < 2; mt++) {
                        #pragma unroll
                        for (int sub = 0; sub < 2; sub++) {
                            float* cc = acc[mt][nq*2 + sub];
                            hmma(cc, ah[mt], bh[sub*2], bh[sub*2+1]);
                        }
                    }
                }
            }
        }
    }

    // ---- register-direct epilogue (no smem staging) ----
    const float* bp2 = bp + nh*128;
    const int rl = lane >> 2, cq = (lane & 3)*2;
    if (gemm == 0) {
        #pragma unroll
        for (int mt = 0; mt < 2; mt++)
            #pragma unroll
            for (int j = 0; j < 8; j++) {
                int cl = wn + j*8 + cq;
                float b0 = bp2[cl], b1 = bp2[cl+1];
                int r = m0 + wm + mt*16 + rl;
                float2 o0 = {acc[mt][j][0] + b0, acc[mt][j][1] + b1};
                float2 o1 = {acc[mt][j][2] + b0, acc[mt][j][3] + b1};
                *(float2*)(g_xv + (size_t)r*Dm + nh*128 + cl)     = o0;
                *(float2*)(g_xv + (size_t)(r+8)*Dm + nh*128 + cl) = o1;
            }
    } else {
        float ps[2][2] = {{0.f,0.f},{0.f,0.f}};
        #pragma unroll
        for (int mt = 0; mt < 2; mt++)
            #pragma unroll
            for (int j = 0; j < 8; j++) {
                int cl = wn + j*8 + cq;
                float b0 = bp2[cl], b1 = bp2[cl+1];
                int r = m0 + wm + mt*16 + rl;
                float e00 = __expf(acc[mt][j][0] + b0);
                float e01 = __expf(acc[mt][j][1] + b1);
                float e10 = __expf(acc[mt][j][2] + b0);
                float e11 = __expf(acc[mt][j][3] + b1);
                ps[mt][0] += e00 + e01;
                ps[mt][1] += e10 + e11;
                uint32_t p0, p1;
                asm("cvt.rn.bf16x2.f32 %0, %1, %2;" : "=r"(p0) : "f"(e01), "f"(e00));
                asm("cvt.rn.bf16x2.f32 %0, %1, %2;" : "=r"(p1) : "f"(e11), "f"(e10));
                *(uint32_t*)(g_eb + (size_t)r*Dm + nh*128 + cl)     = p0;
                *(uint32_t*)(g_eb + (size_t)(r+8)*Dm + nh*128 + cl) = p1;
            }
        int head = nh*2 + (w & 1);
        #pragma unroll
        for (int mt = 0; mt < 2; mt++)
            #pragma unroll
            for (int rr = 0; rr < 2; rr++) {
                float s = ps[mt][rr];
                s += __shfl_xor_sync(0xffffffffu, s, 1);
                s += __shfl_xor_sync(0xffffffffu, s, 2);
                if ((lane & 3) == 0) {
                    int r = m0 + wm + mt*16 + rl + rr*8;
                    g_rs[(size_t)r*Hh + head] = s;
                }
            }
    }
}

// ---------------- kpool: P0[r,d] = sum_n e_bf * bf16(xv/rs), double-buffered ----------------
__global__ void __launch_bounds__(256, 4) kpool() {
    __shared__ char smE[2][64*144];
    __shared__ char smX[2][64*144];
    __shared__ float sred[256];
    uint32_t sE[2] = {(uint32_t)__cvta_generic_to_shared(smE[0]),
                      (uint32_t)__cvta_generic_to_shared(smE[1])};
    uint32_t sX[2] = {(uint32_t)__cvta_generic_to_shared(smX[0]),
                      (uint32_t)__cvta_generic_to_shared(smX[1])};
    const int t = threadIdx.x, w = t >> 5, lane = t & 31;
    const int ch = blockIdx.x, h = blockIdx.y, b = blockIdx.z;
    const int r_base = (w & 3)*16, d_base = (w >> 2)*32;
    float acc[4][4];
    #pragma unroll
    for (int i = 0; i < 4; i++)
        #pragma unroll
        for (int q = 0; q < 4; q++) acc[i][q] = 0.f;
    float Sacc = 0.f;
    const int scol = t & 63, sq = t >> 6;

#define STG_EX(tl, s)                                                         \
    {                                                                         \
        int n0 = ch*512 + (tl)*64;                                            \
        size_t gbase = ((size_t)(b*Nn + n0))*Dm + h*64;                       \
        _Pragma("unroll")                                                     \
        for (int p = 0; p < 2; p++) {                                         \
            int c = t + p*256;                                                \
            int row = c >> 3, off = c & 7;                                    \
            cpa16(sE[s] + row*144 + off*16, g_eb + gbase + (size_t)row*Dm + off*8); \
        }                                                                     \
        CPCOMMIT();                                                           \
        _Pragma("unroll")                                                     \
        for (int p = 0; p < 4; p++) {                                         \
            int c = t + p*256;                                                \
            int row = c >> 4, col4 = c & 15;                                  \
            float4 v = *(const float4*)(g_xv + gbase + (size_t)row*Dm + col4*4); \
            float inv = __fdividef(1.f, g_rs[((size_t)(b*Nn + n0 + row))*Hh + h]); \
            float4 sv = {v.x*inv, v.y*inv, v.z*inv, v.w*inv};                 \
            *(uint2*)(smX[s] + row*144 + col4*8) = f4_to_bf16x4(sv);          \
        }                                                                     \
    }

    STG_EX(0, 0);

    for (int tile = 0; tile < 8; tile++) {
        int s = tile & 1;
        CPWAIT0();
        __syncthreads();
        if (tile < 7) STG_EX(tile + 1, s ^ 1);

        {
            const __nv_bfloat16* Eb = (const __nv_bfloat16*)smE[s];
            float psum = 0.f;
            #pragma unroll
            for (int i = 0; i < 16; i++)
                psum += __bfloat162float(Eb[(sq*16 + i)*72 + scol]);
            Sacc += psum;
        }
        uint32_t aoff = sE[s] + (uint32_t)((((lane >> 4) << 3) + (lane & 7))*144)
                      + (uint32_t)((r_base + (((lane >> 3) & 1) << 3))*2);
        uint32_t boff = sX[s] + (uint32_t)((lane & 15)*144) + (uint32_t)((d_base + (lane >> 4)*8)*2);
        #pragma unroll
        for (int ks = 0; ks < 4; ks++) {
            uint32_t a[4];
            ldsm4t(a, aoff + ks*16*144);
            #pragma unroll
            for (int dq = 0; dq < 2; dq++) {
                uint32_t bf[4];
                ldsm4t(bf, boff + ks*16*144 + dq*32);
                hmma(acc[dq*2],   a, bf[0], bf[1]);
                hmma(acc[dq*2+1], a, bf[2], bf[3]);
            }
        }
    }
    float* pp = g_pool + ((size_t)(b*Hh + h)*Rr)*HDd;
    #pragma unroll
    for (int i = 0; i < 4; i++) {
        int r = r_base + (lane >> 2);
        int d = d_base + i*8 + (lane & 3)*2;
        atomicAdd(&pp[r*HDd + d],       acc[i][0]);
        atomicAdd(&pp[r*HDd + d + 1],   acc[i][1]);
        atomicAdd(&pp[(r+8)*HDd + d],   acc[i][2]);
        atomicAdd(&pp[(r+8)*HDd + d+1], acc[i][3]);
    }
    __syncthreads();
    sred[t] = Sacc;
    __syncthreads();
    if (t < 64)
        atomicAdd(&g_S[(b*Hh + h)*Rr + t],
                  sred[t] + sred[t+64] + sred[t+128] + sred[t+192]);
}

// ---------------- kfin: poolb = bf16(P0 / S) ----------------
__global__ void kfin() {
    int row = blockIdx.x*256 + threadIdx.x;
    float inv = 1.f / g_S[row];
    const float4* p = (const float4*)(g_pool + (size_t)row*HDd);
    uint2* q = (uint2*)(g_poolb + (size_t)row*HDd);
    #pragma unroll
    for (int i = 0; i < 16; i++) {
        float4 v = p[i];
        v.x *= inv; v.y *= inv; v.z *= inv; v.w *= inv;
        q[i] = f4_to_bf16x4(v);
    }
}

// ---------------- kout: out = sa*xv + sb*(E · P)  (HMMA per head) ----------------
#define KO_E  0                  // 64 rows x 528B
#define KO_P  33792              // 256 rows x 144B
#define SMEM_KOUT 70656
__global__ void __launch_bounds__(256)
kout(const float* __restrict__ alpha, const float* __restrict__ beta,
     float* __restrict__ out) {
    extern __shared__ char sm[];
    uint32_t smb = (uint32_t)__cvta_generic_to_shared(sm);
    const int t = threadIdx.x, w = t >> 5, lane = t & 31;
    const int b = blockIdx.x >> 7;
    const int n0 = (blockIdx.x & 127)*64;
    const int hw = w & 3, m_base = (w >> 2)*32;
    size_t gbase = ((size_t)(b*Nn + n0))*Dm;

    #pragma unroll
    for (int p = 0; p < 8; p++) {
        int c = t + p*256;
        int row = c >> 5, off = c & 31;
        cpa16(smb + KO_E + row*528 + off*16, g_eb + gbase + (size_t)row*Dm + off*8);
        int prow = c >> 3, poff = c & 7;
        cpa16(smb + KO_P + prow*144 + poff*16,
              g_poolb + (size_t)b*(Hh*Rr*HDd) + prow*64 + poff*8);
    }
    CPCOMMIT();
    CPWAIT0();
    __syncthreads();

    float acc[2][8][4];
    #pragma unroll
    for (int i = 0; i < 2; i++)
        #pragma unroll
        for (int j = 0; j < 8; j++)
            #pragma unroll
            for (int q = 0; q < 4; q++) acc[i][j][q] = 0.f;

    uint32_t aoff = smb + KO_E + (uint32_t)((m_base + (lane & 15))*528)
                  + (uint32_t)(hw*128) + (lane >> 4)*16;
    uint32_t boff = smb + KO_P + (uint32_t)(hw*9216)
                  + (uint32_t)((lane & 15)*144) + (uint32_t)((lane >> 4)*16);

    #pragma unroll
    for (int ks = 0; ks < 4; ks++) {
        uint32_t a0[4], a1[4];
        ldsm4(a0, aoff + ks*32);
        ldsm4(a1, aoff + ks*32 + 16*528);
        #pragma unroll
        for (int dq = 0; dq < 4; dq++) {
            uint32_t bf[4];
            ldsm4t(bf, boff + ks*16*144 + dq*32);
            hmma(acc[0][dq*2],   a0, bf[0], bf[1]);
            hmma(acc[0][dq*2+1], a0, bf[2], bf[3]);
            hmma(acc[1][dq*2],   a1, bf[0], bf[1]);
            hmma(acc[1][dq*2+1], a1, bf[2], bf[3]);
        }
    }

    float sa = 1.f / (1.f + __expf(-alpha[hw]));
    float sb = 1.f / (1.f + __expf(-beta[hw]));
    #pragma unroll
    for (int mt = 0; mt < 2; mt++)
        #pragma unroll
        for (int j = 0; j < 8; j++) {
            int row = m_base + mt*16 + (lane >> 2);
            int col = hw*64 + j*8 + (lane & 3)*2;
            const float* c = acc[mt][j];
            {
                float2 xv = *(const float2*)(g_xv + gbase + (size_t)row*Dm + col);
                float2 o = {fmaf(sa, xv.x, sb*c[0]), fmaf(sa, xv.y, sb*c[1])};
                *(float2*)(out + gbase + (size_t)row*Dm + col) = o;
            }
            {
                float2 xv = *(const float2*)(g_xv + gbase + (size_t)(row+8)*Dm + col);
                float2 o = {fmaf(sa, xv.x, sb*c[2]), fmaf(sa, xv.y, sb*c[3])};
                *(float2*)(out + gbase + (size_t)(row+8)*Dm + col) = o;
            }
        }
}

extern "C" void kernel_launch(void* const* d_in, const int* in_sizes, int n_in,
                              void* d_out, int out_size) {
    const float* x     = (const float*)d_in[0];
    const float* z     = (const float*)d_in[1];
    const float* Wq    = (const float*)d_in[2];
    const float* bq    = (const float*)d_in[3];
    const float* K     = (const float*)d_in[4];
    const float* Wv    = (const float*)d_in[5];
    const float* bv    = (const float*)d_in[6];
    const float* alpha = (const float*)d_in[7];
    const float* beta  = (const float*)d_in[8];
    float* out = (float*)d_out;

    cudaFuncSetAttribute(kgemm_mma, cudaFuncAttributeMaxDynamicSharedMemorySize, SMEM_MMA);
    cudaFuncSetAttribute(kout,      cudaFuncAttributeMaxDynamicSharedMemorySize, SMEM_KOUT);

    kinit<<<512 + Dm + 1 + Dm, 256>>>(Wq, bq, K, Wv);
    kgemm_mma<<<dim3(Mm/128, 2, 2), 256, SMEM_MMA>>>(x, z, bv);  // both GEMMs, one grid
    kpool<<<dim3(16, Hh, Bz), 256>>>();
    kfin<<<8, 256>>>();
    kout<<<Mm/64, 256, SMEM_KOUT>>>(alpha, beta, out);
}

// round 13
// speedup vs baseline: 1.4452x; 1.0370x over previous
#include <cuda_runtime.h>
#include <cuda_bf16.h>
#include <cstdint>

#define Bz  8
#define Nn  8192
#define Dm  256
#define Hh  4
#define Rr  64
#define HDd 64
#define Mm  (Bz*Nn)

typedef unsigned long long u64;

// ---------------- device scratch ----------------
__device__ float g_bK[Dm];
__device__ float g_xv[(size_t)Mm*Dm];                 // fp32 xv (exact gate term)
__device__ __nv_bfloat16 g_eb  [(size_t)Mm*Dm];       // bf16 raw exp(attn)
__device__ float g_rs[(size_t)Mm*Hh];                 // fp32 rowsum of e per (n,h)
__device__ float g_pool[Bz*Hh*Rr*HDd];                // fp32 P0 accumulator
__device__ float g_S [Bz*Hh*Rr];
__device__ __nv_bfloat16 g_Wh[2][Dm*Dm];              // bf16 hi image of W ([k][n])
__device__ __nv_bfloat16 g_Wl[2][Dm*Dm];              // bf16 lo image (used by gemm0 only)

// ---------------- helpers ----------------
__device__ __forceinline__ void cpa16(uint32_t d, const void* s) {
    asm volatile("cp.async.cg.shared.global [%0], [%1], 16;" :: "r"(d), "l"(s));
}
#define CPCOMMIT() asm volatile("cp.async.commit_group;")
#define CPWAIT0()  asm volatile("cp.async.wait_group 0;")

__device__ __forceinline__ void ldsm4(uint32_t* r, uint32_t a) {
    asm volatile("ldmatrix.sync.aligned.m8n8.x4.shared.b16 {%0,%1,%2,%3}, [%4];"
        : "=r"(r[0]), "=r"(r[1]), "=r"(r[2]), "=r"(r[3]) : "r"(a));
}
__device__ __forceinline__ void ldsm4t(uint32_t* r, uint32_t a) {
    asm volatile("ldmatrix.sync.aligned.m8n8.x4.trans.shared.b16 {%0,%1,%2,%3}, [%4];"
        : "=r"(r[0]), "=r"(r[1]), "=r"(r[2]), "=r"(r[3]) : "r"(a));
}
__device__ __forceinline__ void hmma(float* c, const uint32_t* a, uint32_t b0, uint32_t b1) {
    asm volatile("mma.sync.aligned.m16n8k16.row.col.f32.bf16.bf16.f32 "
        "{%0,%1,%2,%3}, {%4,%5,%6,%7}, {%8,%9}, {%0,%1,%2,%3};"
        : "+f"(c[0]), "+f"(c[1]), "+f"(c[2]), "+f"(c[3])
        : "r"(a[0]), "r"(a[1]), "r"(a[2]), "r"(a[3]), "r"(b0), "r"(b1));
}
__device__ __forceinline__ uint2 f4_to_bf16x4(float4 v) {
    uint32_t a, b;
    asm("cvt.rn.bf16x2.f32 %0, %1, %2;" : "=r"(a) : "f"(v.y), "f"(v.x));
    asm("cvt.rn.bf16x2.f32 %0, %1, %2;" : "=r"(b) : "f"(v.w), "f"(v.z));
    return make_uint2(a, b);
}

// ---------------- fused init: zero accumulators + fold WK + split Wv ----------------
__global__ void kinit(const float* __restrict__ Wq, const float* __restrict__ bq,
                      const float* __restrict__ K, const float* __restrict__ Wv) {
    int bid = blockIdx.x;
    if (bid < 512) {                       // zero g_pool / g_S
        int i = bid*256 + threadIdx.x;
        if (i < Bz*Hh*Rr*HDd) g_pool[i] = 0.f;
        if (i < Bz*Hh*Rr)     g_S[i]   = 0.f;
    } else if (bid < 512 + Dm + 1) {       // fold Wq@K -> WK (bf16 split) + bias
        int col = threadIdx.x;
        int h = col >> 6, r = col & 63;
        const float* Krow = K + r*Dm + h*HDd;
        if (bid - 512 < Dm) {
            int c = bid - 512;
            const float* wq = Wq + c*Dm + h*HDd;
            float s = 0.f;
            #pragma unroll 16
            for (int d = 0; d < HDd; d++) s = fmaf(wq[d], Krow[d], s);
            s *= 0.125f;
            __nv_bfloat16 hi = __float2bfloat16(s);
            g_Wh[1][c*Dm + col] = hi;
            g_Wl[1][c*Dm + col] = __float2bfloat16(s - __bfloat162float(hi));
        } else {
            float s = 0.f;
            #pragma unroll 16
            for (int d = 0; d < HDd; d++) s = fmaf(bq[h*HDd + d], Krow[d], s);
            g_bK[col] = 0.125f * s;
        }
    } else {                               // split Wv
        int k = bid - (512 + Dm + 1), n = threadIdx.x;
        float wv = Wv[(size_t)k*Dm + n];
        __nv_bfloat16 hi = __float2bfloat16(wv);
        g_Wh[0][k*Dm + n] = hi;
        g_Wl[0][k*Dm + n] = __float2bfloat16(wv - __bfloat162float(hi));
    }
}

// ---------------- HMMA GEMM: C[128,128] per CTA, K=256 in 8 chunks of 32 ----------
#define KC     32
#define ABUF(s) ((s)*20480)
#define A_LOO   10240
#define BBUF(s) (40960 + (s)*17408)
#define B_LOO   8704
#define SMEM_MMA 75776

__global__ void __launch_bounds__(256, 2)
kgemm_mma(const float* __restrict__ X, const float* __restrict__ Z,
          const float* __restrict__ bias) {
    extern __shared__ char sm[];
    uint32_t smb = (uint32_t)__cvta_generic_to_shared(sm);
    const int t = threadIdx.x, w = t >> 5, lane = t & 31;
    const int m0 = blockIdx.x*128, nh = blockIdx.y;
    const int gemm = blockIdx.z;
    const float* A = gemm ? Z : X;
    const __nv_bfloat16* Wh = g_Wh[gemm];
    const __nv_bfloat16* Wl = g_Wl[gemm];
    const float* bp = gemm ? g_bK : bias;
    const int wm = (w >> 1)*32, wn = (w & 1)*64;

    float acc[2][8][4];
    #pragma unroll
    for (int i = 0; i < 2; i++)
        #pragma unroll
        for (int j = 0; j < 8; j++)
            #pragma unroll
            for (int q = 0; q < 4; q++) acc[i][j][q] = 0.f;

#define STG_B(c, s)                                                           \
    {                                                                         \
        const __nv_bfloat16* srcH = Wh + (size_t)((c)*KC)*Dm + nh*128;        \
        const __nv_bfloat16* srcL = Wl + (size_t)((c)*KC)*Dm + nh*128;        \
        _Pragma("unroll")                                                     \
        for (int p = 0; p < 2; p++) {                                         \
            int idx = t + p*256;                                              \
            int row = idx >> 4, seg = idx & 15;                               \
            uint32_t d = smb + BBUF(s) + (uint32_t)(row*272 + seg*16);        \
            cpa16(d, srcH + (size_t)row*Dm + seg*8);                          \
            if (gemm == 0)                                                    \
                cpa16(d + B_LOO, srcL + (size_t)row*Dm + seg*8);              \
        }                                                                     \
        CPCOMMIT();                                                           \
    }
#define STG_A(c, s)                                                           \
    {                                                                         \
        int row = t >> 1, half = t & 1;                                       \
        const float4* ar = (const float4*)(A + (size_t)(m0 + row)*Dm + (c)*KC + half*16); \
        float4 vv[4];                                                         \
        _Pragma("unroll")                                                     \
        for (int j4 = 0; j4 < 4; j4++) vv[j4] = ar[j4];                       \
        char* wbH = sm + ABUF(s) + row*80 + half*32;                          \
        char* wbL = wbH + A_LOO;                                              \
        _Pragma("unroll")                                                     \
        for (int j4 = 0; j4 < 4; j4++) {                                      \
            float4 v = vv[j4];                                                \
            uint32_t h01, h23;                                                \
            asm("cvt.rn.bf16x2.f32 %0, %1, %2;" : "=r"(h01) : "f"(v.y), "f"(v.x)); \
            asm("cvt.rn.bf16x2.f32 %0, %1, %2;" : "=r"(h23) : "f"(v.w), "f"(v.z)); \
            *(uint2*)(wbH + j4*8) = make_uint2(h01, h23);                     \
            if (gemm == 0) {                                                  \
                uint32_t q01, q23;                                            \
                float l0 = v.x - __uint_as_float(h01 << 16);                  \
                float l1 = v.y - __uint_as_float(h01 & 0xffff0000u);          \
                float l2 = v.z - __uint_as_float(h23 << 16);                  \
                float l3 = v.w - __uint_as_float(h23 & 0xffff0000u);          \
                asm("cvt.rn.bf16x2.f32 %0, %1, %2;" : "=r"(q01) : "f"(l1), "f"(l0)); \
                asm("cvt.rn.bf16x2.f32 %0, %1, %2;" : "=r"(q23) : "f"(l3), "f"(l2)); \
                *(uint2*)(wbL + j4*8) = make_uint2(q01, q23);                 \
            }                                                                 \
        }                                                                     \
    }

    STG_B(0, 0);
    STG_A(0, 0);

    for (int c = 0; c < 8; c++) {
        int s = c & 1;
        CPWAIT0();
        __syncthreads();
        if (c < 7) {
            STG_B(c + 1, s ^ 1);
            STG_A(c + 1, s ^ 1);
        }
        uint32_t aoff = smb + ABUF(s) + (uint32_t)((wm + (lane & 15))*80) + (lane >> 4)*16;
        uint32_t boff = smb + BBUF(s) + (uint32_t)((lane & 15)*272) + (uint32_t)((wn + (lane >> 4)*8)*2);
        if (gemm == 0) {
            #pragma unroll
            for (int ks = 0; ks < 2; ks++) {
                uint32_t ah[2][4], al[2][4];
                uint32_t ab = aoff + ks*32;
                ldsm4(ah[0], ab);
                ldsm4(ah[1], ab + 16*80);
                ldsm4(al[0], ab + A_LOO);
                ldsm4(al[1], ab + A_LOO + 16*80);
                uint32_t bb = boff + ks*16*272;
                #pragma unroll
                for (int nq = 0; nq < 4; nq++) {
                    uint32_t bh[4], bl[4];
                    ldsm4t(bh, bb + nq*32);
                    ldsm4t(bl, bb + nq*32 + B_LOO);
                    #pragma unroll
                    for (int mt = 0; mt < 2; mt++) {
                        #pragma unroll
                        for (int sub = 0; sub < 2; sub++) {
                            float* cc = acc[mt][nq*2 + sub];
                            hmma(cc, ah[mt], bh[sub*2], bh[sub*2+1]);
                            hmma(cc, al[mt], bh[sub*2], bh[sub*2+1]);
                            hmma(cc, ah[mt], bl[sub*2], bl[sub*2+1]);
                        }
                    }
                }
            }
        } else {
            // single-product attn: Ahi * Whi (lo terms cancel in softmax; validated R8-R12)
            #pragma unroll
            for (int ks = 0; ks < 2; ks++) {
                uint32_t ah[2][4];
                uint32_t ab = aoff + ks*32;
                ldsm4(ah[0], ab);
                ldsm4(ah[1], ab + 16*80);
                uint32_t bb = boff + ks*16*272;
                #pragma unroll
                for (int nq = 0; nq < 4; nq++) {
                    uint32_t bh[4];
                    ldsm4t(bh, bb + nq*32);
                    #pragma unroll
                    for (int mt = 0; mt < 2; mt++) {
                        #pragma unroll
                        for (int sub = 0; sub < 2; sub++) {
                            float* cc = acc[mt][nq*2 + sub];
                            hmma(cc, ah[mt], bh[sub*2], bh[sub*2+1]);
                        }
                    }
                }
            }
        }
    }

    // ---- register-direct epilogue ----
    const float* bp2 = bp + nh*128;
    const int rl = lane >> 2, cq = (lane & 3)*2;
    if (gemm == 0) {
        #pragma unroll
        for (int mt = 0; mt < 2; mt++)
            #pragma unroll
            for (int j = 0; j < 8; j++) {
                int cl = wn + j*8 + cq;
                float b0 = bp2[cl], b1 = bp2[cl+1];
                int r = m0 + wm + mt*16 + rl;
                float2 o0 = {acc[mt][j][0] + b0, acc[mt][j][1] + b1};
                float2 o1 = {acc[mt][j][2] + b0, acc[mt][j][3] + b1};
                *(float2*)(g_xv + (size_t)r*Dm + nh*128 + cl)     = o0;
                *(float2*)(g_xv + (size_t)(r+8)*Dm + nh*128 + cl) = o1;
            }
    } else {
        float ps[2][2] = {{0.f,0.f},{0.f,0.f}};
        #pragma unroll
        for (int mt = 0; mt < 2; mt++)
            #pragma unroll
            for (int j = 0; j < 8; j++) {
                int cl = wn + j*8 + cq;
                float b0 = bp2[cl], b1 = bp2[cl+1];
                int r = m0 + wm + mt*16 + rl;
                float e00 = __expf(acc[mt][j][0] + b0);
                float e01 = __expf(acc[mt][j][1] + b1);
                float e10 = __expf(acc[mt][j][2] + b0);
                float e11 = __expf(acc[mt][j][3] + b1);
                ps[mt][0] += e00 + e01;
                ps[mt][1] += e10 + e11;
                uint32_t p0, p1;
                asm("cvt.rn.bf16x2.f32 %0, %1, %2;" : "=r"(p0) : "f"(e01), "f"(e00));
                asm("cvt.rn.bf16x2.f32 %0, %1, %2;" : "=r"(p1) : "f"(e11), "f"(e10));
                *(uint32_t*)(g_eb + (size_t)r*Dm + nh*128 + cl)     = p0;
                *(uint32_t*)(g_eb + (size_t)(r+8)*Dm + nh*128 + cl) = p1;
            }
        int head = nh*2 + (w & 1);
        #pragma unroll
        for (int mt = 0; mt < 2; mt++)
            #pragma unroll
            for (int rr = 0; rr < 2; rr++) {
                float s = ps[mt][rr];
                s += __shfl_xor_sync(0xffffffffu, s, 1);
                s += __shfl_xor_sync(0xffffffffu, s, 2);
                if ((lane & 3) == 0) {
                    int r = m0 + wm + mt*16 + rl + rr*8;
                    g_rs[(size_t)r*Hh + head] = s;
                }
            }
    }
}

// ---------------- kpool: P0 += E^T·(xv/rs); S += E^T·1 (ones-HMMA) ----------------
#define ONESB 0x3F803F80u
__global__ void __launch_bounds__(256, 4) kpool() {
    __shared__ char smE[2][64*144];
    __shared__ char smX[2][64*144];
    uint32_t sE[2] = {(uint32_t)__cvta_generic_to_shared(smE[0]),
                      (uint32_t)__cvta_generic_to_shared(smE[1])};
    uint32_t sX[2] = {(uint32_t)__cvta_generic_to_shared(smX[0]),
                      (uint32_t)__cvta_generic_to_shared(smX[1])};
    const int t = threadIdx.x, w = t >> 5, lane = t & 31;
    const int ch = blockIdx.x, h = blockIdx.y, b = blockIdx.z;
    const int r_base = (w & 3)*16, d_base = (w >> 2)*32;
    float acc[4][4];
    #pragma unroll
    for (int i = 0; i < 4; i++)
        #pragma unroll
        for (int q = 0; q < 4; q++) acc[i][q] = 0.f;
    float acc2[4] = {0.f, 0.f, 0.f, 0.f};   // S via ones-HMMA (warps 0-3 only)

#define STG_EX(tl, s)                                                         \
    {                                                                         \
        int n0 = ch*512 + (tl)*64;                                            \
        size_t gbase = ((size_t)(b*Nn + n0))*Dm + h*64;                       \
        _Pragma("unroll")                                                     \
        for (int p = 0; p < 2; p++) {                                         \
            int c = t + p*256;                                                \
            int row = c >> 3, off = c & 7;                                    \
            cpa16(sE[s] + row*144 + off*16, g_eb + gbase + (size_t)row*Dm + off*8); \
        }                                                                     \
        CPCOMMIT();                                                           \
        _Pragma("unroll")                                                     \
        for (int p = 0; p < 4; p++) {                                         \
            int c = t + p*256;                                                \
            int row = c >> 4, col4 = c & 15;                                  \
            float4 v = *(const float4*)(g_xv + gbase + (size_t)row*Dm + col4*4); \
            float inv = __fdividef(1.f, g_rs[((size_t)(b*Nn + n0 + row))*Hh + h]); \
            float4 sv = {v.x*inv, v.y*inv, v.z*inv, v.w*inv};                 \
            *(uint2*)(smX[s] + row*144 + col4*8) = f4_to_bf16x4(sv);          \
        }                                                                     \
    }

    STG_EX(0, 0);

    for (int tile = 0; tile < 8; tile++) {
        int s = tile & 1;
        CPWAIT0();
        __syncthreads();
        if (tile < 7) STG_EX(tile + 1, s ^ 1);

        uint32_t aoff = sE[s] + (uint32_t)((((lane >> 4) << 3) + (lane & 7))*144)
                      + (uint32_t)((r_base + (((lane >> 3) & 1) << 3))*2);
        uint32_t boff = sX[s] + (uint32_t)((lane & 15)*144) + (uint32_t)((d_base + (lane >> 4)*8)*2);
        #pragma unroll
        for (int ks = 0; ks < 4; ks++) {
            uint32_t a[4];
            ldsm4t(a, aoff + ks*16*144);
            if (w < 4) hmma(acc2, a, ONESB, ONESB);   // S[r] += sum_n e
            #pragma unroll
            for (int dq = 0; dq < 2; dq++) {
                uint32_t bf[4];
                ldsm4t(bf, boff + ks*16*144 + dq*32);
                hmma(acc[dq*2],   a, bf[0], bf[1]);
                hmma(acc[dq*2+1], a, bf[2], bf[3]);
            }
        }
        __syncthreads();
    }
    float* pp = g_pool + ((size_t)(b*Hh + h)*Rr)*HDd;
    #pragma unroll
    for (int i = 0; i < 4; i++) {
        int r = r_base + (lane >> 2);
        int d = d_base + i*8 + (lane & 3)*2;
        atomicAdd(&pp[r*HDd + d],       acc[i][0]);
        atomicAdd(&pp[r*HDd + d + 1],   acc[i][1]);
        atomicAdd(&pp[(r+8)*HDd + d],   acc[i][2]);
        atomicAdd(&pp[(r+8)*HDd + d+1], acc[i][3]);
    }
    if (w < 4 && (lane & 3) == 0) {
        int r = r_base + (lane >> 2);
        atomicAdd(&g_S[(b*Hh + h)*Rr + r],     acc2[0]);
        atomicAdd(&g_S[(b*Hh + h)*Rr + r + 8], acc2[2]);
    }
}

// ---------------- kout: out = sa*xv + sb*(E · P/S)  (kfin fused) ----------------
#define KO_E  0                  // 64 rows x 528B
#define KO_P  33792              // 256 rows x 144B (bf16 of pool/S)
#define SMEM_KOUT 70656
__global__ void __launch_bounds__(256)
kout(const float* __restrict__ alpha, const float* __restrict__ beta,
     float* __restrict__ out) {
    extern __shared__ char sm[];
    uint32_t smb = (uint32_t)__cvta_generic_to_shared(sm);
    const int t = threadIdx.x, w = t >> 5, lane = t & 31;
    const int b = blockIdx.x >> 7;
    const int n0 = (blockIdx.x & 127)*64;
    const int hw = w & 3, m_base = (w >> 2)*32;
    size_t gbase = ((size_t)(b*Nn + n0))*Dm;

    // stage E via cp.async
    #pragma unroll
    for (int p = 0; p < 8; p++) {
        int c = t + p*256;
        int row = c >> 5, off = c & 31;
        cpa16(smb + KO_E + row*528 + off*16, g_eb + gbase + (size_t)row*Dm + off*8);
    }
    CPCOMMIT();
    // stage P = bf16(g_pool / S) directly (fp32 pool is L2-resident; kfin fused here)
    #pragma unroll
    for (int p = 0; p < 16; p++) {
        int idx = t + p*256;
        int prow = idx >> 4, pcol4 = idx & 15;
        const float* basep = g_pool + (size_t)b*(Hh*Rr*HDd);
        float4 v = *(const float4*)(basep + prow*64 + pcol4*4);
        float inv = __fdividef(1.f, g_S[b*(Hh*Rr) + prow]);
        float4 sv = {v.x*inv, v.y*inv, v.z*inv, v.w*inv};
        *(uint2*)(sm + KO_P + prow*144 + pcol4*8) = f4_to_bf16x4(sv);
    }
    CPWAIT0();
    __syncthreads();

    float acc[2][8][4];
    #pragma unroll
    for (int i = 0; i < 2; i++)
        #pragma unroll
        for (int j = 0; j < 8; j++)
            #pragma unroll
            for (int q = 0; q < 4; q++) acc[i][j][q] = 0.f;

    uint32_t aoff = smb + KO_E + (uint32_t)((m_base + (lane & 15))*528)
                  + (uint32_t)(hw*128) + (lane >> 4)*16;
    uint32_t boff = smb + KO_P + (uint32_t)(hw*9216)
                  + (uint32_t)((lane & 15)*144) + (uint32_t)((lane >> 4)*16);

    #pragma unroll
    for (int ks = 0; ks < 4; ks++) {
        uint32_t a0[4], a1[4];
        ldsm4(a0, aoff + ks*32);
        ldsm4(a1, aoff + ks*32 + 16*528);
        #pragma unroll
        for (int dq = 0; dq < 4; dq++) {
            uint32_t bf[4];
            ldsm4t(bf, boff + ks*16*144 + dq*32);
            hmma(acc[0][dq*2],   a0, bf[0], bf[1]);
            hmma(acc[0][dq*2+1], a0, bf[2], bf[3]);
            hmma(acc[1][dq*2],   a1, bf[0], bf[1]);
            hmma(acc[1][dq*2+1], a1, bf[2], bf[3]);
        }
    }

    float sa = 1.f / (1.f + __expf(-alpha[hw]));
    float sb = 1.f / (1.f + __expf(-beta[hw]));
    #pragma unroll
    for (int mt = 0; mt < 2; mt++)
        #pragma unroll
        for (int j = 0; j < 8; j++) {
            int row = m_base + mt*16 + (lane >> 2);
            int col = hw*64 + j*8 + (lane & 3)*2;
            const float* c = acc[mt][j];
            {
                float2 xv = *(const float2*)(g_xv + gbase + (size_t)row*Dm + col);
                float2 o = {fmaf(sa, xv.x, sb*c[0]), fmaf(sa, xv.y, sb*c[1])};
                *(float2*)(out + gbase + (size_t)row*Dm + col) = o;
            }
            {
                float2 xv = *(const float2*)(g_xv + gbase + (size_t)(row+8)*Dm + col);
                float2 o = {fmaf(sa, xv.x, sb*c[2]), fmaf(sa, xv.y, sb*c[3])};
                *(float2*)(out + gbase + (size_t)(row+8)*Dm + col) = o;
            }
        }
}

extern "C" void kernel_launch(void* const* d_in, const int* in_sizes, int n_in,
                              void* d_out, int out_size) {
    const float* x     = (const float*)d_in[0];
    const float* z     = (const float*)d_in[1];
    const float* Wq    = (const float*)d_in[2];
    const float* bq    = (const float*)d_in[3];
    const float* K     = (const float*)d_in[4];
    const float* Wv    = (const float*)d_in[5];
    const float* bv    = (const float*)d_in[6];
    const float* alpha = (const float*)d_in[7];
    const float* beta  = (const float*)d_in[8];
    float* out = (float*)d_out;

    cudaFuncSetAttribute(kgemm_mma, cudaFuncAttributeMaxDynamicSharedMemorySize, SMEM_MMA);
    cudaFuncSetAttribute(kout,      cudaFuncAttributeMaxDynamicSharedMemorySize, SMEM_KOUT);

    kinit<<<512 + Dm + 1 + Dm, 256>>>(Wq, bq, K, Wv);
    kgemm_mma<<<dim3(Mm/128, 2, 2), 256, SMEM_MMA>>>(x, z, bv);
    kpool<<<dim3(16, Hh, Bz), 256>>>();
    kout<<<Mm/64, 256, SMEM_KOUT>>>(alpha, beta, out);
}

// round 14
// speedup vs baseline: 1.4669x; 1.0150x over previous
#include <cuda_runtime.h>
#include <cuda_bf16.h>
#include <cstdint>

#define Bz  8
#define Nn  8192
#define Dm  256
#define Hh  4
#define Rr  64
#define HDd 64
#define Mm  (Bz*Nn)

typedef unsigned long long u64;

// ---------------- device scratch ----------------
__device__ float g_bK[Dm];
__device__ float g_xv[(size_t)Mm*Dm];                 // fp32 xv (exact gate term)
__device__ __nv_bfloat16 g_eb  [(size_t)Mm*Dm];       // bf16 raw exp(attn)
__device__ float g_rs[(size_t)Mm*Hh];                 // fp32 rowsum of e per (n,h)
__device__ float g_pool[Bz*Hh*Rr*HDd];                // fp32 P0 accumulator
__device__ float g_S [Bz*Hh*Rr];
__device__ __nv_bfloat16 g_Wh[2][Dm*Dm];              // bf16 hi image of W ([k][n])
__device__ __nv_bfloat16 g_Wl[2][Dm*Dm];              // bf16 lo image (used by gemm0 only)

// ---------------- helpers ----------------
__device__ __forceinline__ void cpa16(uint32_t d, const void* s) {
    asm volatile("cp.async.cg.shared.global [%0], [%1], 16;" :: "r"(d), "l"(s));
}
#define CPCOMMIT() asm volatile("cp.async.commit_group;")
#define CPWAIT0()  asm volatile("cp.async.wait_group 0;")
#define CPWAIT1()  asm volatile("cp.async.wait_group 1;")

__device__ __forceinline__ void ldsm4(uint32_t* r, uint32_t a) {
    asm volatile("ldmatrix.sync.aligned.m8n8.x4.shared.b16 {%0,%1,%2,%3}, [%4];"
        : "=r"(r[0]), "=r"(r[1]), "=r"(r[2]), "=r"(r[3]) : "r"(a));
}
__device__ __forceinline__ void ldsm4t(uint32_t* r, uint32_t a) {
    asm volatile("ldmatrix.sync.aligned.m8n8.x4.trans.shared.b16 {%0,%1,%2,%3}, [%4];"
        : "=r"(r[0]), "=r"(r[1]), "=r"(r[2]), "=r"(r[3]) : "r"(a));
}
__device__ __forceinline__ void hmma(float* c, const uint32_t* a, uint32_t b0, uint32_t b1) {
    asm volatile("mma.sync.aligned.m16n8k16.row.col.f32.bf16.bf16.f32 "
        "{%0,%1,%2,%3}, {%4,%5,%6,%7}, {%8,%9}, {%0,%1,%2,%3};"
        : "+f"(c[0]), "+f"(c[1]), "+f"(c[2]), "+f"(c[3])
        : "r"(a[0]), "r"(a[1]), "r"(a[2]), "r"(a[3]), "r"(b0), "r"(b1));
}
__device__ __forceinline__ uint2 f4_to_bf16x4(float4 v) {
    uint32_t a, b;
    asm("cvt.rn.bf16x2.f32 %0, %1, %2;" : "=r"(a) : "f"(v.y), "f"(v.x));
    asm("cvt.rn.bf16x2.f32 %0, %1, %2;" : "=r"(b) : "f"(v.w), "f"(v.z));
    return make_uint2(a, b);
}

// ---------------- fused init ----------------
__global__ void kinit(const float* __restrict__ Wq, const float* __restrict__ bq,
                      const float* __restrict__ K, const float* __restrict__ Wv) {
    int bid = blockIdx.x;
    if (bid < 512) {
        int i = bid*256 + threadIdx.x;
        if (i < Bz*Hh*Rr*HDd) g_pool[i] = 0.f;
        if (i < Bz*Hh*Rr)     g_S[i]   = 0.f;
    } else if (bid < 512 + Dm + 1) {
        int col = threadIdx.x;
        int h = col >> 6, r = col & 63;
        const float* Krow = K + r*Dm + h*HDd;
        if (bid - 512 < Dm) {
            int c = bid - 512;
            const float* wq = Wq + c*Dm + h*HDd;
            float s = 0.f;
            #pragma unroll 16
            for (int d = 0; d < HDd; d++) s = fmaf(wq[d], Krow[d], s);
            s *= 0.125f;
            __nv_bfloat16 hi = __float2bfloat16(s);
            g_Wh[1][c*Dm + col] = hi;
            g_Wl[1][c*Dm + col] = __float2bfloat16(s - __bfloat162float(hi));
        } else {
            float s = 0.f;
            #pragma unroll 16
            for (int d = 0; d < HDd; d++) s = fmaf(bq[h*HDd + d], Krow[d], s);
            g_bK[col] = 0.125f * s;
        }
    } else {
        int k = bid - (512 + Dm + 1), n = threadIdx.x;
        float wv = Wv[(size_t)k*Dm + n];
        __nv_bfloat16 hi = __float2bfloat16(wv);
        g_Wh[0][k*Dm + n] = hi;
        g_Wl[0][k*Dm + n] = __float2bfloat16(wv - __bfloat162float(hi));
    }
}

// ---------------- HMMA GEMM: C[128,128] per CTA, K=256 in 8 chunks of 32 ----------
#define KC     32
#define ABUF(s) ((s)*20480)
#define A_LOO   10240
#define BBUF(s) (40960 + (s)*17408)
#define B_LOO   8704
#define SMEM_MMA 75776

__global__ void __launch_bounds__(256, 2)
kgemm_mma(const float* __restrict__ X, const float* __restrict__ Z,
          const float* __restrict__ bias) {
    extern __shared__ char sm[];
    uint32_t smb = (uint32_t)__cvta_generic_to_shared(sm);
    const int t = threadIdx.x, w = t >> 5, lane = t & 31;
    const int m0 = blockIdx.x*128, nh = blockIdx.y;
    const int gemm = blockIdx.z;
    const float* A = gemm ? Z : X;
    const __nv_bfloat16* Wh = g_Wh[gemm];
    const __nv_bfloat16* Wl = g_Wl[gemm];
    const float* bp = gemm ? g_bK : bias;
    const int wm = (w >> 1)*32, wn = (w & 1)*64;

    float acc[2][8][4];
    #pragma unroll
    for (int i = 0; i < 2; i++)
        #pragma unroll
        for (int j = 0; j < 8; j++)
            #pragma unroll
            for (int q = 0; q < 4; q++) acc[i][j][q] = 0.f;

#define STG_B(c, s)                                                           \
    {                                                                         \
        const __nv_bfloat16* srcH = Wh + (size_t)((c)*KC)*Dm + nh*128;        \
        const __nv_bfloat16* srcL = Wl + (size_t)((c)*KC)*Dm + nh*128;        \
        _Pragma("unroll")                                                     \
        for (int p = 0; p < 2; p++) {                                         \
            int idx = t + p*256;                                              \
            int row = idx >> 4, seg = idx & 15;                               \
            uint32_t d = smb + BBUF(s) + (uint32_t)(row*272 + seg*16);        \
            cpa16(d, srcH + (size_t)row*Dm + seg*8);                          \
            if (gemm == 0)                                                    \
                cpa16(d + B_LOO, srcL + (size_t)row*Dm + seg*8);              \
        }                                                                     \
        CPCOMMIT();                                                           \
    }
#define STG_A(c, s)                                                           \
    {                                                                         \
        int row = t >> 1, half = t & 1;                                       \
        const float4* ar = (const float4*)(A + (size_t)(m0 + row)*Dm + (c)*KC + half*16); \
        float4 vv[4];                                                         \
        _Pragma("unroll")                                                     \
        for (int j4 = 0; j4 < 4; j4++) vv[j4] = ar[j4];                       \
        char* wbH = sm + ABUF(s) + row*80 + half*32;                          \
        char* wbL = wbH + A_LOO;                                              \
        uint32_t hreg[4], lreg[4];                                            \
        _Pragma("unroll")                                                     \
        for (int j4 = 0; j4 < 4; j4++) {                                      \
            float4 v = vv[j4];                                                \
            asm("cvt.rn.bf16x2.f32 %0, %1, %2;" : "=r"(hreg[j4]) : "f"(v.y), "f"(v.x)); \
            uint32_t h23;                                                     \
            asm("cvt.rn.bf16x2.f32 %0, %1, %2;" : "=r"(h23) : "f"(v.w), "f"(v.z)); \
            if (gemm == 0) {                                                  \
                float l0 = v.x - __uint_as_float(hreg[j4] << 16);             \
                float l1 = v.y - __uint_as_float(hreg[j4] & 0xffff0000u);     \
                float l2 = v.z - __uint_as_float(h23 << 16);                  \
                float l3 = v.w - __uint_as_float(h23 & 0xffff0000u);          \
                asm("cvt.rn.bf16x2.f32 %0, %1, %2;" : "=r"(lreg[j4]) : "f"(l1), "f"(l0)); \
                uint32_t q23;                                                 \
                asm("cvt.rn.bf16x2.f32 %0, %1, %2;" : "=r"(q23) : "f"(l3), "f"(l2)); \
                lreg[j4] = lreg[j4]; /* keep */                               \
                ((uint32_t*)&vv[j4])[0] = lreg[j4]; ((uint32_t*)&vv[j4])[1] = q23; \
            }                                                                 \
            ((uint32_t*)&vv[j4])[2] = hreg[j4]; ((uint32_t*)&vv[j4])[3] = h23; \
        }                                                                     \
        *(uint4*)(wbH +  0) = make_uint4(((uint32_t*)&vv[0])[2], ((uint32_t*)&vv[0])[3], \
                                         ((uint32_t*)&vv[1])[2], ((uint32_t*)&vv[1])[3]); \
        *(uint4*)(wbH + 16) = make_uint4(((uint32_t*)&vv[2])[2], ((uint32_t*)&vv[2])[3], \
                                         ((uint32_t*)&vv[3])[2], ((uint32_t*)&vv[3])[3]); \
        if (gemm == 0) {                                                      \
            *(uint4*)(wbL +  0) = make_uint4(((uint32_t*)&vv[0])[0], ((uint32_t*)&vv[0])[1], \
                                             ((uint32_t*)&vv[1])[0], ((uint32_t*)&vv[1])[1]); \
            *(uint4*)(wbL + 16) = make_uint4(((uint32_t*)&vv[2])[0], ((uint32_t*)&vv[2])[1], \
                                             ((uint32_t*)&vv[3])[0], ((uint32_t*)&vv[3])[1]); \
        }                                                                     \
    }

    STG_B(0, 0);
    STG_A(0, 0);

    for (int c = 0; c < 8; c++) {
        int s = c & 1;
        CPWAIT0();
        __syncthreads();
        if (c < 7) {
            STG_B(c + 1, s ^ 1);
            STG_A(c + 1, s ^ 1);
        }
        uint32_t aoff = smb + ABUF(s) + (uint32_t)((wm + (lane & 15))*80) + (lane >> 4)*16;
        uint32_t boff = smb + BBUF(s) + (uint32_t)((lane & 15)*272) + (uint32_t)((wn + (lane >> 4)*8)*2);
        if (gemm == 0) {
            #pragma unroll
            for (int ks = 0; ks < 2; ks++) {
                uint32_t ah[2][4], al[2][4];
                uint32_t ab = aoff + ks*32;
                ldsm4(ah[0], ab);
                ldsm4(ah[1], ab + 16*80);
                ldsm4(al[0], ab + A_LOO);
                ldsm4(al[1], ab + A_LOO + 16*80);
                uint32_t bb = boff + ks*16*272;
                #pragma unroll
                for (int nq = 0; nq < 4; nq++) {
                    uint32_t bh[4], bl[4];
                    ldsm4t(bh, bb + nq*32);
                    ldsm4t(bl, bb + nq*32 + B_LOO);
                    #pragma unroll
                    for (int mt = 0; mt < 2; mt++) {
                        #pragma unroll
                        for (int sub = 0; sub < 2; sub++) {
                            float* cc = acc[mt][nq*2 + sub];
                            hmma(cc, ah[mt], bh[sub*2], bh[sub*2+1]);
                            hmma(cc, al[mt], bh[sub*2], bh[sub*2+1]);
                            hmma(cc, ah[mt], bl[sub*2], bl[sub*2+1]);
                        }
                    }
                }
            }
        } else {
            #pragma unroll
            for (int ks = 0; ks < 2; ks++) {
                uint32_t ah[2][4];
                uint32_t ab = aoff + ks*32;
                ldsm4(ah[0], ab);
                ldsm4(ah[1], ab + 16*80);
                uint32_t bb = boff + ks*16*272;
                #pragma unroll
                for (int nq = 0; nq < 4; nq++) {
                    uint32_t bh[4];
                    ldsm4t(bh, bb + nq*32);
                    #pragma unroll
                    for (int mt = 0; mt < 2; mt++) {
                        #pragma unroll
                        for (int sub = 0; sub < 2; sub++) {
                            float* cc = acc[mt][nq*2 + sub];
                            hmma(cc, ah[mt], bh[sub*2], bh[sub*2+1]);
                        }
                    }
                }
            }
        }
    }

    // ---- register-direct epilogue ----
    const float* bp2 = bp + nh*128;
    const int rl = lane >> 2, cq = (lane & 3)*2;
    if (gemm == 0) {
        #pragma unroll
        for (int mt = 0; mt < 2; mt++)
            #pragma unroll
            for (int j = 0; j < 8; j++) {
                int cl = wn + j*8 + cq;
                float b0 = bp2[cl], b1 = bp2[cl+1];
                int r = m0 + wm + mt*16 + rl;
                float2 o0 = {acc[mt][j][0] + b0, acc[mt][j][1] + b1};
                float2 o1 = {acc[mt][j][2] + b0, acc[mt][j][3] + b1};
                *(float2*)(g_xv + (size_t)r*Dm + nh*128 + cl)     = o0;
                *(float2*)(g_xv + (size_t)(r+8)*Dm + nh*128 + cl) = o1;
            }
    } else {
        float ps[2][2] = {{0.f,0.f},{0.f,0.f}};
        #pragma unroll
        for (int mt = 0; mt < 2; mt++)
            #pragma unroll
            for (int j = 0; j < 8; j++) {
                int cl = wn + j*8 + cq;
                float b0 = bp2[cl], b1 = bp2[cl+1];
                int r = m0 + wm + mt*16 + rl;
                float e00 = __expf(acc[mt][j][0] + b0);
                float e01 = __expf(acc[mt][j][1] + b1);
                float e10 = __expf(acc[mt][j][2] + b0);
                float e11 = __expf(acc[mt][j][3] + b1);
                ps[mt][0] += e00 + e01;
                ps[mt][1] += e10 + e11;
                uint32_t p0, p1;
                asm("cvt.rn.bf16x2.f32 %0, %1, %2;" : "=r"(p0) : "f"(e01), "f"(e00));
                asm("cvt.rn.bf16x2.f32 %0, %1, %2;" : "=r"(p1) : "f"(e11), "f"(e10));
                *(uint32_t*)(g_eb + (size_t)r*Dm + nh*128 + cl)     = p0;
                *(uint32_t*)(g_eb + (size_t)(r+8)*Dm + nh*128 + cl) = p1;
            }
        int head = nh*2 + (w & 1);
        #pragma unroll
        for (int mt = 0; mt < 2; mt++)
            #pragma unroll
            for (int rr = 0; rr < 2; rr++) {
                float s = ps[mt][rr];
                s += __shfl_xor_sync(0xffffffffu, s, 1);
                s += __shfl_xor_sync(0xffffffffu, s, 2);
                if ((lane & 3) == 0) {
                    int r = m0 + wm + mt*16 + rl + rr*8;
                    g_rs[(size_t)r*Hh + head] = s;
                }
            }
    }
}

// ---------------- kpool ----------------
#define ONESB 0x3F803F80u
__global__ void __launch_bounds__(256, 4) kpool() {
    __shared__ char smE[2][64*144];
    __shared__ char smX[2][64*144];
    uint32_t sE[2] = {(uint32_t)__cvta_generic_to_shared(smE[0]),
                      (uint32_t)__cvta_generic_to_shared(smE[1])};
    uint32_t sX[2] = {(uint32_t)__cvta_generic_to_shared(smX[0]),
                      (uint32_t)__cvta_generic_to_shared(smX[1])};
    const int t = threadIdx.x, w = t >> 5, lane = t & 31;
    const int ch = blockIdx.x, h = blockIdx.y, b = blockIdx.z;
    const int r_base = (w & 3)*16, d_base = (w >> 2)*32;
    float acc[4][4];
    #pragma unroll
    for (int i = 0; i < 4; i++)
        #pragma unroll
        for (int q = 0; q < 4; q++) acc[i][q] = 0.f;
    float acc2[4] = {0.f, 0.f, 0.f, 0.f};

#define STG_EX(tl, s)                                                         \
    {                                                                         \
        int n0 = ch*512 + (tl)*64;                                            \
        size_t gbase = ((size_t)(b*Nn + n0))*Dm + h*64;                       \
        _Pragma("unroll")                                                     \
        for (int p = 0; p < 2; p++) {                                         \
            int c = t + p*256;                                                \
            int row = c >> 3, off = c & 7;                                    \
            cpa16(sE[s] + row*144 + off*16, g_eb + gbase + (size_t)row*Dm + off*8); \
        }                                                                     \
        CPCOMMIT();                                                           \
        _Pragma("unroll")                                                     \
        for (int p = 0; p < 4; p++) {                                         \
            int c = t + p*256;                                                \
            int row = c >> 4, col4 = c & 15;                                  \
            float4 v = *(const float4*)(g_xv + gbase + (size_t)row*Dm + col4*4); \
            float inv = __fdividef(1.f, g_rs[((size_t)(b*Nn + n0 + row))*Hh + h]); \
            float4 sv = {v.x*inv, v.y*inv, v.z*inv, v.w*inv};                 \
            *(uint2*)(smX[s] + row*144 + col4*8) = f4_to_bf16x4(sv);          \
        }                                                                     \
    }

    STG_EX(0, 0);

    for (int tile = 0; tile < 8; tile++) {
        int s = tile & 1;
        CPWAIT0();
        __syncthreads();
        if (tile < 7) STG_EX(tile + 1, s ^ 1);

        uint32_t aoff = sE[s] + (uint32_t)((((lane >> 4) << 3) + (lane & 7))*144)
                      + (uint32_t)((r_base + (((lane >> 3) & 1) << 3))*2);
        uint32_t boff = sX[s] + (uint32_t)((lane & 15)*144) + (uint32_t)((d_base + (lane >> 4)*8)*2);
        #pragma unroll
        for (int ks = 0; ks < 4; ks++) {
            uint32_t a[4];
            ldsm4t(a, aoff + ks*16*144);
            if (w < 4) hmma(acc2, a, ONESB, ONESB);
            #pragma unroll
            for (int dq = 0; dq < 2; dq++) {
                uint32_t bf[4];
                ldsm4t(bf, boff + ks*16*144 + dq*32);
                hmma(acc[dq*2],   a, bf[0], bf[1]);
                hmma(acc[dq*2+1], a, bf[2], bf[3]);
            }
        }
        __syncthreads();
    }
    float* pp = g_pool + ((size_t)(b*Hh + h)*Rr)*HDd;
    #pragma unroll
    for (int i = 0; i < 4; i++) {
        int r = r_base + (lane >> 2);
        int d = d_base + i*8 + (lane & 3)*2;
        atomicAdd(&pp[r*HDd + d],       acc[i][0]);
        atomicAdd(&pp[r*HDd + d + 1],   acc[i][1]);
        atomicAdd(&pp[(r+8)*HDd + d],   acc[i][2]);
        atomicAdd(&pp[(r+8)*HDd + d+1], acc[i][3]);
    }
    if (w < 4 && (lane & 3) == 0) {
        int r = r_base + (lane >> 2);
        atomicAdd(&g_S[(b*Hh + h)*Rr + r],     acc2[0]);
        atomicAdd(&g_S[(b*Hh + h)*Rr + r + 8], acc2[2]);
    }
}

// ---------------- kout: 2 sub-tiles per CTA, double-buffered E ----------------
#define KO_E(s) ((s)*33792)          // 64 rows x 528B each
#define KO_P    67584                // 256 rows x 144B (bf16 pool/S)
#define SMEM_KOUT 104448
__global__ void __launch_bounds__(256, 2)
kout(const float* __restrict__ alpha, const float* __restrict__ beta,
     float* __restrict__ out) {
    extern __shared__ char sm[];
    uint32_t smb = (uint32_t)__cvta_generic_to_shared(sm);
    const int t = threadIdx.x, w = t >> 5, lane = t & 31;
    const int b = blockIdx.x >> 6;
    const int n0 = (blockIdx.x & 63)*128;
    const int hw = w & 3, m_base = (w >> 2)*32;

    // issue both E sub-tile loads up-front
    #pragma unroll
    for (int st = 0; st < 2; st++) {
        size_t gb = ((size_t)(b*Nn + n0 + st*64))*Dm;
        #pragma unroll
        for (int p = 0; p < 8; p++) {
            int c = t + p*256;
            int row = c >> 5, off = c & 31;
            cpa16(smb + KO_E(st) + row*528 + off*16, g_eb + gb + (size_t)row*Dm + off*8);
        }
        CPCOMMIT();
    }
    // stage P = bf16(pool/S) once, under the E flights
    #pragma unroll
    for (int p = 0; p < 16; p++) {
        int idx = t + p*256;
        int prow = idx >> 4, pcol4 = idx & 15;
        const float* basep = g_pool + (size_t)b*(Hh*Rr*HDd);
        float4 v = *(const float4*)(basep + prow*64 + pcol4*4);
        float inv = __fdividef(1.f, g_S[b*(Hh*Rr) + prow]);
        float4 sv = {v.x*inv, v.y*inv, v.z*inv, v.w*inv};
        *(uint2*)(sm + KO_P + prow*144 + pcol4*8) = f4_to_bf16x4(sv);
    }

    float sa = 1.f / (1.f + __expf(-alpha[hw]));
    float sb = 1.f / (1.f + __expf(-beta[hw]));
    uint32_t boff = smb + KO_P + (uint32_t)(hw*9216)
                  + (uint32_t)((lane & 15)*144) + (uint32_t)((lane >> 4)*16);

    #pragma unroll
    for (int st = 0; st < 2; st++) {
        if (st == 0) CPWAIT1(); else CPWAIT0();
        __syncthreads();

        float acc[2][8][4];
        #pragma unroll
        for (int i = 0; i < 2; i++)
            #pragma unroll
            for (int j = 0; j < 8; j++)
                #pragma unroll
                for (int q = 0; q < 4; q++) acc[i][j][q] = 0.f;

        uint32_t aoff = smb + KO_E(st) + (uint32_t)((m_base + (lane & 15))*528)
                      + (uint32_t)(hw*128) + (lane >> 4)*16;
        #pragma unroll
        for (int ks = 0; ks < 4; ks++) {
            uint32_t a0[4], a1[4];
            ldsm4(a0, aoff + ks*32);
            ldsm4(a1, aoff + ks*32 + 16*528);
            #pragma unroll
            for (int dq = 0; dq < 4; dq++) {
                uint32_t bf[4];
                ldsm4t(bf, boff + ks*16*144 + dq*32);
                hmma(acc[0][dq*2],   a0, bf[0], bf[1]);
                hmma(acc[0][dq*2+1], a0, bf[2], bf[3]);
                hmma(acc[1][dq*2],   a1, bf[0], bf[1]);
                hmma(acc[1][dq*2+1], a1, bf[2], bf[3]);
            }
        }

        size_t gbase = ((size_t)(b*Nn + n0 + st*64))*Dm;
        #pragma unroll
        for (int mt = 0; mt < 2; mt++)
            #pragma unroll
            for (int j = 0; j < 8; j++) {
                int row = m_base + mt*16 + (lane >> 2);
                int col = hw*64 + j*8 + (lane & 3)*2;
                const float* c = acc[mt][j];
                {
                    float2 xv = *(const float2*)(g_xv + gbase + (size_t)row*Dm + col);
                    float2 o = {fmaf(sa, xv.x, sb*c[0]), fmaf(sa, xv.y, sb*c[1])};
                    *(float2*)(out + gbase + (size_t)row*Dm + col) = o;
                }
                {
                    float2 xv = *(const float2*)(g_xv + gbase + (size_t)(row+8)*Dm + col);
                    float2 o = {fmaf(sa, xv.x, sb*c[2]), fmaf(sa, xv.y, sb*c[3])};
                    *(float2*)(out + gbase + (size_t)(row+8)*Dm + col) = o;
                }
            }
    }
}

extern "C" void kernel_launch(void* const* d_in, const int* in_sizes, int n_in,
                              void* d_out, int out_size) {
    const float* x     = (const float*)d_in[0];
    const float* z     = (const float*)d_in[1];
    const float* Wq    = (const float*)d_in[2];
    const float* bq    = (const float*)d_in[3];
    const float* K     = (const float*)d_in[4];
    const float* Wv    = (const float*)d_in[5];
    const float* bv    = (const float*)d_in[6];
    const float* alpha = (const float*)d_in[7];
    const float* beta  = (const float*)d_in[8];
    float* out = (float*)d_out;

    cudaFuncSetAttribute(kgemm_mma, cudaFuncAttributeMaxDynamicSharedMemorySize, SMEM_MMA);
    cudaFuncSetAttribute(kout,      cudaFuncAttributeMaxDynamicSharedMemorySize, SMEM_KOUT);

    kinit<<<512 + Dm + 1 + Dm, 256>>>(Wq, bq, K, Wv);
    kgemm_mma<<<dim3(Mm/128, 2, 2), 256, SMEM_MMA>>>(x, z, bv);
    kpool<<<dim3(16, Hh, Bz), 256>>>();
    kout<<<Mm/128, 256, SMEM_KOUT>>>(alpha, beta, out);
}

// round 15
// speedup vs baseline: 1.5479x; 1.0552x over previous
#include <cuda_runtime.h>
#include <cuda_bf16.h>
#include <cstdint>

#define Bz  8
#define Nn  8192
#define Dm  256
#define Hh  4
#define Rr  64
#define HDd 64
#define Mm  (Bz*Nn)

typedef unsigned long long u64;

// ---------------- device scratch ----------------
__device__ float g_bK[Dm];
__device__ float g_xv[(size_t)Mm*Dm];                 // fp32 xv (exact gate term)
__device__ __nv_bfloat16 g_eb  [(size_t)Mm*Dm];       // bf16 raw exp(attn)
__device__ float g_rs[(size_t)Mm*Hh];                 // fp32 rowsum of e per (n,h)
__device__ float g_pool[Bz*Hh*Rr*HDd];                // fp32 P0 accumulator
__device__ float g_S [Bz*Hh*Rr];
__device__ __nv_bfloat16 g_Wh[2][Dm*Dm];              // bf16 hi image of W ([k][n])
__device__ __nv_bfloat16 g_Wl[2][Dm*Dm];              // bf16 lo image (used by gemm0 only)

// ---------------- helpers ----------------
__device__ __forceinline__ void cpa16(uint32_t d, const void* s) {
    asm volatile("cp.async.cg.shared.global [%0], [%1], 16;" :: "r"(d), "l"(s));
}
#define CPCOMMIT() asm volatile("cp.async.commit_group;")
#define CPWAIT0()  asm volatile("cp.async.wait_group 0;")

__device__ __forceinline__ void ldsm4(uint32_t* r, uint32_t a) {
    asm volatile("ldmatrix.sync.aligned.m8n8.x4.shared.b16 {%0,%1,%2,%3}, [%4];"
        : "=r"(r[0]), "=r"(r[1]), "=r"(r[2]), "=r"(r[3]) : "r"(a));
}
__device__ __forceinline__ void ldsm4t(uint32_t* r, uint32_t a) {
    asm volatile("ldmatrix.sync.aligned.m8n8.x4.trans.shared.b16 {%0,%1,%2,%3}, [%4];"
        : "=r"(r[0]), "=r"(r[1]), "=r"(r[2]), "=r"(r[3]) : "r"(a));
}
__device__ __forceinline__ void hmma(float* c, const uint32_t* a, uint32_t b0, uint32_t b1) {
    asm volatile("mma.sync.aligned.m16n8k16.row.col.f32.bf16.bf16.f32 "
        "{%0,%1,%2,%3}, {%4,%5,%6,%7}, {%8,%9}, {%0,%1,%2,%3};"
        : "+f"(c[0]), "+f"(c[1]), "+f"(c[2]), "+f"(c[3])
        : "r"(a[0]), "r"(a[1]), "r"(a[2]), "r"(a[3]), "r"(b0), "r"(b1));
}
__device__ __forceinline__ uint2 f4_to_bf16x4(float4 v) {
    uint32_t a, b;
    asm("cvt.rn.bf16x2.f32 %0, %1, %2;" : "=r"(a) : "f"(v.y), "f"(v.x));
    asm("cvt.rn.bf16x2.f32 %0, %1, %2;" : "=r"(b) : "f"(v.w), "f"(v.z));
    return make_uint2(a, b);
}

// ---------------- fused init ----------------
__global__ void kinit(const float* __restrict__ Wq, const float* __restrict__ bq,
                      const float* __restrict__ K, const float* __restrict__ Wv) {
    int bid = blockIdx.x;
    if (bid < 512) {
        int i = bid*256 + threadIdx.x;
        if (i < Bz*Hh*Rr*HDd) g_pool[i] = 0.f;
        if (i < Bz*Hh*Rr)     g_S[i]   = 0.f;
    } else if (bid < 512 + Dm + 1) {
        int col = threadIdx.x;
        int h = col >> 6, r = col & 63;
        const float* Krow = K + r*Dm + h*HDd;
        if (bid - 512 < Dm) {
            int c = bid - 512;
            const float* wq = Wq + c*Dm + h*HDd;
            float s = 0.f;
            #pragma unroll 16
            for (int d = 0; d < HDd; d++) s = fmaf(wq[d], Krow[d], s);
            s *= 0.125f;
            __nv_bfloat16 hi = __float2bfloat16(s);
            g_Wh[1][c*Dm + col] = hi;
            g_Wl[1][c*Dm + col] = __float2bfloat16(s - __bfloat162float(hi));
        } else {
            float s = 0.f;
            #pragma unroll 16
            for (int d = 0; d < HDd; d++) s = fmaf(bq[h*HDd + d], Krow[d], s);
            g_bK[col] = 0.125f * s;
        }
    } else {
        int k = bid - (512 + Dm + 1), n = threadIdx.x;
        float wv = Wv[(size_t)k*Dm + n];
        __nv_bfloat16 hi = __float2bfloat16(wv);
        g_Wh[0][k*Dm + n] = hi;
        g_Wl[0][k*Dm + n] = __float2bfloat16(wv - __bfloat162float(hi));
    }
}

// ---------------- HMMA GEMM: C[128,128] per CTA, K=256 in 8 chunks of 32 ----------
#define KC     32
#define ABUF(s) ((s)*20480)
#define A_LOO   10240
#define BBUF(s) (40960 + (s)*17408)
#define B_LOO   8704
#define SMEM_MMA 75776

__global__ void __launch_bounds__(256, 2)
kgemm_mma(const float* __restrict__ X, const float* __restrict__ Z,
          const float* __restrict__ bias) {
    extern __shared__ char sm[];
    uint32_t smb = (uint32_t)__cvta_generic_to_shared(sm);
    const int t = threadIdx.x, w = t >> 5, lane = t & 31;
    const int m0 = blockIdx.x*128, nh = blockIdx.y;
    const int gemm = blockIdx.z;
    const float* A = gemm ? Z : X;
    const __nv_bfloat16* Wh = g_Wh[gemm];
    const __nv_bfloat16* Wl = g_Wl[gemm];
    const float* bp = gemm ? g_bK : bias;
    const int wm = (w >> 1)*32, wn = (w & 1)*64;

    float acc[2][8][4];
    #pragma unroll
    for (int i = 0; i < 2; i++)
        #pragma unroll
        for (int j = 0; j < 8; j++)
            #pragma unroll
            for (int q = 0; q < 4; q++) acc[i][j][q] = 0.f;

#define STG_B(c, s)                                                           \
    {                                                                         \
        const __nv_bfloat16* srcH = Wh + (size_t)((c)*KC)*Dm + nh*128;        \
        const __nv_bfloat16* srcL = Wl + (size_t)((c)*KC)*Dm + nh*128;        \
        _Pragma("unroll")                                                     \
        for (int p = 0; p < 2; p++) {                                         \
            int idx = t + p*256;                                              \
            int row = idx >> 4, seg = idx & 15;                               \
            uint32_t d = smb + BBUF(s) + (uint32_t)(row*272 + seg*16);        \
            cpa16(d, srcH + (size_t)row*Dm + seg*8);                          \
            if (gemm == 0)                                                    \
                cpa16(d + B_LOO, srcL + (size_t)row*Dm + seg*8);              \
        }                                                                     \
        CPCOMMIT();                                                           \
    }
#define STG_A(c, s)                                                           \
    {                                                                         \
        int row = t >> 1, half = t & 1;                                       \
        const float4* ar = (const float4*)(A + (size_t)(m0 + row)*Dm + (c)*KC + half*16); \
        float4 vv[4];                                                         \
        _Pragma("unroll")                                                     \
        for (int j4 = 0; j4 < 4; j4++) vv[j4] = ar[j4];                       \
        char* wbH = sm + ABUF(s) + row*80 + half*32;                          \
        char* wbL = wbH + A_LOO;                                              \
        uint32_t hr[8], lr[8];                                                \
        _Pragma("unroll")                                                     \
        for (int j4 = 0; j4 < 4; j4++) {                                      \
            float4 v = vv[j4];                                                \
            asm("cvt.rn.bf16x2.f32 %0, %1, %2;" : "=r"(hr[j4*2])   : "f"(v.y), "f"(v.x)); \
            asm("cvt.rn.bf16x2.f32 %0, %1, %2;" : "=r"(hr[j4*2+1]) : "f"(v.w), "f"(v.z)); \
            if (gemm == 0) {                                                  \
                float l0 = v.x - __uint_as_float(hr[j4*2] << 16);             \
                float l1 = v.y - __uint_as_float(hr[j4*2] & 0xffff0000u);     \
                float l2 = v.z - __uint_as_float(hr[j4*2+1] << 16);           \
                float l3 = v.w - __uint_as_float(hr[j4*2+1] & 0xffff0000u);   \
                asm("cvt.rn.bf16x2.f32 %0, %1, %2;" : "=r"(lr[j4*2])   : "f"(l1), "f"(l0)); \
                asm("cvt.rn.bf16x2.f32 %0, %1, %2;" : "=r"(lr[j4*2+1]) : "f"(l3), "f"(l2)); \
            }                                                                 \
        }                                                                     \
        *(uint4*)(wbH +  0) = make_uint4(hr[0], hr[1], hr[2], hr[3]);         \
        *(uint4*)(wbH + 16) = make_uint4(hr[4], hr[5], hr[6], hr[7]);         \
        if (gemm == 0) {                                                      \
            *(uint4*)(wbL +  0) = make_uint4(lr[0], lr[1], lr[2], lr[3]);     \
            *(uint4*)(wbL + 16) = make_uint4(lr[4], lr[5], lr[6], lr[7]);     \
        }                                                                     \
    }

    STG_B(0, 0);
    STG_A(0, 0);

    for (int c = 0; c < 8; c++) {
        int s = c & 1;
        CPWAIT0();
        __syncthreads();
        if (c < 7) {
            STG_B(c + 1, s ^ 1);
            STG_A(c + 1, s ^ 1);
        }
        uint32_t aoff = smb + ABUF(s) + (uint32_t)((wm + (lane & 15))*80) + (lane >> 4)*16;
        uint32_t boff = smb + BBUF(s) + (uint32_t)((lane & 15)*272) + (uint32_t)((wn + (lane >> 4)*8)*2);
        if (gemm == 0) {
            #pragma unroll
            for (int ks = 0; ks < 2; ks++) {
                uint32_t ah[2][4], al[2][4];
                uint32_t ab = aoff + ks*32;
                ldsm4(ah[0], ab);
                ldsm4(ah[1], ab + 16*80);
                ldsm4(al[0], ab + A_LOO);
                ldsm4(al[1], ab + A_LOO + 16*80);
                uint32_t bb = boff + ks*16*272;
                #pragma unroll
                for (int nq = 0; nq < 4; nq++) {
                    uint32_t bh[4], bl[4];
                    ldsm4t(bh, bb + nq*32);
                    ldsm4t(bl, bb + nq*32 + B_LOO);
                    #pragma unroll
                    for (int mt = 0; mt < 2; mt++) {
                        #pragma unroll
                        for (int sub = 0; sub < 2; sub++) {
                            float* cc = acc[mt][nq*2 + sub];
                            hmma(cc, ah[mt], bh[sub*2], bh[sub*2+1]);
                            hmma(cc, al[mt], bh[sub*2], bh[sub*2+1]);
                            hmma(cc, ah[mt], bl[sub*2], bl[sub*2+1]);
                        }
                    }
                }
            }
        } else {
            #pragma unroll
            for (int ks = 0; ks < 2; ks++) {
                uint32_t ah[2][4];
                uint32_t ab = aoff + ks*32;
                ldsm4(ah[0], ab);
                ldsm4(ah[1], ab + 16*80);
                uint32_t bb = boff + ks*16*272;
                #pragma unroll
                for (int nq = 0; nq < 4; nq++) {
                    uint32_t bh[4];
                    ldsm4t(bh, bb + nq*32);
                    #pragma unroll
                    for (int mt = 0; mt < 2; mt++) {
                        #pragma unroll
                        for (int sub = 0; sub < 2; sub++) {
                            float* cc = acc[mt][nq*2 + sub];
                            hmma(cc, ah[mt], bh[sub*2], bh[sub*2+1]);
                        }
                    }
                }
            }
        }
    }

    // ---- register-direct epilogue ----
    const float* bp2 = bp + nh*128;
    const int rl = lane >> 2, cq = (lane & 3)*2;
    if (gemm == 0) {
        #pragma unroll
        for (int mt = 0; mt < 2; mt++)
            #pragma unroll
            for (int j = 0; j < 8; j++) {
                int cl = wn + j*8 + cq;
                float b0 = bp2[cl], b1 = bp2[cl+1];
                int r = m0 + wm + mt*16 + rl;
                float2 o0 = {acc[mt][j][0] + b0, acc[mt][j][1] + b1};
                float2 o1 = {acc[mt][j][2] + b0, acc[mt][j][3] + b1};
                *(float2*)(g_xv + (size_t)r*Dm + nh*128 + cl)     = o0;
                *(float2*)(g_xv + (size_t)(r+8)*Dm + nh*128 + cl) = o1;
            }
    } else {
        float ps[2][2] = {{0.f,0.f},{0.f,0.f}};
        #pragma unroll
        for (int mt = 0; mt < 2; mt++)
            #pragma unroll
            for (int j = 0; j < 8; j++) {
                int cl = wn + j*8 + cq;
                float b0 = bp2[cl], b1 = bp2[cl+1];
                int r = m0 + wm + mt*16 + rl;
                float e00 = __expf(acc[mt][j][0] + b0);
                float e01 = __expf(acc[mt][j][1] + b1);
                float e10 = __expf(acc[mt][j][2] + b0);
                float e11 = __expf(acc[mt][j][3] + b1);
                ps[mt][0] += e00 + e01;
                ps[mt][1] += e10 + e11;
                uint32_t p0, p1;
                asm("cvt.rn.bf16x2.f32 %0, %1, %2;" : "=r"(p0) : "f"(e01), "f"(e00));
                asm("cvt.rn.bf16x2.f32 %0, %1, %2;" : "=r"(p1) : "f"(e11), "f"(e10));
                *(uint32_t*)(g_eb + (size_t)r*Dm + nh*128 + cl)     = p0;
                *(uint32_t*)(g_eb + (size_t)(r+8)*Dm + nh*128 + cl) = p1;
            }
        int head = nh*2 + (w & 1);
        #pragma unroll
        for (int mt = 0; mt < 2; mt++)
            #pragma unroll
            for (int rr = 0; rr < 2; rr++) {
                float s = ps[mt][rr];
                s += __shfl_xor_sync(0xffffffffu, s, 1);
                s += __shfl_xor_sync(0xffffffffu, s, 2);
                if ((lane & 3) == 0) {
                    int r = m0 + wm + mt*16 + rl + rr*8;
                    g_rs[(size_t)r*Hh + head] = s;
                }
            }
    }
}

// ---------------- kpool ----------------
#define ONESB 0x3F803F80u
__global__ void __launch_bounds__(256, 4) kpool() {
    __shared__ char smE[2][64*144];
    __shared__ char smX[2][64*144];
    uint32_t sE[2] = {(uint32_t)__cvta_generic_to_shared(smE[0]),
                      (uint32_t)__cvta_generic_to_shared(smE[1])};
    uint32_t sX[2] = {(uint32_t)__cvta_generic_to_shared(smX[0]),
                      (uint32_t)__cvta_generic_to_shared(smX[1])};
    const int t = threadIdx.x, w = t >> 5, lane = t & 31;
    const int ch = blockIdx.x, h = blockIdx.y, b = blockIdx.z;
    const int r_base = (w & 3)*16, d_base = (w >> 2)*32;
    float acc[4][4];
    #pragma unroll
    for (int i = 0; i < 4; i++)
        #pragma unroll
        for (int q = 0; q < 4; q++) acc[i][q] = 0.f;
    float acc2[4] = {0.f, 0.f, 0.f, 0.f};

#define STG_EX(tl, s)                                                         \
    {                                                                         \
        int n0 = ch*512 + (tl)*64;                                            \
        size_t gbase = ((size_t)(b*Nn + n0))*Dm + h*64;                       \
        _Pragma("unroll")                                                     \
        for (int p = 0; p < 2; p++) {                                         \
            int c = t + p*256;                                                \
            int row = c >> 3, off = c & 7;                                    \
            cpa16(sE[s] + row*144 + off*16, g_eb + gbase + (size_t)row*Dm + off*8); \
        }                                                                     \
        CPCOMMIT();                                                           \
        _Pragma("unroll")                                                     \
        for (int p = 0; p < 4; p++) {                                         \
            int c = t + p*256;                                                \
            int row = c >> 4, col4 = c & 15;                                  \
            float4 v = *(const float4*)(g_xv + gbase + (size_t)row*Dm + col4*4); \
            float inv = __fdividef(1.f, g_rs[((size_t)(b*Nn + n0 + row))*Hh + h]); \
            float4 sv = {v.x*inv, v.y*inv, v.z*inv, v.w*inv};                 \
            *(uint2*)(smX[s] + row*144 + col4*8) = f4_to_bf16x4(sv);          \
        }                                                                     \
    }

    STG_EX(0, 0);

    for (int tile = 0; tile < 8; tile++) {
        int s = tile & 1;
        CPWAIT0();
        __syncthreads();
        if (tile < 7) STG_EX(tile + 1, s ^ 1);

        uint32_t aoff = sE[s] + (uint32_t)((((lane >> 4) << 3) + (lane & 7))*144)
                      + (uint32_t)((r_base + (((lane >> 3) & 1) << 3))*2);
        uint32_t boff = sX[s] + (uint32_t)((lane & 15)*144) + (uint32_t)((d_base + (lane >> 4)*8)*2);
        #pragma unroll
        for (int ks = 0; ks < 4; ks++) {
            uint32_t a[4];
            ldsm4t(a, aoff + ks*16*144);
            if (w < 4) hmma(acc2, a, ONESB, ONESB);
            #pragma unroll
            for (int dq = 0; dq < 2; dq++) {
                uint32_t bf[4];
                ldsm4t(bf, boff + ks*16*144 + dq*32);
                hmma(acc[dq*2],   a, bf[0], bf[1]);
                hmma(acc[dq*2+1], a, bf[2], bf[3]);
            }
        }
        __syncthreads();
    }
    float* pp = g_pool + ((size_t)(b*Hh + h)*Rr)*HDd;
    #pragma unroll
    for (int i = 0; i < 4; i++) {
        int r = r_base + (lane >> 2);
        int d = d_base + i*8 + (lane & 3)*2;
        atomicAdd(&pp[r*HDd + d],       acc[i][0]);
        atomicAdd(&pp[r*HDd + d + 1],   acc[i][1]);
        atomicAdd(&pp[(r+8)*HDd + d],   acc[i][2]);
        atomicAdd(&pp[(r+8)*HDd + d+1], acc[i][3]);
    }
    if (w < 4 && (lane & 3) == 0) {
        int r = r_base + (lane >> 2);
        atomicAdd(&g_S[(b*Hh + h)*Rr + r],     acc2[0]);
        atomicAdd(&g_S[(b*Hh + h)*Rr + r + 8], acc2[2]);
    }
}

// ---------------- kout: single tile, mt-split accumulators, batched xv loads ----------------
#define KO_E  0                  // 64 rows x 528B
#define KO_P  33792              // 256 rows x 144B (bf16 pool/S)
#define SMEM_KOUT 70656
__global__ void __launch_bounds__(256, 3)
kout(const float* __restrict__ alpha, const float* __restrict__ beta,
     float* __restrict__ out) {
    extern __shared__ char sm[];
    uint32_t smb = (uint32_t)__cvta_generic_to_shared(sm);
    const int t = threadIdx.x, w = t >> 5, lane = t & 31;
    const int b = blockIdx.x >> 7;
    const int n0 = (blockIdx.x & 127)*64;
    const int hw = w & 3, m_base = (w >> 2)*32;
    size_t gbase = ((size_t)(b*Nn + n0))*Dm;

    // stage E via cp.async
    #pragma unroll
    for (int p = 0; p < 8; p++) {
        int c = t + p*256;
        int row = c >> 5, off = c & 31;
        cpa16(smb + KO_E + row*528 + off*16, g_eb + gbase + (size_t)row*Dm + off*8);
    }
    CPCOMMIT();
    // stage P = bf16(pool/S) under the E flight
    #pragma unroll
    for (int p = 0; p < 16; p++) {
        int idx = t + p*256;
        int prow = idx >> 4, pcol4 = idx & 15;
        const float* basep = g_pool + (size_t)b*(Hh*Rr*HDd);
        float4 v = *(const float4*)(basep + prow*64 + pcol4*4);
        float inv = __fdividef(1.f, g_S[b*(Hh*Rr) + prow]);
        float4 sv = {v.x*inv, v.y*inv, v.z*inv, v.w*inv};
        *(uint2*)(sm + KO_P + prow*144 + pcol4*8) = f4_to_bf16x4(sv);
    }
    CPWAIT0();
    __syncthreads();

    float sa = 1.f / (1.f + __expf(-alpha[hw]));
    float sb = 1.f / (1.f + __expf(-beta[hw]));
    uint32_t boff = smb + KO_P + (uint32_t)(hw*9216)
                  + (uint32_t)((lane & 15)*144) + (uint32_t)((lane >> 4)*16);
    const int colb = hw*64 + (lane & 3)*2;

    #pragma unroll
    for (int mt = 0; mt < 2; mt++) {
        float acc[8][4];
        #pragma unroll
        for (int j = 0; j < 8; j++)
            #pragma unroll
            for (int q = 0; q < 4; q++) acc[j][q] = 0.f;

        uint32_t aoff = smb + KO_E + (uint32_t)((m_base + mt*16 + (lane & 15))*528)
                      + (uint32_t)(hw*128) + (lane >> 4)*16;
        #pragma unroll
        for (int ks = 0; ks < 4; ks++) {
            uint32_t a[4];
            ldsm4(a, aoff + ks*32);
            #pragma unroll
            for (int dq = 0; dq < 4; dq++) {
                uint32_t bf[4];
                ldsm4t(bf, boff + ks*16*144 + dq*32);
                hmma(acc[dq*2],   a, bf[0], bf[1]);
                hmma(acc[dq*2+1], a, bf[2], bf[3]);
            }
        }

        // batched epilogue: issue all 16 xv loads first (MLP=16), then FMA+store
        int row = m_base + mt*16 + (lane >> 2);
        const float* xvp0 = g_xv + gbase + (size_t)row*Dm + colb;
        const float* xvp1 = g_xv + gbase + (size_t)(row+8)*Dm + colb;
        float2 xv0[8], xv1[8];
        #pragma unroll
        for (int j = 0; j < 8; j++) {
            xv0[j] = *(const float2*)(xvp0 + j*8);
            xv1[j] = *(const float2*)(xvp1 + j*8);
        }
        float* op0 = out + gbase + (size_t)row*Dm + colb;
        float* op1 = out + gbase + (size_t)(row+8)*Dm + colb;
        #pragma unroll
        for (int j = 0; j < 8; j++) {
            float2 o0 = {fmaf(sa, xv0[j].x, sb*acc[j][0]),
                         fmaf(sa, xv0[j].y, sb*acc[j][1])};
            float2 o1 = {fmaf(sa, xv1[j].x, sb*acc[j][2]),
                         fmaf(sa, xv1[j].y, sb*acc[j][3])};
            *(float2*)(op0 + j*8) = o0;
            *(float2*)(op1 + j*8) = o1;
        }
    }
}

extern "C" void kernel_launch(void* const* d_in, const int* in_sizes, int n_in,
                              void* d_out, int out_size) {
    const float* x     = (const float*)d_in[0];
    const float* z     = (const float*)d_in[1];
    const float* Wq    = (const float*)d_in[2];
    const float* bq    = (const float*)d_in[3];
    const float* K     = (const float*)d_in[4];
    const float* Wv    = (const float*)d_in[5];
    const float* bv    = (const float*)d_in[6];
    const float* alpha = (const float*)d_in[7];
    const float* beta  = (const float*)d_in[8];
    float* out = (float*)d_out;

    cudaFuncSetAttribute(kgemm_mma, cudaFuncAttributeMaxDynamicSharedMemorySize, SMEM_MMA);
    cudaFuncSetAttribute(kout,      cudaFuncAttributeMaxDynamicSharedMemorySize, SMEM_KOUT);

    kinit<<<512 + Dm + 1 + Dm, 256>>>(Wq, bq, K, Wv);
    kgemm_mma<<<dim3(Mm/128, 2, 2), 256, SMEM_MMA>>>(x, z, bv);
    kpool<<<dim3(16, Hh, Bz), 256>>>();
    kout<<<Mm/64, 256, SMEM_KOUT>>>(alpha, beta, out);
}

// round 16
// speedup vs baseline: 1.5812x; 1.0215x over previous
#include <cuda_runtime.h>
#include <cuda_bf16.h>
#include <cstdint>

#define Bz  8
#define Nn  8192
#define Dm  256
#define Hh  4
#define Rr  64
#define HDd 64
#define Mm  (Bz*Nn)

typedef unsigned long long u64;

// ---------------- device scratch ----------------
__device__ float g_bK[Dm];
__device__ float g_xv[(size_t)Mm*Dm];                 // fp32 xv (exact gate term)
__device__ __nv_bfloat16 g_eb  [(size_t)Mm*Dm];       // bf16 raw exp(attn)
__device__ float g_rs[(size_t)Mm*Hh];                 // fp32 rowsum of e per (n,h)
__device__ float g_pool[Bz*Hh*Rr*HDd];                // fp32 P0 accumulator
__device__ float g_S [Bz*Hh*Rr];
__device__ __nv_bfloat16 g_Wh[2][Dm*Dm];              // bf16 hi image of W ([k][n])
__device__ __nv_bfloat16 g_Wl[2][Dm*Dm];              // bf16 lo image (used by gemm0 only)

// ---------------- helpers ----------------
__device__ __forceinline__ void cpa16(uint32_t d, const void* s) {
    asm volatile("cp.async.cg.shared.global [%0], [%1], 16;" :: "r"(d), "l"(s));
}
#define CPCOMMIT() asm volatile("cp.async.commit_group;")
#define CPWAIT0()  asm volatile("cp.async.wait_group 0;")

__device__ __forceinline__ void ldsm4(uint32_t* r, uint32_t a) {
    asm volatile("ldmatrix.sync.aligned.m8n8.x4.shared.b16 {%0,%1,%2,%3}, [%4];"
        : "=r"(r[0]), "=r"(r[1]), "=r"(r[2]), "=r"(r[3]) : "r"(a));
}
__device__ __forceinline__ void ldsm4t(uint32_t* r, uint32_t a) {
    asm volatile("ldmatrix.sync.aligned.m8n8.x4.trans.shared.b16 {%0,%1,%2,%3}, [%4];"
        : "=r"(r[0]), "=r"(r[1]), "=r"(r[2]), "=r"(r[3]) : "r"(a));
}
__device__ __forceinline__ void hmma(float* c, const uint32_t* a, uint32_t b0, uint32_t b1) {
    asm volatile("mma.sync.aligned.m16n8k16.row.col.f32.bf16.bf16.f32 "
        "{%0,%1,%2,%3}, {%4,%5,%6,%7}, {%8,%9}, {%0,%1,%2,%3};"
        : "+f"(c[0]), "+f"(c[1]), "+f"(c[2]), "+f"(c[3])
        : "r"(a[0]), "r"(a[1]), "r"(a[2]), "r"(a[3]), "r"(b0), "r"(b1));
}
__device__ __forceinline__ uint2 f4_to_bf16x4(float4 v) {
    uint32_t a, b;
    asm("cvt.rn.bf16x2.f32 %0, %1, %2;" : "=r"(a) : "f"(v.y), "f"(v.x));
    asm("cvt.rn.bf16x2.f32 %0, %1, %2;" : "=r"(b) : "f"(v.w), "f"(v.z));
    return make_uint2(a, b);
}

// ---------------- fused init ----------------
__global__ void kinit(const float* __restrict__ Wq, const float* __restrict__ bq,
                      const float* __restrict__ K, const float* __restrict__ Wv) {
    int bid = blockIdx.x;
    if (bid < 512) {
        int i = bid*256 + threadIdx.x;
        if (i < Bz*Hh*Rr*HDd) g_pool[i] = 0.f;
        if (i < Bz*Hh*Rr)     g_S[i]   = 0.f;
    } else if (bid < 512 + Dm + 1) {
        int col = threadIdx.x;
        int h = col >> 6, r = col & 63;
        const float* Krow = K + r*Dm + h*HDd;
        if (bid - 512 < Dm) {
            int c = bid - 512;
            const float* wq = Wq + c*Dm + h*HDd;
            float s = 0.f;
            #pragma unroll 16
            for (int d = 0; d < HDd; d++) s = fmaf(wq[d], Krow[d], s);
            s *= 0.125f;
            __nv_bfloat16 hi = __float2bfloat16(s);
            g_Wh[1][c*Dm + col] = hi;
            g_Wl[1][c*Dm + col] = __float2bfloat16(s - __bfloat162float(hi));
        } else {
            float s = 0.f;
            #pragma unroll 16
            for (int d = 0; d < HDd; d++) s = fmaf(bq[h*HDd + d], Krow[d], s);
            g_bK[col] = 0.125f * s;
        }
    } else {
        int k = bid - (512 + Dm + 1), n = threadIdx.x;
        float wv = Wv[(size_t)k*Dm + n];
        __nv_bfloat16 hi = __float2bfloat16(wv);
        g_Wh[0][k*Dm + n] = hi;
        g_Wl[0][k*Dm + n] = __float2bfloat16(wv - __bfloat162float(hi));
    }
}

// ---------------- HMMA GEMM: C[128,128] per CTA, K=256 in 8 chunks of 32 ----------
#define KC     32
#define ABUF(s) ((s)*20480)
#define A_LOO   10240
#define BBUF(s) (40960 + (s)*17408)
#define B_LOO   8704
#define SMEM_MMA 75776

__global__ void __launch_bounds__(256, 2)
kgemm_mma(const float* __restrict__ X, const float* __restrict__ Z,
          const float* __restrict__ bias) {
    extern __shared__ char sm[];
    uint32_t smb = (uint32_t)__cvta_generic_to_shared(sm);
    const int t = threadIdx.x, w = t >> 5, lane = t & 31;
    const int m0 = blockIdx.x*128, nh = blockIdx.y;
    const int gemm = blockIdx.z;
    const float* A = gemm ? Z : X;
    const __nv_bfloat16* Wh = g_Wh[gemm];
    const __nv_bfloat16* Wl = g_Wl[gemm];
    const float* bp = gemm ? g_bK : bias;
    const int wm = (w >> 1)*32, wn = (w & 1)*64;

    float acc[2][8][4];
    #pragma unroll
    for (int i = 0; i < 2; i++)
        #pragma unroll
        for (int j = 0; j < 8; j++)
            #pragma unroll
            for (int q = 0; q < 4; q++) acc[i][j][q] = 0.f;

#define STG_B(c, s)                                                           \
    {                                                                         \
        const __nv_bfloat16* srcH = Wh + (size_t)((c)*KC)*Dm + nh*128;        \
        const __nv_bfloat16* srcL = Wl + (size_t)((c)*KC)*Dm + nh*128;        \
        _Pragma("unroll")                                                     \
        for (int p = 0; p < 2; p++) {                                         \
            int idx = t + p*256;                                              \
            int row = idx >> 4, seg = idx & 15;                               \
            uint32_t d = smb + BBUF(s) + (uint32_t)(row*272 + seg*16);        \
            cpa16(d, srcH + (size_t)row*Dm + seg*8);                          \
            if (gemm == 0)                                                    \
                cpa16(d + B_LOO, srcL + (size_t)row*Dm + seg*8);              \
        }                                                                     \
        CPCOMMIT();                                                           \
    }
#define STG_A(c, s)                                                           \
    {                                                                         \
        int row = t >> 1, half = t & 1;                                       \
        const float4* ar = (const float4*)(A + (size_t)(m0 + row)*Dm + (c)*KC + half*16); \
        float4 vv[4];                                                         \
        _Pragma("unroll")                                                     \
        for (int j4 = 0; j4 < 4; j4++) vv[j4] = ar[j4];                       \
        char* wbH = sm + ABUF(s) + row*80 + half*32;                          \
        char* wbL = wbH + A_LOO;                                              \
        uint32_t hr[8], lr[8];                                                \
        _Pragma("unroll")                                                     \
        for (int j4 = 0; j4 < 4; j4++) {                                      \
            float4 v = vv[j4];                                                \
            asm("cvt.rn.bf16x2.f32 %0, %1, %2;" : "=r"(hr[j4*2])   : "f"(v.y), "f"(v.x)); \
            asm("cvt.rn.bf16x2.f32 %0, %1, %2;" : "=r"(hr[j4*2+1]) : "f"(v.w), "f"(v.z)); \
            if (gemm == 0) {                                                  \
                float l0 = v.x - __uint_as_float(hr[j4*2] << 16);             \
                float l1 = v.y - __uint_as_float(hr[j4*2] & 0xffff0000u);     \
                float l2 = v.z - __uint_as_float(hr[j4*2+1] << 16);           \
                float l3 = v.w - __uint_as_float(hr[j4*2+1] & 0xffff0000u);   \
                asm("cvt.rn.bf16x2.f32 %0, %1, %2;" : "=r"(lr[j4*2])   : "f"(l1), "f"(l0)); \
                asm("cvt.rn.bf16x2.f32 %0, %1, %2;" : "=r"(lr[j4*2+1]) : "f"(l3), "f"(l2)); \
            }                                                                 \
        }                                                                     \
        *(uint4*)(wbH +  0) = make_uint4(hr[0], hr[1], hr[2], hr[3]);         \
        *(uint4*)(wbH + 16) = make_uint4(hr[4], hr[5], hr[6], hr[7]);         \
        if (gemm == 0) {                                                      \
            *(uint4*)(wbL +  0) = make_uint4(lr[0], lr[1], lr[2], lr[3]);     \
            *(uint4*)(wbL + 16) = make_uint4(lr[4], lr[5], lr[6], lr[7]);     \
        }                                                                     \
    }

    STG_B(0, 0);
    STG_A(0, 0);

    for (int c = 0; c < 8; c++) {
        int s = c & 1;
        CPWAIT0();
        __syncthreads();
        if (c < 7) {
            STG_B(c + 1, s ^ 1);
            STG_A(c + 1, s ^ 1);
        }
        uint32_t aoff = smb + ABUF(s) + (uint32_t)((wm + (lane & 15))*80) + (lane >> 4)*16;
        uint32_t boff = smb + BBUF(s) + (uint32_t)((lane & 15)*272) + (uint32_t)((wn + (lane >> 4)*8)*2);
        if (gemm == 0) {
            #pragma unroll
            for (int ks = 0; ks < 2; ks++) {
                uint32_t ah[2][4], al[2][4];
                uint32_t ab = aoff + ks*32;
                ldsm4(ah[0], ab);
                ldsm4(ah[1], ab + 16*80);
                ldsm4(al[0], ab + A_LOO);
                ldsm4(al[1], ab + A_LOO + 16*80);
                uint32_t bb = boff + ks*16*272;
                #pragma unroll
                for (int nq = 0; nq < 4; nq++) {
                    uint32_t bh[4], bl[4];
                    ldsm4t(bh, bb + nq*32);
                    ldsm4t(bl, bb + nq*32 + B_LOO);
                    #pragma unroll
                    for (int mt = 0; mt < 2; mt++) {
                        #pragma unroll
                        for (int sub = 0; sub < 2; sub++) {
                            float* cc = acc[mt][nq*2 + sub];
                            hmma(cc, ah[mt], bh[sub*2], bh[sub*2+1]);
                            hmma(cc, al[mt], bh[sub*2], bh[sub*2+1]);
                            hmma(cc, ah[mt], bl[sub*2], bl[sub*2+1]);
                        }
                    }
                }
            }
        } else {
            #pragma unroll
            for (int ks = 0; ks < 2; ks++) {
                uint32_t ah[2][4];
                uint32_t ab = aoff + ks*32;
                ldsm4(ah[0], ab);
                ldsm4(ah[1], ab + 16*80);
                uint32_t bb = boff + ks*16*272;
                #pragma unroll
                for (int nq = 0; nq < 4; nq++) {
                    uint32_t bh[4];
                    ldsm4t(bh, bb + nq*32);
                    #pragma unroll
                    for (int mt = 0; mt < 2; mt++) {
                        #pragma unroll
                        for (int sub = 0; sub < 2; sub++) {
                            float* cc = acc[mt][nq*2 + sub];
                            hmma(cc, ah[mt], bh[sub*2], bh[sub*2+1]);
                        }
                    }
                }
            }
        }
    }

    // ---- register-direct epilogue ----
    const float* bp2 = bp + nh*128;
    const int rl = lane >> 2, cq = (lane & 3)*2;
    if (gemm == 0) {
        #pragma unroll
        for (int mt = 0; mt < 2; mt++)
            #pragma unroll
            for (int j = 0; j < 8; j++) {
                int cl = wn + j*8 + cq;
                float b0 = bp2[cl], b1 = bp2[cl+1];
                int r = m0 + wm + mt*16 + rl;
                float2 o0 = {acc[mt][j][0] + b0, acc[mt][j][1] + b1};
                float2 o1 = {acc[mt][j][2] + b0, acc[mt][j][3] + b1};
                *(float2*)(g_xv + (size_t)r*Dm + nh*128 + cl)     = o0;
                *(float2*)(g_xv + (size_t)(r+8)*Dm + nh*128 + cl) = o1;
            }
    } else {
        float ps[2][2] = {{0.f,0.f},{0.f,0.f}};
        #pragma unroll
        for (int mt = 0; mt < 2; mt++)
            #pragma unroll
            for (int j = 0; j < 8; j++) {
                int cl = wn + j*8 + cq;
                float b0 = bp2[cl], b1 = bp2[cl+1];
                int r = m0 + wm + mt*16 + rl;
                float e00 = __expf(acc[mt][j][0] + b0);
                float e01 = __expf(acc[mt][j][1] + b1);
                float e10 = __expf(acc[mt][j][2] + b0);
                float e11 = __expf(acc[mt][j][3] + b1);
                ps[mt][0] += e00 + e01;
                ps[mt][1] += e10 + e11;
                uint32_t p0, p1;
                asm("cvt.rn.bf16x2.f32 %0, %1, %2;" : "=r"(p0) : "f"(e01), "f"(e00));
                asm("cvt.rn.bf16x2.f32 %0, %1, %2;" : "=r"(p1) : "f"(e11), "f"(e10));
                *(uint32_t*)(g_eb + (size_t)r*Dm + nh*128 + cl)     = p0;
                *(uint32_t*)(g_eb + (size_t)(r+8)*Dm + nh*128 + cl) = p1;
            }
        int head = nh*2 + (w & 1);
        #pragma unroll
        for (int mt = 0; mt < 2; mt++)
            #pragma unroll
            for (int rr = 0; rr < 2; rr++) {
                float s = ps[mt][rr];
                s += __shfl_xor_sync(0xffffffffu, s, 1);
                s += __shfl_xor_sync(0xffffffffu, s, 2);
                if ((lane & 3) == 0) {
                    int r = m0 + wm + mt*16 + rl + rr*8;
                    g_rs[(size_t)r*Hh + head] = s;
                }
            }
    }
}

// ---------------- kpool ----------------
#define ONESB 0x3F803F80u
__global__ void __launch_bounds__(256, 4) kpool() {
    __shared__ char smE[2][64*144];
    __shared__ char smX[2][64*144];
    uint32_t sE[2] = {(uint32_t)__cvta_generic_to_shared(smE[0]),
                      (uint32_t)__cvta_generic_to_shared(smE[1])};
    uint32_t sX[2] = {(uint32_t)__cvta_generic_to_shared(smX[0]),
                      (uint32_t)__cvta_generic_to_shared(smX[1])};
    const int t = threadIdx.x, w = t >> 5, lane = t & 31;
    const int ch = blockIdx.x, h = blockIdx.y, b = blockIdx.z;
    const int r_base = (w & 3)*16, d_base = (w >> 2)*32;
    float acc[4][4];
    #pragma unroll
    for (int i = 0; i < 4; i++)
        #pragma unroll
        for (int q = 0; q < 4; q++) acc[i][q] = 0.f;
    float acc2[4] = {0.f, 0.f, 0.f, 0.f};

#define STG_EX(tl, s)                                                         \
    {                                                                         \
        int n0 = ch*512 + (tl)*64;                                            \
        size_t gbase = ((size_t)(b*Nn + n0))*Dm + h*64;                       \
        _Pragma("unroll")                                                     \
        for (int p = 0; p < 2; p++) {                                         \
            int c = t + p*256;                                                \
            int row = c >> 3, off = c & 7;                                    \
            cpa16(sE[s] + row*144 + off*16, g_eb + gbase + (size_t)row*Dm + off*8); \
        }                                                                     \
        CPCOMMIT();                                                           \
        _Pragma("unroll")                                                     \
        for (int p = 0; p < 4; p++) {                                         \
            int c = t + p*256;                                                \
            int row = c >> 4, col4 = c & 15;                                  \
            float4 v = *(const float4*)(g_xv + gbase + (size_t)row*Dm + col4*4); \
            float inv = __fdividef(1.f, g_rs[((size_t)(b*Nn + n0 + row))*Hh + h]); \
            float4 sv = {v.x*inv, v.y*inv, v.z*inv, v.w*inv};                 \
            *(uint2*)(smX[s] + row*144 + col4*8) = f4_to_bf16x4(sv);          \
        }                                                                     \
    }

    STG_EX(0, 0);

    for (int tile = 0; tile < 8; tile++) {
        int s = tile & 1;
        CPWAIT0();
        __syncthreads();
        if (tile < 7) STG_EX(tile + 1, s ^ 1);

        uint32_t aoff = sE[s] + (uint32_t)((((lane >> 4) << 3) + (lane & 7))*144)
                      + (uint32_t)((r_base + (((lane >> 3) & 1) << 3))*2);
        uint32_t boff = sX[s] + (uint32_t)((lane & 15)*144) + (uint32_t)((d_base + (lane >> 4)*8)*2);
        #pragma unroll
        for (int ks = 0; ks < 4; ks++) {
            uint32_t a[4];
            ldsm4t(a, aoff + ks*16*144);
            if (w < 4) hmma(acc2, a, ONESB, ONESB);
            #pragma unroll
            for (int dq = 0; dq < 2; dq++) {
                uint32_t bf[4];
                ldsm4t(bf, boff + ks*16*144 + dq*32);
                hmma(acc[dq*2],   a, bf[0], bf[1]);
                hmma(acc[dq*2+1], a, bf[2], bf[3]);
            }
        }
        __syncthreads();
    }
    float* pp = g_pool + ((size_t)(b*Hh + h)*Rr)*HDd;
    #pragma unroll
    for (int i = 0; i < 4; i++) {
        int r = r_base + (lane >> 2);
        int d = d_base + i*8 + (lane & 3)*2;
        atomicAdd(&pp[r*HDd + d],       acc[i][0]);
        atomicAdd(&pp[r*HDd + d + 1],   acc[i][1]);
        atomicAdd(&pp[(r+8)*HDd + d],   acc[i][2]);
        atomicAdd(&pp[(r+8)*HDd + d+1], acc[i][3]);
    }
    if (w < 4 && (lane & 3) == 0) {
        int r = r_base + (lane >> 2);
        atomicAdd(&g_S[(b*Hh + h)*Rr + r],     acc2[0]);
        atomicAdd(&g_S[(b*Hh + h)*Rr + r + 8], acc2[2]);
    }
}

// ---------------- kout: 32-row tiles, 4 CTA/SM, one 16-row pass per warp ----------------
#define KO_E  0                  // 32 rows x 528B = 16896
#define KO_P  16896              // 256 rows x 144B (bf16 pool/S) = 36864
#define SMEM_KOUT 53760
__global__ void __launch_bounds__(256, 4)
kout(const float* __restrict__ alpha, const float* __restrict__ beta,
     float* __restrict__ out) {
    extern __shared__ char sm[];
    uint32_t smb = (uint32_t)__cvta_generic_to_shared(sm);
    const int t = threadIdx.x, w = t >> 5, lane = t & 31;
    const int b = blockIdx.x >> 8;
    const int n0 = (blockIdx.x & 255)*32;
    const int hw = w & 3, m_base = (w >> 2)*16;
    size_t gbase = ((size_t)(b*Nn + n0))*Dm;

    // stage E (32 rows) via cp.async
    #pragma unroll
    for (int p = 0; p < 4; p++) {
        int c = t + p*256;
        int row = c >> 5, off = c & 31;
        cpa16(smb + KO_E + row*528 + off*16, g_eb + gbase + (size_t)row*Dm + off*8);
    }
    CPCOMMIT();
    // stage P = bf16(pool/S) under the E flight (pool is L2-resident)
    #pragma unroll
    for (int p = 0; p < 16; p++) {
        int idx = t + p*256;
        int prow = idx >> 4, pcol4 = idx & 15;
        const float* basep = g_pool + (size_t)b*(Hh*Rr*HDd);
        float4 v = *(const float4*)(basep + prow*64 + pcol4*4);
        float inv = __fdividef(1.f, g_S[b*(Hh*Rr) + prow]);
        float4 sv = {v.x*inv, v.y*inv, v.z*inv, v.w*inv};
        *(uint2*)(sm + KO_P + prow*144 + pcol4*8) = f4_to_bf16x4(sv);
    }
    CPWAIT0();
    __syncthreads();

    float sa = 1.f / (1.f + __expf(-alpha[hw]));
    float sb = 1.f / (1.f + __expf(-beta[hw]));
    uint32_t boff = smb + KO_P + (uint32_t)(hw*9216)
                  + (uint32_t)((lane & 15)*144) + (uint32_t)((lane >> 4)*16);
    const int colb = hw*64 + (lane & 3)*2;

    float acc[8][4];
    #pragma unroll
    for (int j = 0; j < 8; j++)
        #pragma unroll
        for (int q = 0; q < 4; q++) acc[j][q] = 0.f;

    uint32_t aoff = smb + KO_E + (uint32_t)((m_base + (lane & 15))*528)
                  + (uint32_t)(hw*128) + (lane >> 4)*16;
    #pragma unroll
    for (int ks = 0; ks < 4; ks++) {
        uint32_t a[4];
        ldsm4(a, aoff + ks*32);
        #pragma unroll
        for (int dq = 0; dq < 4; dq++) {
            uint32_t bf[4];
            ldsm4t(bf, boff + ks*16*144 + dq*32);
            hmma(acc[dq*2],   a, bf[0], bf[1]);
            hmma(acc[dq*2+1], a, bf[2], bf[3]);
        }
    }

    // batched epilogue: two 8-deep load waves, then FMA+store
    int row = m_base + (lane >> 2);
    const float* xvp0 = g_xv + gbase + (size_t)row*Dm + colb;
    float* op0 = out + gbase + (size_t)row*Dm + colb;
    {
        float2 xv0[8];
        #pragma unroll
        for (int j = 0; j < 8; j++) xv0[j] = *(const float2*)(xvp0 + j*8);
        #pragma unroll
        for (int j = 0; j < 8; j++) {
            float2 o = {fmaf(sa, xv0[j].x, sb*acc[j][0]),
                        fmaf(sa, xv0[j].y, sb*acc[j][1])};
            *(float2*)(op0 + j*8) = o;
        }
    }
    {
        const float* xvp1 = xvp0 + 8*Dm;
        float* op1 = op0 + 8*Dm;
        float2 xv1[8];
        #pragma unroll
        for (int j = 0; j < 8; j++) xv1[j] = *(const float2*)(xvp1 + j*8);
        #pragma unroll
        for (int j = 0; j < 8; j++) {
            float2 o = {fmaf(sa, xv1[j].x, sb*acc[j][2]),
                        fmaf(sa, xv1[j].y, sb*acc[j][3])};
            *(float2*)(op1 + j*8) = o;
        }
    }
}

extern "C" void kernel_launch(void* const* d_in, const int* in_sizes, int n_in,
                              void* d_out, int out_size) {
    const float* x     = (const float*)d_in[0];
    const float* z     = (const float*)d_in[1];
    const float* Wq    = (const float*)d_in[2];
    const float* bq    = (const float*)d_in[3];
    const float* K     = (const float*)d_in[4];
    const float* Wv    = (const float*)d_in[5];
    const float* bv    = (const float*)d_in[6];
    const float* alpha = (const float*)d_in[7];
    const float* beta  = (const float*)d_in[8];
    float* out = (float*)d_out;

    cudaFuncSetAttribute(kgemm_mma, cudaFuncAttributeMaxDynamicSharedMemorySize, SMEM_MMA);
    cudaFuncSetAttribute(kout,      cudaFuncAttributeMaxDynamicSharedMemorySize, SMEM_KOUT);

    kinit<<<512 + Dm + 1 + Dm, 256>>>(Wq, bq, K, Wv);
    kgemm_mma<<<dim3(Mm/128, 2, 2), 256, SMEM_MMA>>>(x, z, bv);
    kpool<<<dim3(16, Hh, Bz), 256>>>();
    kout<<<Mm/32, 256, SMEM_KOUT>>>(alpha, beta, out);
}